// round 5
// baseline (speedup 1.0000x reference)
#include <cuda_runtime.h>
#include <cuda_bf16.h>
#include <cstdint>
#include <math.h>

#define TOK 20000      // 2 * 16 windows * 625 tokens
#define DCH 256
#define QKVN 768
#define HID 512

typedef unsigned short ush;

// ---- scratch: split-bf16 stored as separate hi / lo planes ----
__device__ ush g_xw_h [TOK * DCH];
__device__ ush g_xw_l [TOK * DCH];
__device__ ush g_qkv_h[TOK * QKVN];
__device__ ush g_qkv_l[TOK * QKVN];
__device__ ush g_att_h[TOK * DCH];
__device__ ush g_att_l[TOK * DCH];
__device__ float g_proj[TOK * DCH];
__device__ ush g_ln_h [TOK * DCH];
__device__ ush g_ln_l [TOK * DCH];
__device__ ush g_hid_h[TOK * HID];
__device__ ush g_hid_l[TOK * HID];
// all four weight matrices concatenated: wqkv | wout | w1 | w2
#define WQ 0
#define WO 196608
#define W1 262144
#define W2 393216
#define WTOT 524288
__device__ ush g_w_h[WTOT];
__device__ ush g_w_l[WTOT];

// ---------------------------------------------------------------------------
// helpers
// ---------------------------------------------------------------------------
__device__ __forceinline__ uint32_t smem_u32(const void* p) {
    uint32_t a;
    asm("{ .reg .u64 t; cvta.to.shared.u64 t, %1; cvt.u32.u64 %0, t; }" : "=r"(a) : "l"(p));
    return a;
}
#define CP_ASYNC16(dst, src) \
    asm volatile("cp.async.cg.shared.global [%0], [%1], 16;" :: "r"(dst), "l"(src))
#define CP_COMMIT() asm volatile("cp.async.commit_group;")
#define CP_WAIT1()  asm volatile("cp.async.wait_group 1;")
#define CP_WAIT0()  asm volatile("cp.async.wait_group 0;")

__device__ __forceinline__ void ldm_x4(uint32_t& d0, uint32_t& d1, uint32_t& d2,
                                       uint32_t& d3, uint32_t addr)
{
    asm volatile("ldmatrix.sync.aligned.m8n8.x4.shared.b16 {%0,%1,%2,%3}, [%4];"
                 : "=r"(d0), "=r"(d1), "=r"(d2), "=r"(d3) : "r"(addr));
}

__device__ __forceinline__ void mma16816(float c[4], uint32_t a0, uint32_t a1,
                                         uint32_t a2, uint32_t a3,
                                         uint32_t b0, uint32_t b1)
{
    asm volatile(
        "mma.sync.aligned.m16n8k16.row.col.f32.bf16.bf16.f32 "
        "{%0,%1,%2,%3}, {%4,%5,%6,%7}, {%8,%9}, {%0,%1,%2,%3};"
        : "+f"(c[0]), "+f"(c[1]), "+f"(c[2]), "+f"(c[3])
        : "r"(a0), "r"(a1), "r"(a2), "r"(a3), "r"(b0), "r"(b1));
}

__device__ __forceinline__ void splitf(float f, ush& h, ush& l) {
    __nv_bfloat16 bh = __float2bfloat16_rn(f);
    h = __bfloat16_as_ushort(bh);
    l = __bfloat16_as_ushort(__float2bfloat16_rn(f - __bfloat162float(bh)));
}

__device__ __forceinline__ float gelu_exact(float v)
{
    return 0.5f * v * (1.0f + erff(v * 0.70710678118654752f));
}

// ---------------------------------------------------------------------------
// merged weight conversion: 4 fp32 weight tensors -> concatenated hi/lo planes
// ---------------------------------------------------------------------------
__global__ __launch_bounds__(256) void cvt4_kernel(
    const float* __restrict__ s0, const float* __restrict__ s1,
    const float* __restrict__ s2, const float* __restrict__ s3,
    ush* __restrict__ h, ush* __restrict__ l)
{
    int base = (blockIdx.x * blockDim.x + threadIdx.x) * 4;
    if (base >= WTOT) return;
    const float* src;
    int off;
    if (base < WO)      { src = s0; off = base; }
    else if (base < W1) { src = s1; off = base - WO; }
    else if (base < W2) { src = s2; off = base - W1; }
    else                { src = s3; off = base - W2; }
    float4 v = *(const float4*)(src + off);
    ushort4 hh, ll;
    splitf(v.x, hh.x, ll.x); splitf(v.y, hh.y, ll.y);
    splitf(v.z, hh.z, ll.z); splitf(v.w, hh.w, ll.w);
    *(ushort4*)(h + base) = hh;
    *(ushort4*)(l + base) = ll;
}

// ---------------------------------------------------------------------------
// window partition with smem transpose: x (2,256,100,100) -> planes (20000,256)
// block = 32 tokens x 32 channels; coalesced reads along token dim,
// coalesced plane writes along channel dim.
// ---------------------------------------------------------------------------
__global__ __launch_bounds__(256) void gather_kernel(const float* __restrict__ x,
                                                     ush* __restrict__ xh,
                                                     ush* __restrict__ xl)
{
    __shared__ float sm[32][33];
    const int w = threadIdx.x >> 5, lane = threadIdx.x & 31;
    const int tk0 = blockIdx.x * 32;       // 625 blocks
    const int ch0 = blockIdx.y * 32;       // 8 blocks

    // load: warp w loads channels ch0+w*4..+3 for token tk0+lane
    {
        int tk = tk0 + lane;
        int bb = tk / 10000, rr = tk % 10000;
        int win = rr / 625, t = rr % 625;
        int hh = (win >> 2) * 25 + t / 25;
        int ww = (win & 3) * 25 + t % 25;
        int base = bb * 2560000 + hh * 100 + ww;
#pragma unroll
        for (int i = 0; i < 4; i++) {
            int ch = ch0 + w * 4 + i;
            sm[w * 4 + i][lane] = x[base + ch * 10000];
        }
    }
    __syncthreads();

    // store: warp w writes tokens tk0+w*4..+3, channel = ch0+lane
#pragma unroll
    for (int i = 0; i < 4; i++) {
        int tl = w * 4 + i;
        float v = sm[lane][tl];
        ush h, l;
        splitf(v, h, l);
        size_t o = (size_t)(tk0 + tl) * DCH + ch0 + lane;
        xh[o] = h;
        xl[o] = l;
    }
}

// ---------------------------------------------------------------------------
// split-bf16 tensor-core GEMM v2: cp.async double-buffer + ldmatrix.
// C[M,N] = A[M,K] @ B[N,K]^T ; A,B hi/lo bf16 planes.
// CTA 256 thr, tile 128x128, warp 32x64, BK=32.
// mode 0: C fp32   mode 1: gelu(C+bias) -> planes   mode 2: scatter+residual
// mode 3: C -> planes
// ---------------------------------------------------------------------------
#define SB   80           // smem row stride bytes (64 data + 16 pad)
#define PLB  10240        // one plane: 128 rows * SB
#define BUFB 40960        // 4 planes
#define GEMM_SMEM (2 * BUFB)

__global__ __launch_bounds__(256) void gemm_tc(
    const ush* __restrict__ Ah, const ush* __restrict__ Al,
    const ush* __restrict__ Bh, const ush* __restrict__ Bl,
    int M, int N, int K, int mode,
    const float* __restrict__ bias, const float* __restrict__ xres,
    float* __restrict__ outF, ush* __restrict__ oh, ush* __restrict__ ol)
{
    extern __shared__ char smem[];
    const uint32_t sbb = smem_u32(smem);
    const int tid = threadIdx.x;
    const int wid = tid >> 5, lane = tid & 31;
    const int g = lane >> 2, t = lane & 3;
    const int wm = (wid & 3) * 32;
    const int wn = (wid >> 2) * 64;
    const int row0 = blockIdx.y * 128, coln0 = blockIdx.x * 128;

    float acc[2][8][4];
#pragma unroll
    for (int i = 0; i < 2; i++)
#pragma unroll
        for (int j = 0; j < 8; j++)
#pragma unroll
            for (int q = 0; q < 4; q++) acc[i][j][q] = 0.f;

    const int nst = K >> 5;

    // loader slot: 512 slots/plane-pair iteration: r = slot>>2, chunk c = slot&3
    const int lslot0 = tid, lslot1 = tid + 256;
    const int lr0 = lslot0 >> 2, lc0 = lslot0 & 3;
    const int lr1 = lslot1 >> 2, lc1 = lslot1 & 3;
    int ga0 = row0 + lr0; if (ga0 > M - 1) ga0 = M - 1;
    int ga1 = row0 + lr1; if (ga1 > M - 1) ga1 = M - 1;

#define ISSUE(s) do {                                                          \
    int _b = (s) & 1;                                                          \
    int _k0 = (s) << 5;                                                        \
    uint32_t _d0 = sbb + _b * BUFB + lr0 * SB + lc0 * 16;                      \
    size_t _gaa = (size_t)ga0 * K + _k0 + lc0 * 8;                             \
    size_t _gbb = (size_t)(coln0 + lr0) * K + _k0 + lc0 * 8;                   \
    CP_ASYNC16(_d0,            Ah + _gaa);                                     \
    CP_ASYNC16(_d0 + PLB,      Al + _gaa);                                     \
    CP_ASYNC16(_d0 + 2 * PLB,  Bh + _gbb);                                     \
    CP_ASYNC16(_d0 + 3 * PLB,  Bl + _gbb);                                     \
    uint32_t _d1 = sbb + _b * BUFB + lr1 * SB + lc1 * 16;                      \
    size_t _ga2 = (size_t)ga1 * K + _k0 + lc1 * 8;                             \
    size_t _gb2 = (size_t)(coln0 + lr1) * K + _k0 + lc1 * 8;                   \
    CP_ASYNC16(_d1,            Ah + _ga2);                                     \
    CP_ASYNC16(_d1 + PLB,      Al + _ga2);                                     \
    CP_ASYNC16(_d1 + 2 * PLB,  Bh + _gb2);                                     \
    CP_ASYNC16(_d1 + 3 * PLB,  Bl + _gb2);                                     \
} while (0)

    ISSUE(0); CP_COMMIT();

    const int arow = (lane & 7) + ((lane >> 3) & 1) * 8;
    const int kh = (lane >> 4) * 16;

    for (int s = 0; s < nst; s++) {
        if (s + 1 < nst) { ISSUE(s + 1); CP_COMMIT(); CP_WAIT1(); }
        else             { CP_WAIT0(); }
        __syncthreads();

        const uint32_t pa = sbb + (s & 1) * BUFB;
        const uint32_t pb = pa + 2 * PLB;
#pragma unroll
        for (int ks = 0; ks < 2; ks++) {
            const uint32_t cb = ks * 32 + kh;
            uint32_t ah[2][4], al[2][4];
#pragma unroll
            for (int mt = 0; mt < 2; mt++) {
                uint32_t ad = pa + (wm + mt * 16 + arow) * SB + cb;
                ldm_x4(ah[mt][0], ah[mt][1], ah[mt][2], ah[mt][3], ad);
                ldm_x4(al[mt][0], al[mt][1], al[mt][2], al[mt][3], ad + PLB);
            }
            uint32_t bh[8][2], bl[8][2];
#pragma unroll
            for (int p = 0; p < 4; p++) {
                uint32_t bd = pb + (wn + p * 16 + arow) * SB + cb;
                ldm_x4(bh[2 * p][0], bh[2 * p + 1][0], bh[2 * p][1], bh[2 * p + 1][1], bd);
                ldm_x4(bl[2 * p][0], bl[2 * p + 1][0], bl[2 * p][1], bl[2 * p + 1][1], bd + PLB);
            }
#pragma unroll
            for (int mt = 0; mt < 2; mt++)
#pragma unroll
                for (int nt = 0; nt < 8; nt++) {
                    mma16816(acc[mt][nt], ah[mt][0], ah[mt][1], ah[mt][2], ah[mt][3],
                             bh[nt][0], bh[nt][1]);
                    mma16816(acc[mt][nt], ah[mt][0], ah[mt][1], ah[mt][2], ah[mt][3],
                             bl[nt][0], bl[nt][1]);
                    mma16816(acc[mt][nt], al[mt][0], al[mt][1], al[mt][2], al[mt][3],
                             bh[nt][0], bh[nt][1]);
                }
        }
        __syncthreads();
    }
#undef ISSUE

    // ---- epilogue ----
#pragma unroll
    for (int mt = 0; mt < 2; mt++) {
#pragma unroll
        for (int half = 0; half < 2; half++) {
            int r = row0 + wm + mt * 16 + g + half * 8;
            if (r >= M) continue;
#pragma unroll
            for (int nt = 0; nt < 8; nt++) {
                int col = coln0 + wn + nt * 8 + 2 * t;
                float v0 = acc[mt][nt][half * 2 + 0];
                float v1 = acc[mt][nt][half * 2 + 1];
                if (mode == 0) {
                    *(float2*)(outF + (size_t)r * N + col) = make_float2(v0, v1);
                } else if (mode == 3) {
                    ushort2 hh, ll;
                    splitf(v0, hh.x, ll.x); splitf(v1, hh.y, ll.y);
                    *(ushort2*)(oh + (size_t)r * N + col) = hh;
                    *(ushort2*)(ol + (size_t)r * N + col) = ll;
                } else if (mode == 1) {
                    float g0 = gelu_exact(v0 + bias[col]);
                    float g1 = gelu_exact(v1 + bias[col + 1]);
                    ushort2 hh, ll;
                    splitf(g0, hh.x, ll.x); splitf(g1, hh.y, ll.y);
                    *(ushort2*)(oh + (size_t)r * N + col) = hh;
                    *(ushort2*)(ol + (size_t)r * N + col) = ll;
                } else {
                    int bb = r / 10000, rr = r % 10000;
                    int win = rr / 625, tt = rr % 625;
                    int hh2 = (win >> 2) * 25 + tt / 25;
                    int ww = (win & 3) * 25 + tt % 25;
                    int obase = bb * 2560000 + hh2 * 100 + ww;
                    int oi0 = obase + col * 10000;
                    int oi1 = obase + (col + 1) * 10000;
                    outF[oi0] = xres[oi0] + v0 + bias[col];
                    outF[oi1] = xres[oi1] + v1 + bias[col + 1];
                }
            }
        }
    }
}

// ---------------------------------------------------------------------------
// tensor-core windowed attention (unchanged math; inputs/outputs are planes)
// ---------------------------------------------------------------------------
#define SROW 20
#define AQHI 0
#define AQLO 2560
#define AKHI 5120
#define AKLO 6400
#define AVTH 7680
#define AVTL 8832
#define ABL  9984
#define ASUB 12385
#define AVMK 12449
#define ATTN_SMEM_WORDS 12513
#define VTS 36

__global__ __launch_bounds__(256) void attn_tc(const ush* __restrict__ qh_,
                                               const ush* __restrict__ ql_,
                                               const float* __restrict__ table,
                                               ush* __restrict__ oh,
                                               ush* __restrict__ ol)
{
    extern __shared__ uint32_t sm[];
    uint32_t* QHI = sm + AQHI;
    uint32_t* QLO = sm + AQLO;
    uint32_t* KHI = sm + AKHI;
    uint32_t* KLO = sm + AKLO;
    uint32_t* VTH = sm + AVTH;
    uint32_t* VTL = sm + AVTL;
    float*    BL  = (float*)(sm + ABL);
    int*      SUB = (int*)(sm + ASUB);
    float*    VMK = (float*)(sm + AVMK);

    const int head = blockIdx.x;
    const int win  = blockIdx.y;
    const int qt   = blockIdx.z;
    const int tid  = threadIdx.x;
    const int w = tid >> 5, lane = tid & 31;
    const int g = lane >> 2, t = lane & 3;
    const int tok0 = win * 625;
    const int qbase = qt * 128;

    for (int i = tid; i < 2401; i += 256) BL[i] = table[i * 8 + head];

    // Q tile: 128 rows x (hi,lo) x 4 chunks of 16B
#pragma unroll
    for (int it = 0; it < 4; it++) {
        int idx = it * 256 + tid;
        int r = idx >> 3, rem = idx & 7;
        int pl = rem >> 2, c = rem & 3;
        int qi = qbase + r;
        uint4 v = make_uint4(0, 0, 0, 0);
        if (qi < 625) {
            const ush* src = (pl ? ql_ : qh_) + (size_t)(tok0 + qi) * QKVN
                           + head * 32 + c * 8;
            v = *(const uint4*)src;
        }
        uint32_t* dst = (pl ? QLO : QHI) + r * SROW + c * 4;
        *(uint4*)dst = v;
    }
    __syncthreads();

    uint32_t qh[2][4], ql[2][4];
    {
        int r0 = w * 16 + g;
#pragma unroll
        for (int kc = 0; kc < 2; kc++) {
            qh[kc][0] = QHI[r0 * SROW + kc * 8 + t];
            qh[kc][1] = QHI[(r0 + 8) * SROW + kc * 8 + t];
            qh[kc][2] = QHI[r0 * SROW + kc * 8 + t + 4];
            qh[kc][3] = QHI[(r0 + 8) * SROW + kc * 8 + t + 4];
            ql[kc][0] = QLO[r0 * SROW + kc * 8 + t];
            ql[kc][1] = QLO[(r0 + 8) * SROW + kc * 8 + t];
            ql[kc][2] = QLO[r0 * SROW + kc * 8 + t + 4];
            ql[kc][3] = QLO[(r0 + 8) * SROW + kc * 8 + t + 4];
        }
    }

    const int qi0 = qbase + w * 16 + g;
    const int qi1 = qi0 + 8;
    const int cq0 = qi0 < 625 ? qi0 : 624;
    const int cq1 = qi1 < 625 ? qi1 : 624;
    const int add0 = (cq0 / 25 + 24) * 49 + (cq0 % 25) + 24;
    const int add1 = (cq1 / 25 + 24) * 49 + (cq1 % 25) + 24;

    float l0 = 0.f, l1 = 0.f;
    float oacc[4][4];
#pragma unroll
    for (int i = 0; i < 4; i++)
#pragma unroll
        for (int j = 0; j < 4; j++) oacc[i][j] = 0.f;

    const float scale = 0.17677669529663687f;

    for (int kb = 0; kb < 10; kb++) {
        __syncthreads();
        // K tile: 64 rows x (hi,lo) x 4 chunks
#pragma unroll
        for (int it = 0; it < 2; it++) {
            int idx = it * 256 + tid;
            int r = idx >> 3, rem = idx & 7;
            int pl = rem >> 2, c = rem & 3;
            int jg = kb * 64 + r;
            uint4 v = make_uint4(0, 0, 0, 0);
            if (jg < 625) {
                const ush* src = (pl ? ql_ : qh_) + (size_t)(tok0 + jg) * QKVN
                               + 256 + head * 32 + c * 8;
                v = *(const uint4*)src;
            }
            uint32_t* dst = (pl ? KLO : KHI) + r * SROW + c * 4;
            *(uint4*)dst = v;
        }
        // V tile transposed
#pragma unroll
        for (int it = 0; it < 4; it++) {
            int idx = it * 256 + tid;
            int d = idx & 31, jp = idx >> 5;
            int j0 = kb * 64 + jp * 2;
            size_t base0 = (size_t)(tok0 + j0) * QKVN + 512 + head * 32 + d;
            uint32_t h0 = 0, h1 = 0, lo0 = 0, lo1 = 0;
            if (j0 < 625)     { h0 = qh_[base0];        lo0 = ql_[base0]; }
            if (j0 + 1 < 625) { h1 = qh_[base0 + QKVN]; lo1 = ql_[base0 + QKVN]; }
            VTH[d * VTS + jp] = h0 | (h1 << 16);
            VTL[d * VTS + jp] = lo0 | (lo1 << 16);
        }
        if (tid < 64) {
            int jg = kb * 64 + tid;
            int jj = jg < 625 ? jg : 624;
            SUB[tid] = (jj / 25) * 49 + (jj % 25);
            VMK[tid] = (jg < 625) ? 0.f : -1e30f;
        }
        __syncthreads();

        float sacc[8][4];
#pragma unroll
        for (int i = 0; i < 8; i++)
#pragma unroll
            for (int j = 0; j < 4; j++) sacc[i][j] = 0.f;

#pragma unroll
        for (int nt = 0; nt < 8; nt++) {
            int rb = nt * 8 + g;
#pragma unroll
            for (int kc = 0; kc < 2; kc++) {
                uint32_t bh0 = KHI[rb * SROW + kc * 8 + t];
                uint32_t bh1 = KHI[rb * SROW + kc * 8 + t + 4];
                uint32_t bl0 = KLO[rb * SROW + kc * 8 + t];
                uint32_t bl1 = KLO[rb * SROW + kc * 8 + t + 4];
                mma16816(sacc[nt], qh[kc][0], qh[kc][1], qh[kc][2], qh[kc][3], bh0, bh1);
                mma16816(sacc[nt], qh[kc][0], qh[kc][1], qh[kc][2], qh[kc][3], bl0, bl1);
                mma16816(sacc[nt], ql[kc][0], ql[kc][1], ql[kc][2], ql[kc][3], bh0, bh1);
            }
        }

        uint32_t pha[8][2], pla[8][2];
#pragma unroll
        for (int nt = 0; nt < 8; nt++) {
            int jl0 = nt * 8 + 2 * t;
            int jl1 = jl0 + 1;
            int s0i = SUB[jl0], s1i = SUB[jl1];
            float m0 = VMK[jl0], m1 = VMK[jl1];
            float p0 = __expf(sacc[nt][0] * scale + BL[add0 - s0i] + m0);
            float p1 = __expf(sacc[nt][1] * scale + BL[add0 - s1i] + m1);
            float p2 = __expf(sacc[nt][2] * scale + BL[add1 - s0i] + m0);
            float p3 = __expf(sacc[nt][3] * scale + BL[add1 - s1i] + m1);
            l0 += p0 + p1;
            l1 += p2 + p3;
            ush h0, h1, h2, h3, e0, e1, e2, e3;
            splitf(p0, h0, e0); splitf(p1, h1, e1);
            splitf(p2, h2, e2); splitf(p3, h3, e3);
            pha[nt][0] = (uint32_t)h0 | ((uint32_t)h1 << 16);
            pha[nt][1] = (uint32_t)h2 | ((uint32_t)h3 << 16);
            pla[nt][0] = (uint32_t)e0 | ((uint32_t)e1 << 16);
            pla[nt][1] = (uint32_t)e2 | ((uint32_t)e3 << 16);
        }

#pragma unroll
        for (int nt2 = 0; nt2 < 4; nt2++) {
            int dr = nt2 * 8 + g;
#pragma unroll
            for (int kc2 = 0; kc2 < 4; kc2++) {
                uint32_t bh0 = VTH[dr * VTS + kc2 * 8 + t];
                uint32_t bh1 = VTH[dr * VTS + kc2 * 8 + t + 4];
                uint32_t bl0 = VTL[dr * VTS + kc2 * 8 + t];
                uint32_t bl1 = VTL[dr * VTS + kc2 * 8 + t + 4];
                mma16816(oacc[nt2], pha[2 * kc2][0], pha[2 * kc2][1],
                         pha[2 * kc2 + 1][0], pha[2 * kc2 + 1][1], bh0, bh1);
                mma16816(oacc[nt2], pha[2 * kc2][0], pha[2 * kc2][1],
                         pha[2 * kc2 + 1][0], pha[2 * kc2 + 1][1], bl0, bl1);
                mma16816(oacc[nt2], pla[2 * kc2][0], pla[2 * kc2][1],
                         pla[2 * kc2 + 1][0], pla[2 * kc2 + 1][1], bh0, bh1);
            }
        }
    }

    l0 += __shfl_xor_sync(0xffffffffu, l0, 1);
    l0 += __shfl_xor_sync(0xffffffffu, l0, 2);
    l1 += __shfl_xor_sync(0xffffffffu, l1, 1);
    l1 += __shfl_xor_sync(0xffffffffu, l1, 2);
    float inv0 = 1.f / l0, inv1 = 1.f / l1;

    if (qi0 < 625) {
        size_t o = (size_t)(tok0 + qi0) * DCH + head * 32;
#pragma unroll
        for (int nt2 = 0; nt2 < 4; nt2++) {
            int d = nt2 * 8 + 2 * t;
            ushort2 hh, ll;
            splitf(oacc[nt2][0] * inv0, hh.x, ll.x);
            splitf(oacc[nt2][1] * inv0, hh.y, ll.y);
            *(ushort2*)(oh + o + d) = hh;
            *(ushort2*)(ol + o + d) = ll;
        }
    }
    if (qi1 < 625) {
        size_t o = (size_t)(tok0 + qi1) * DCH + head * 32;
#pragma unroll
        for (int nt2 = 0; nt2 < 4; nt2++) {
            int d = nt2 * 8 + 2 * t;
            ushort2 hh, ll;
            splitf(oacc[nt2][2] * inv1, hh.x, ll.x);
            splitf(oacc[nt2][3] * inv1, hh.y, ll.y);
            *(ushort2*)(oh + o + d) = hh;
            *(ushort2*)(ol + o + d) = ll;
        }
    }
}

// ---------------------------------------------------------------------------
// LayerNorm over d=256: one warp per token; outputs hi/lo planes
// ---------------------------------------------------------------------------
__global__ __launch_bounds__(256) void ln_kernel(const float* __restrict__ in,
                                                 ush* __restrict__ oh,
                                                 ush* __restrict__ ol,
                                                 const float* __restrict__ g,
                                                 const float* __restrict__ b)
{
    int wid = threadIdx.x >> 5, lane = threadIdx.x & 31;
    int t = blockIdx.x * 8 + wid;
    const float4* p = (const float4*)(in + (size_t)t * DCH);
    float4 v0 = p[lane];
    float4 v1 = p[lane + 32];
    float s  = v0.x + v0.y + v0.z + v0.w + v1.x + v1.y + v1.z + v1.w;
    float ss = v0.x * v0.x + v0.y * v0.y + v0.z * v0.z + v0.w * v0.w
             + v1.x * v1.x + v1.y * v1.y + v1.z * v1.z + v1.w * v1.w;
#pragma unroll
    for (int off = 16; off > 0; off >>= 1) {
        s  += __shfl_xor_sync(0xffffffffu, s, off);
        ss += __shfl_xor_sync(0xffffffffu, ss, off);
    }
    float mean = s * (1.f / 256.f);
    float var  = ss * (1.f / 256.f) - mean * mean;
    float rstd = rsqrtf(var + 1e-5f);

    const float4* g4 = (const float4*)g;
    const float4* b4 = (const float4*)b;
    float4 ga = g4[lane], gb = g4[lane + 32];
    float4 ba = b4[lane], bb = b4[lane + 32];

    ushort4 h0, l0_, h1, l1_;
    splitf((v0.x - mean) * rstd * ga.x + ba.x, h0.x, l0_.x);
    splitf((v0.y - mean) * rstd * ga.y + ba.y, h0.y, l0_.y);
    splitf((v0.z - mean) * rstd * ga.z + ba.z, h0.z, l0_.z);
    splitf((v0.w - mean) * rstd * ga.w + ba.w, h0.w, l0_.w);
    splitf((v1.x - mean) * rstd * gb.x + bb.x, h1.x, l1_.x);
    splitf((v1.y - mean) * rstd * gb.y + bb.y, h1.y, l1_.y);
    splitf((v1.z - mean) * rstd * gb.z + bb.z, h1.z, l1_.z);
    splitf((v1.w - mean) * rstd * gb.w + bb.w, h1.w, l1_.w);

    size_t o = (size_t)t * DCH;
    *(ushort4*)(oh + o + lane * 4)       = h0;
    *(ushort4*)(ol + o + lane * 4)       = l0_;
    *(ushort4*)(oh + o + 128 + lane * 4) = h1;
    *(ushort4*)(ol + o + 128 + lane * 4) = l1_;
}

// ---------------------------------------------------------------------------
extern "C" void kernel_launch(void* const* d_in, const int* in_sizes, int n_in,
                              void* d_out, int out_size)
{
    const float* x      = (const float*)d_in[0];
    const float* w_qkv  = (const float*)d_in[1];
    const float* w_out  = (const float*)d_in[2];
    const float* table  = (const float*)d_in[3];
    const float* gamma2 = (const float*)d_in[4];
    const float* beta2  = (const float*)d_in[5];
    const float* w1     = (const float*)d_in[6];
    const float* b1     = (const float*)d_in[7];
    const float* w2     = (const float*)d_in[8];
    const float* b2     = (const float*)d_in[9];
    float* out = (float*)d_out;

    ush *xwh, *xwl, *qh, *ql, *ath, *atl, *lnh, *lnl, *hih, *hil, *wh, *wl;
    float *proj;
    cudaGetSymbolAddress((void**)&xwh, g_xw_h);
    cudaGetSymbolAddress((void**)&xwl, g_xw_l);
    cudaGetSymbolAddress((void**)&qh,  g_qkv_h);
    cudaGetSymbolAddress((void**)&ql,  g_qkv_l);
    cudaGetSymbolAddress((void**)&ath, g_att_h);
    cudaGetSymbolAddress((void**)&atl, g_att_l);
    cudaGetSymbolAddress((void**)&proj, g_proj);
    cudaGetSymbolAddress((void**)&lnh, g_ln_h);
    cudaGetSymbolAddress((void**)&lnl, g_ln_l);
    cudaGetSymbolAddress((void**)&hih, g_hid_h);
    cudaGetSymbolAddress((void**)&hil, g_hid_l);
    cudaGetSymbolAddress((void**)&wh,  g_w_h);
    cudaGetSymbolAddress((void**)&wl,  g_w_l);

    const int attn_smem = ATTN_SMEM_WORDS * (int)sizeof(uint32_t);
    cudaFuncSetAttribute(attn_tc, cudaFuncAttributeMaxDynamicSharedMemorySize, attn_smem);
    cudaFuncSetAttribute(gemm_tc, cudaFuncAttributeMaxDynamicSharedMemorySize, GEMM_SMEM);

    // 0) weights -> concatenated hi/lo planes (one launch)
    cvt4_kernel<<<WTOT / 4 / 256, 256>>>(w_qkv, w_out, w1, w2, wh, wl);

    // 1) window partition (transposed, coalesced)
    gather_kernel<<<dim3(625, 8), 256>>>(x, xwh, xwl);
    // 2) QKV projection -> planes
    gemm_tc<<<dim3(6, 157), 256, GEMM_SMEM>>>(xwh, xwl, wh + WQ, wl + WQ,
        TOK, QKVN, DCH, 3, nullptr, nullptr, nullptr, qh, ql);
    // 3) tensor-core windowed attention -> planes
    attn_tc<<<dim3(8, 32, 5), 256, attn_smem>>>(qh, ql, table, ath, atl);
    // 4) output projection -> fp32
    gemm_tc<<<dim3(2, 157), 256, GEMM_SMEM>>>(ath, atl, wh + WO, wl + WO,
        TOK, DCH, DCH, 0, nullptr, nullptr, proj, nullptr, nullptr);
    // 5) layernorm -> planes
    ln_kernel<<<2500, 256>>>(proj, lnh, lnl, gamma2, beta2);
    // 6) MLP fc1 + exact GELU -> planes
    gemm_tc<<<dim3(4, 157), 256, GEMM_SMEM>>>(lnh, lnl, wh + W1, wl + W1,
        TOK, HID, DCH, 1, b1, nullptr, nullptr, hih, hil);
    // 7) MLP fc2 + bias + un-partition + residual -> d_out
    gemm_tc<<<dim3(2, 157), 256, GEMM_SMEM>>>(hih, hil, wh + W2, wl + W2,
        TOK, DCH, HID, 2, b2, x, out, nullptr, nullptr);
}

// round 6
// speedup vs baseline: 1.2363x; 1.2363x over previous
#include <cuda_runtime.h>
#include <cuda_bf16.h>
#include <cstdint>
#include <math.h>

#define TOK 20000      // 2 * 16 windows * 625 tokens
#define DCH 256
#define QKVN 768
#define HID 512

typedef unsigned short ush;

// ---- scratch: split-bf16 stored as separate hi / lo planes ----
__device__ ush g_xw_h [TOK * DCH];
__device__ ush g_xw_l [TOK * DCH];
__device__ ush g_qkv_h[TOK * QKVN];
__device__ ush g_att_h[TOK * DCH];
__device__ ush g_att_l[TOK * DCH];
__device__ float g_proj[TOK * DCH];
__device__ ush g_ln_h [TOK * DCH];
__device__ ush g_ln_l [TOK * DCH];
__device__ ush g_hid_h[TOK * HID];
__device__ ush g_hid_l[TOK * HID];
// all four weight matrices concatenated: wqkv | wout | w1 | w2
#define WQ 0
#define WO 196608
#define W1 262144
#define W2 393216
#define WTOT 524288
__device__ ush g_w_h[WTOT];
__device__ ush g_w_l[WTOT];

// ---------------------------------------------------------------------------
// helpers
// ---------------------------------------------------------------------------
__device__ __forceinline__ uint32_t smem_u32(const void* p) {
    uint32_t a;
    asm("{ .reg .u64 t; cvta.to.shared.u64 t, %1; cvt.u32.u64 %0, t; }" : "=r"(a) : "l"(p));
    return a;
}
#define CP_ASYNC16(dst, src) \
    asm volatile("cp.async.cg.shared.global [%0], [%1], 16;" :: "r"(dst), "l"(src))
#define CP_COMMIT() asm volatile("cp.async.commit_group;")
#define CP_WAIT1()  asm volatile("cp.async.wait_group 1;")
#define CP_WAIT0()  asm volatile("cp.async.wait_group 0;")

__device__ __forceinline__ void ldm_x4(uint32_t& d0, uint32_t& d1, uint32_t& d2,
                                       uint32_t& d3, uint32_t addr)
{
    asm volatile("ldmatrix.sync.aligned.m8n8.x4.shared.b16 {%0,%1,%2,%3}, [%4];"
                 : "=r"(d0), "=r"(d1), "=r"(d2), "=r"(d3) : "r"(addr));
}

__device__ __forceinline__ void mma16816(float c[4], uint32_t a0, uint32_t a1,
                                         uint32_t a2, uint32_t a3,
                                         uint32_t b0, uint32_t b1)
{
    asm volatile(
        "mma.sync.aligned.m16n8k16.row.col.f32.bf16.bf16.f32 "
        "{%0,%1,%2,%3}, {%4,%5,%6,%7}, {%8,%9}, {%0,%1,%2,%3};"
        : "+f"(c[0]), "+f"(c[1]), "+f"(c[2]), "+f"(c[3])
        : "r"(a0), "r"(a1), "r"(a2), "r"(a3), "r"(b0), "r"(b1));
}

__device__ __forceinline__ void splitf(float f, ush& h, ush& l) {
    __nv_bfloat16 bh = __float2bfloat16_rn(f);
    h = __bfloat16_as_ushort(bh);
    l = __bfloat16_as_ushort(__float2bfloat16_rn(f - __bfloat162float(bh)));
}

__device__ __forceinline__ uint32_t pack2bf(float a, float b) {
    return (uint32_t)__bfloat16_as_ushort(__float2bfloat16_rn(a)) |
           ((uint32_t)__bfloat16_as_ushort(__float2bfloat16_rn(b)) << 16);
}

__device__ __forceinline__ float gelu_exact(float v)
{
    return 0.5f * v * (1.0f + erff(v * 0.70710678118654752f));
}

// ---------------------------------------------------------------------------
// merged weight conversion: 4 fp32 weight tensors -> concatenated hi/lo planes
// ---------------------------------------------------------------------------
__global__ __launch_bounds__(256) void cvt4_kernel(
    const float* __restrict__ s0, const float* __restrict__ s1,
    const float* __restrict__ s2, const float* __restrict__ s3,
    ush* __restrict__ h, ush* __restrict__ l)
{
    int base = (blockIdx.x * blockDim.x + threadIdx.x) * 4;
    if (base >= WTOT) return;
    const float* src;
    int off;
    if (base < WO)      { src = s0; off = base; }
    else if (base < W1) { src = s1; off = base - WO; }
    else if (base < W2) { src = s2; off = base - W1; }
    else                { src = s3; off = base - W2; }
    float4 v = *(const float4*)(src + off);
    ushort4 hh, ll;
    splitf(v.x, hh.x, ll.x); splitf(v.y, hh.y, ll.y);
    splitf(v.z, hh.z, ll.z); splitf(v.w, hh.w, ll.w);
    *(ushort4*)(h + base) = hh;
    *(ushort4*)(l + base) = ll;
}

// ---------------------------------------------------------------------------
// window partition with smem transpose: x (2,256,100,100) -> planes (20000,256)
// ---------------------------------------------------------------------------
__global__ __launch_bounds__(256) void gather_kernel(const float* __restrict__ x,
                                                     ush* __restrict__ xh,
                                                     ush* __restrict__ xl)
{
    __shared__ float sm[32][33];
    const int w = threadIdx.x >> 5, lane = threadIdx.x & 31;
    const int tk0 = blockIdx.x * 32;       // 625 blocks
    const int ch0 = blockIdx.y * 32;       // 8 blocks

    {
        int tk = tk0 + lane;
        int bb = tk / 10000, rr = tk % 10000;
        int win = rr / 625, t = rr % 625;
        int hh = (win >> 2) * 25 + t / 25;
        int ww = (win & 3) * 25 + t % 25;
        int base = bb * 2560000 + hh * 100 + ww;
#pragma unroll
        for (int i = 0; i < 4; i++) {
            int ch = ch0 + w * 4 + i;
            sm[w * 4 + i][lane] = x[base + ch * 10000];
        }
    }
    __syncthreads();

#pragma unroll
    for (int i = 0; i < 4; i++) {
        int tl = w * 4 + i;
        float v = sm[lane][tl];
        ush h, l;
        splitf(v, h, l);
        size_t o = (size_t)(tk0 + tl) * DCH + ch0 + lane;
        xh[o] = h;
        xl[o] = l;
    }
}

// ---------------------------------------------------------------------------
// split-bf16 tensor-core GEMM: cp.async double-buffer + ldmatrix.
// C[M,N] = A[M,K] @ B[N,K]^T ; A,B hi/lo bf16 planes.
// mode 0: C fp32   mode 1: gelu(C+bias) -> planes   mode 2: scatter+residual
// mode 3: C -> hi plane only
// ---------------------------------------------------------------------------
#define SB   80           // smem row stride bytes (64 data + 16 pad)
#define PLB  10240        // one plane: 128 rows * SB
#define BUFB 40960        // 4 planes
#define GEMM_SMEM (2 * BUFB)

__global__ __launch_bounds__(256) void gemm_tc(
    const ush* __restrict__ Ah, const ush* __restrict__ Al,
    const ush* __restrict__ Bh, const ush* __restrict__ Bl,
    int M, int N, int K, int mode,
    const float* __restrict__ bias, const float* __restrict__ xres,
    float* __restrict__ outF, ush* __restrict__ oh, ush* __restrict__ ol)
{
    extern __shared__ char smem[];
    const uint32_t sbb = smem_u32(smem);
    const int tid = threadIdx.x;
    const int wid = tid >> 5, lane = tid & 31;
    const int g = lane >> 2, t = lane & 3;
    const int wm = (wid & 3) * 32;
    const int wn = (wid >> 2) * 64;
    const int row0 = blockIdx.y * 128, coln0 = blockIdx.x * 128;

    float acc[2][8][4];
#pragma unroll
    for (int i = 0; i < 2; i++)
#pragma unroll
        for (int j = 0; j < 8; j++)
#pragma unroll
            for (int q = 0; q < 4; q++) acc[i][j][q] = 0.f;

    const int nst = K >> 5;

    const int lslot0 = tid, lslot1 = tid + 256;
    const int lr0 = lslot0 >> 2, lc0 = lslot0 & 3;
    const int lr1 = lslot1 >> 2, lc1 = lslot1 & 3;
    int ga0 = row0 + lr0; if (ga0 > M - 1) ga0 = M - 1;
    int ga1 = row0 + lr1; if (ga1 > M - 1) ga1 = M - 1;

#define ISSUE(s) do {                                                          \
    int _b = (s) & 1;                                                          \
    int _k0 = (s) << 5;                                                        \
    uint32_t _d0 = sbb + _b * BUFB + lr0 * SB + lc0 * 16;                      \
    size_t _gaa = (size_t)ga0 * K + _k0 + lc0 * 8;                             \
    size_t _gbb = (size_t)(coln0 + lr0) * K + _k0 + lc0 * 8;                   \
    CP_ASYNC16(_d0,            Ah + _gaa);                                     \
    CP_ASYNC16(_d0 + PLB,      Al + _gaa);                                     \
    CP_ASYNC16(_d0 + 2 * PLB,  Bh + _gbb);                                     \
    CP_ASYNC16(_d0 + 3 * PLB,  Bl + _gbb);                                     \
    uint32_t _d1 = sbb + _b * BUFB + lr1 * SB + lc1 * 16;                      \
    size_t _ga2 = (size_t)ga1 * K + _k0 + lc1 * 8;                             \
    size_t _gb2 = (size_t)(coln0 + lr1) * K + _k0 + lc1 * 8;                   \
    CP_ASYNC16(_d1,            Ah + _ga2);                                     \
    CP_ASYNC16(_d1 + PLB,      Al + _ga2);                                     \
    CP_ASYNC16(_d1 + 2 * PLB,  Bh + _gb2);                                     \
    CP_ASYNC16(_d1 + 3 * PLB,  Bl + _gb2);                                     \
} while (0)

    ISSUE(0); CP_COMMIT();

    const int arow = (lane & 7) + ((lane >> 3) & 1) * 8;
    const int kh = (lane >> 4) * 16;

    for (int s = 0; s < nst; s++) {
        if (s + 1 < nst) { ISSUE(s + 1); CP_COMMIT(); CP_WAIT1(); }
        else             { CP_WAIT0(); }
        __syncthreads();

        const uint32_t pa = sbb + (s & 1) * BUFB;
        const uint32_t pb = pa + 2 * PLB;
#pragma unroll
        for (int ks = 0; ks < 2; ks++) {
            const uint32_t cb = ks * 32 + kh;
            uint32_t ah[2][4], al[2][4];
#pragma unroll
            for (int mt = 0; mt < 2; mt++) {
                uint32_t ad = pa + (wm + mt * 16 + arow) * SB + cb;
                ldm_x4(ah[mt][0], ah[mt][1], ah[mt][2], ah[mt][3], ad);
                ldm_x4(al[mt][0], al[mt][1], al[mt][2], al[mt][3], ad + PLB);
            }
            uint32_t bh[8][2], bl[8][2];
#pragma unroll
            for (int p = 0; p < 4; p++) {
                uint32_t bd = pb + (wn + p * 16 + arow) * SB + cb;
                ldm_x4(bh[2 * p][0], bh[2 * p + 1][0], bh[2 * p][1], bh[2 * p + 1][1], bd);
                ldm_x4(bl[2 * p][0], bl[2 * p + 1][0], bl[2 * p][1], bl[2 * p + 1][1], bd + PLB);
            }
#pragma unroll
            for (int mt = 0; mt < 2; mt++)
#pragma unroll
                for (int nt = 0; nt < 8; nt++) {
                    mma16816(acc[mt][nt], ah[mt][0], ah[mt][1], ah[mt][2], ah[mt][3],
                             bh[nt][0], bh[nt][1]);
                    mma16816(acc[mt][nt], ah[mt][0], ah[mt][1], ah[mt][2], ah[mt][3],
                             bl[nt][0], bl[nt][1]);
                    mma16816(acc[mt][nt], al[mt][0], al[mt][1], al[mt][2], al[mt][3],
                             bh[nt][0], bh[nt][1]);
                }
        }
        __syncthreads();
    }
#undef ISSUE

    // ---- epilogue ----
#pragma unroll
    for (int mt = 0; mt < 2; mt++) {
#pragma unroll
        for (int half = 0; half < 2; half++) {
            int r = row0 + wm + mt * 16 + g + half * 8;
            if (r >= M) continue;
#pragma unroll
            for (int nt = 0; nt < 8; nt++) {
                int col = coln0 + wn + nt * 8 + 2 * t;
                float v0 = acc[mt][nt][half * 2 + 0];
                float v1 = acc[mt][nt][half * 2 + 1];
                if (mode == 0) {
                    *(float2*)(outF + (size_t)r * N + col) = make_float2(v0, v1);
                } else if (mode == 3) {
                    ushort2 hh;
                    hh.x = __bfloat16_as_ushort(__float2bfloat16_rn(v0));
                    hh.y = __bfloat16_as_ushort(__float2bfloat16_rn(v1));
                    *(ushort2*)(oh + (size_t)r * N + col) = hh;
                } else if (mode == 1) {
                    float g0 = gelu_exact(v0 + bias[col]);
                    float g1 = gelu_exact(v1 + bias[col + 1]);
                    ushort2 hh, ll;
                    splitf(g0, hh.x, ll.x); splitf(g1, hh.y, ll.y);
                    *(ushort2*)(oh + (size_t)r * N + col) = hh;
                    *(ushort2*)(ol + (size_t)r * N + col) = ll;
                } else {
                    int bb = r / 10000, rr = r % 10000;
                    int win = rr / 625, tt = rr % 625;
                    int hh2 = (win >> 2) * 25 + tt / 25;
                    int ww = (win & 3) * 25 + tt % 25;
                    int obase = bb * 2560000 + hh2 * 100 + ww;
                    int oi0 = obase + col * 10000;
                    int oi1 = obase + (col + 1) * 10000;
                    outF[oi0] = xres[oi0] + v0 + bias[col];
                    outF[oi1] = xres[oi1] + v1 + bias[col + 1];
                }
            }
        }
    }
}

// ---------------------------------------------------------------------------
// tensor-core windowed attention, plain bf16 (hi plane only).
// grid = (head 8, win 32, qtile 5); CTA 256 thr; warp owns 16 q-rows.
// S = QK^T (1 mma), p = exp(s*scale+bias), O += P V (1 mma).
// Output split into hi/lo planes (out-proj GEMM keeps full precision).
// ---------------------------------------------------------------------------
#define SROW 20
#define VTS 36

__global__ __launch_bounds__(256) void attn_tc(const ush* __restrict__ qh_,
                                               const float* __restrict__ table,
                                               ush* __restrict__ oh,
                                               ush* __restrict__ ol)
{
    __shared__ uint32_t QHI[128 * SROW];
    __shared__ uint32_t KHI[64 * SROW];
    __shared__ uint32_t VTH[32 * VTS];
    __shared__ float    BL[2401];
    __shared__ int      SUB[64];
    __shared__ float    VMK[64];

    const int head = blockIdx.x;
    const int win  = blockIdx.y;
    const int qt   = blockIdx.z;
    const int tid  = threadIdx.x;
    const int w = tid >> 5, lane = tid & 31;
    const int g = lane >> 2, t = tid & 3;
    const int tok0 = win * 625;
    const int qbase = qt * 128;

    for (int i = tid; i < 2401; i += 256) BL[i] = table[i * 8 + head];

    // Q tile: 128 rows x 4 chunks of 16B
#pragma unroll
    for (int it = 0; it < 2; it++) {
        int idx = it * 256 + tid;
        int r = idx >> 2, c = idx & 3;
        int qi = qbase + r;
        uint4 v = make_uint4(0, 0, 0, 0);
        if (qi < 625)
            v = *(const uint4*)(qh_ + (size_t)(tok0 + qi) * QKVN + head * 32 + c * 8);
        *(uint4*)(QHI + r * SROW + c * 4) = v;
    }
    __syncthreads();

    uint32_t qh[2][4];
    {
        int r0 = w * 16 + g;
#pragma unroll
        for (int kc = 0; kc < 2; kc++) {
            qh[kc][0] = QHI[r0 * SROW + kc * 8 + t];
            qh[kc][1] = QHI[(r0 + 8) * SROW + kc * 8 + t];
            qh[kc][2] = QHI[r0 * SROW + kc * 8 + t + 4];
            qh[kc][3] = QHI[(r0 + 8) * SROW + kc * 8 + t + 4];
        }
    }

    const int qi0 = qbase + w * 16 + g;
    const int qi1 = qi0 + 8;
    const int cq0 = qi0 < 625 ? qi0 : 624;
    const int cq1 = qi1 < 625 ? qi1 : 624;
    const int add0 = (cq0 / 25 + 24) * 49 + (cq0 % 25) + 24;
    const int add1 = (cq1 / 25 + 24) * 49 + (cq1 % 25) + 24;

    float l0 = 0.f, l1 = 0.f;
    float oacc[4][4];
#pragma unroll
    for (int i = 0; i < 4; i++)
#pragma unroll
        for (int j = 0; j < 4; j++) oacc[i][j] = 0.f;

    const float scale = 0.17677669529663687f;

    for (int kb = 0; kb < 10; kb++) {
        __syncthreads();
        // K tile: 64 rows x 4 chunks
        {
            int r = tid >> 2, c = tid & 3;
            int jg = kb * 64 + r;
            uint4 v = make_uint4(0, 0, 0, 0);
            if (jg < 625)
                v = *(const uint4*)(qh_ + (size_t)(tok0 + jg) * QKVN + 256
                                    + head * 32 + c * 8);
            *(uint4*)(KHI + r * SROW + c * 4) = v;
        }
        // V tile transposed: 32 dims x 64 keys (pairs)
#pragma unroll
        for (int it = 0; it < 4; it++) {
            int idx = it * 256 + tid;
            int d = idx & 31, jp = idx >> 5;
            int j0 = kb * 64 + jp * 2;
            size_t base0 = (size_t)(tok0 + j0) * QKVN + 512 + head * 32 + d;
            uint32_t h0 = 0, h1 = 0;
            if (j0 < 625)     h0 = qh_[base0];
            if (j0 + 1 < 625) h1 = qh_[base0 + QKVN];
            VTH[d * VTS + jp] = h0 | (h1 << 16);
        }
        if (tid < 64) {
            int jg = kb * 64 + tid;
            int jj = jg < 625 ? jg : 624;
            SUB[tid] = (jj / 25) * 49 + (jj % 25);
            VMK[tid] = (jg < 625) ? 0.f : -1e30f;
        }
        __syncthreads();

        // ---- S = Q K^T ----
        float sacc[8][4];
#pragma unroll
        for (int i = 0; i < 8; i++)
#pragma unroll
            for (int j = 0; j < 4; j++) sacc[i][j] = 0.f;

#pragma unroll
        for (int nt = 0; nt < 8; nt++) {
            int rb = nt * 8 + g;
#pragma unroll
            for (int kc = 0; kc < 2; kc++) {
                uint32_t bh0 = KHI[rb * SROW + kc * 8 + t];
                uint32_t bh1 = KHI[rb * SROW + kc * 8 + t + 4];
                mma16816(sacc[nt], qh[kc][0], qh[kc][1], qh[kc][2], qh[kc][3], bh0, bh1);
            }
        }

        // ---- bias + exp + pack P to bf16 ----
        uint32_t pha[8][2];
#pragma unroll
        for (int nt = 0; nt < 8; nt++) {
            int jl0 = nt * 8 + 2 * t;
            int jl1 = jl0 + 1;
            int s0i = SUB[jl0], s1i = SUB[jl1];
            float m0 = VMK[jl0], m1 = VMK[jl1];
            float p0 = __expf(sacc[nt][0] * scale + BL[add0 - s0i] + m0);
            float p1 = __expf(sacc[nt][1] * scale + BL[add0 - s1i] + m1);
            float p2 = __expf(sacc[nt][2] * scale + BL[add1 - s0i] + m0);
            float p3 = __expf(sacc[nt][3] * scale + BL[add1 - s1i] + m1);
            l0 += p0 + p1;
            l1 += p2 + p3;
            pha[nt][0] = pack2bf(p0, p1);
            pha[nt][1] = pack2bf(p2, p3);
        }

        // ---- O += P V ----
#pragma unroll
        for (int nt2 = 0; nt2 < 4; nt2++) {
            int dr = nt2 * 8 + g;
#pragma unroll
            for (int kc2 = 0; kc2 < 4; kc2++) {
                uint32_t bh0 = VTH[dr * VTS + kc2 * 8 + t];
                uint32_t bh1 = VTH[dr * VTS + kc2 * 8 + t + 4];
                mma16816(oacc[nt2], pha[2 * kc2][0], pha[2 * kc2][1],
                         pha[2 * kc2 + 1][0], pha[2 * kc2 + 1][1], bh0, bh1);
            }
        }
    }

    l0 += __shfl_xor_sync(0xffffffffu, l0, 1);
    l0 += __shfl_xor_sync(0xffffffffu, l0, 2);
    l1 += __shfl_xor_sync(0xffffffffu, l1, 1);
    l1 += __shfl_xor_sync(0xffffffffu, l1, 2);
    float inv0 = 1.f / l0, inv1 = 1.f / l1;

    if (qi0 < 625) {
        size_t o = (size_t)(tok0 + qi0) * DCH + head * 32;
#pragma unroll
        for (int nt2 = 0; nt2 < 4; nt2++) {
            int d = nt2 * 8 + 2 * t;
            ushort2 hh, ll;
            splitf(oacc[nt2][0] * inv0, hh.x, ll.x);
            splitf(oacc[nt2][1] * inv0, hh.y, ll.y);
            *(ushort2*)(oh + o + d) = hh;
            *(ushort2*)(ol + o + d) = ll;
        }
    }
    if (qi1 < 625) {
        size_t o = (size_t)(tok0 + qi1) * DCH + head * 32;
#pragma unroll
        for (int nt2 = 0; nt2 < 4; nt2++) {
            int d = nt2 * 8 + 2 * t;
            ushort2 hh, ll;
            splitf(oacc[nt2][2] * inv1, hh.x, ll.x);
            splitf(oacc[nt2][3] * inv1, hh.y, ll.y);
            *(ushort2*)(oh + o + d) = hh;
            *(ushort2*)(ol + o + d) = ll;
        }
    }
}

// ---------------------------------------------------------------------------
// LayerNorm over d=256: one warp per token; outputs hi/lo planes
// ---------------------------------------------------------------------------
__global__ __launch_bounds__(256) void ln_kernel(const float* __restrict__ in,
                                                 ush* __restrict__ oh,
                                                 ush* __restrict__ ol,
                                                 const float* __restrict__ g,
                                                 const float* __restrict__ b)
{
    int wid = threadIdx.x >> 5, lane = threadIdx.x & 31;
    int t = blockIdx.x * 8 + wid;
    const float4* p = (const float4*)(in + (size_t)t * DCH);
    float4 v0 = p[lane];
    float4 v1 = p[lane + 32];
    float s  = v0.x + v0.y + v0.z + v0.w + v1.x + v1.y + v1.z + v1.w;
    float ss = v0.x * v0.x + v0.y * v0.y + v0.z * v0.z + v0.w * v0.w
             + v1.x * v1.x + v1.y * v1.y + v1.z * v1.z + v1.w * v1.w;
#pragma unroll
    for (int off = 16; off > 0; off >>= 1) {
        s  += __shfl_xor_sync(0xffffffffu, s, off);
        ss += __shfl_xor_sync(0xffffffffu, ss, off);
    }
    float mean = s * (1.f / 256.f);
    float var  = ss * (1.f / 256.f) - mean * mean;
    float rstd = rsqrtf(var + 1e-5f);

    const float4* g4 = (const float4*)g;
    const float4* b4 = (const float4*)b;
    float4 ga = g4[lane], gb = g4[lane + 32];
    float4 ba = b4[lane], bb = b4[lane + 32];

    ushort4 h0, l0_, h1, l1_;
    splitf((v0.x - mean) * rstd * ga.x + ba.x, h0.x, l0_.x);
    splitf((v0.y - mean) * rstd * ga.y + ba.y, h0.y, l0_.y);
    splitf((v0.z - mean) * rstd * ga.z + ba.z, h0.z, l0_.z);
    splitf((v0.w - mean) * rstd * ga.w + ba.w, h0.w, l0_.w);
    splitf((v1.x - mean) * rstd * gb.x + bb.x, h1.x, l1_.x);
    splitf((v1.y - mean) * rstd * gb.y + bb.y, h1.y, l1_.y);
    splitf((v1.z - mean) * rstd * gb.z + bb.z, h1.z, l1_.z);
    splitf((v1.w - mean) * rstd * gb.w + bb.w, h1.w, l1_.w);

    size_t o = (size_t)t * DCH;
    *(ushort4*)(oh + o + lane * 4)       = h0;
    *(ushort4*)(ol + o + lane * 4)       = l0_;
    *(ushort4*)(oh + o + 128 + lane * 4) = h1;
    *(ushort4*)(ol + o + 128 + lane * 4) = l1_;
}

// ---------------------------------------------------------------------------
extern "C" void kernel_launch(void* const* d_in, const int* in_sizes, int n_in,
                              void* d_out, int out_size)
{
    const float* x      = (const float*)d_in[0];
    const float* w_qkv  = (const float*)d_in[1];
    const float* w_out  = (const float*)d_in[2];
    const float* table  = (const float*)d_in[3];
    const float* gamma2 = (const float*)d_in[4];
    const float* beta2  = (const float*)d_in[5];
    const float* w1     = (const float*)d_in[6];
    const float* b1     = (const float*)d_in[7];
    const float* w2     = (const float*)d_in[8];
    const float* b2     = (const float*)d_in[9];
    float* out = (float*)d_out;

    ush *xwh, *xwl, *qh, *ath, *atl, *lnh, *lnl, *hih, *hil, *wh, *wl;
    float *proj;
    cudaGetSymbolAddress((void**)&xwh, g_xw_h);
    cudaGetSymbolAddress((void**)&xwl, g_xw_l);
    cudaGetSymbolAddress((void**)&qh,  g_qkv_h);
    cudaGetSymbolAddress((void**)&ath, g_att_h);
    cudaGetSymbolAddress((void**)&atl, g_att_l);
    cudaGetSymbolAddress((void**)&proj, g_proj);
    cudaGetSymbolAddress((void**)&lnh, g_ln_h);
    cudaGetSymbolAddress((void**)&lnl, g_ln_l);
    cudaGetSymbolAddress((void**)&hih, g_hid_h);
    cudaGetSymbolAddress((void**)&hil, g_hid_l);
    cudaGetSymbolAddress((void**)&wh,  g_w_h);
    cudaGetSymbolAddress((void**)&wl,  g_w_l);

    cudaFuncSetAttribute(gemm_tc, cudaFuncAttributeMaxDynamicSharedMemorySize, GEMM_SMEM);

    // 0) weights -> concatenated hi/lo planes (one launch)
    cvt4_kernel<<<WTOT / 4 / 256, 256>>>(w_qkv, w_out, w1, w2, wh, wl);

    // 1) window partition (transposed, coalesced)
    gather_kernel<<<dim3(625, 8), 256>>>(x, xwh, xwl);
    // 2) QKV projection -> hi plane only (attention is plain bf16)
    gemm_tc<<<dim3(6, 157), 256, GEMM_SMEM>>>(xwh, xwl, wh + WQ, wl + WQ,
        TOK, QKVN, DCH, 3, nullptr, nullptr, nullptr, qh, nullptr);
    // 3) tensor-core windowed attention (bf16) -> hi/lo planes
    attn_tc<<<dim3(8, 32, 5), 256>>>(qh, table, ath, atl);
    // 4) output projection -> fp32
    gemm_tc<<<dim3(2, 157), 256, GEMM_SMEM>>>(ath, atl, wh + WO, wl + WO,
        TOK, DCH, DCH, 0, nullptr, nullptr, proj, nullptr, nullptr);
    // 5) layernorm -> planes
    ln_kernel<<<2500, 256>>>(proj, lnh, lnl, gamma2, beta2);
    // 6) MLP fc1 + exact GELU -> planes
    gemm_tc<<<dim3(4, 157), 256, GEMM_SMEM>>>(lnh, lnl, wh + W1, wl + W1,
        TOK, HID, DCH, 1, b1, nullptr, nullptr, hih, hil);
    // 7) MLP fc2 + bias + un-partition + residual -> d_out
    gemm_tc<<<dim3(2, 157), 256, GEMM_SMEM>>>(hih, hil, wh + W2, wl + W2,
        TOK, DCH, HID, 2, b2, x, out, nullptr, nullptr);
}

// round 7
// speedup vs baseline: 2.1210x; 1.7156x over previous
#include <cuda_runtime.h>
#include <cuda_bf16.h>
#include <cstdint>
#include <math.h>

#define TOK 20000      // 2 * 16 windows * 625 tokens
#define DCH 256
#define QKVN 768
#define HID 512

typedef unsigned short ush;

// ---- scratch: plain bf16 planes ----
__device__ ush g_xw  [TOK * DCH];
__device__ ush g_qkv [TOK * QKVN];
__device__ ush g_att [TOK * DCH];
__device__ float g_proj[TOK * DCH];
__device__ ush g_ln  [TOK * DCH];
__device__ ush g_hid [TOK * HID];
// all four weight matrices concatenated: wqkv | wout | w1 | w2
#define WQ 0
#define WO 196608
#define W1 262144
#define W2 393216
#define WTOT 524288
__device__ ush g_w[WTOT];

// ---------------------------------------------------------------------------
// helpers
// ---------------------------------------------------------------------------
__device__ __forceinline__ uint32_t smem_u32(const void* p) {
    uint32_t a;
    asm("{ .reg .u64 t; cvta.to.shared.u64 t, %1; cvt.u32.u64 %0, t; }" : "=r"(a) : "l"(p));
    return a;
}
#define CP_ASYNC16(dst, src) \
    asm volatile("cp.async.cg.shared.global [%0], [%1], 16;" :: "r"(dst), "l"(src))
#define CP_COMMIT() asm volatile("cp.async.commit_group;")
#define CP_WAIT1()  asm volatile("cp.async.wait_group 1;")
#define CP_WAIT0()  asm volatile("cp.async.wait_group 0;")

__device__ __forceinline__ void ldm_x4(uint32_t& d0, uint32_t& d1, uint32_t& d2,
                                       uint32_t& d3, uint32_t addr)
{
    asm volatile("ldmatrix.sync.aligned.m8n8.x4.shared.b16 {%0,%1,%2,%3}, [%4];"
                 : "=r"(d0), "=r"(d1), "=r"(d2), "=r"(d3) : "r"(addr));
}

__device__ __forceinline__ void mma16816(float c[4], uint32_t a0, uint32_t a1,
                                         uint32_t a2, uint32_t a3,
                                         uint32_t b0, uint32_t b1)
{
    asm volatile(
        "mma.sync.aligned.m16n8k16.row.col.f32.bf16.bf16.f32 "
        "{%0,%1,%2,%3}, {%4,%5,%6,%7}, {%8,%9}, {%0,%1,%2,%3};"
        : "+f"(c[0]), "+f"(c[1]), "+f"(c[2]), "+f"(c[3])
        : "r"(a0), "r"(a1), "r"(a2), "r"(a3), "r"(b0), "r"(b1));
}

__device__ __forceinline__ ush bfr(float f) {
    return __bfloat16_as_ushort(__float2bfloat16_rn(f));
}
__device__ __forceinline__ uint32_t pack2bf(float a, float b) {
    return (uint32_t)bfr(a) | ((uint32_t)bfr(b) << 16);
}

__device__ __forceinline__ float gelu_exact(float v)
{
    return 0.5f * v * (1.0f + erff(v * 0.70710678118654752f));
}

// ---------------------------------------------------------------------------
// merged weight conversion: 4 fp32 weight tensors -> one concatenated bf16 plane
// ---------------------------------------------------------------------------
__global__ __launch_bounds__(256) void cvt4_kernel(
    const float* __restrict__ s0, const float* __restrict__ s1,
    const float* __restrict__ s2, const float* __restrict__ s3,
    ush* __restrict__ h)
{
    int base = (blockIdx.x * blockDim.x + threadIdx.x) * 4;
    if (base >= WTOT) return;
    const float* src;
    int off;
    if (base < WO)      { src = s0; off = base; }
    else if (base < W1) { src = s1; off = base - WO; }
    else if (base < W2) { src = s2; off = base - W1; }
    else                { src = s3; off = base - W2; }
    float4 v = *(const float4*)(src + off);
    ushort4 hh;
    hh.x = bfr(v.x); hh.y = bfr(v.y); hh.z = bfr(v.z); hh.w = bfr(v.w);
    *(ushort4*)(h + base) = hh;
}

// ---------------------------------------------------------------------------
// window partition with smem transpose: x (2,256,100,100) -> bf16 (20000,256)
// ---------------------------------------------------------------------------
__global__ __launch_bounds__(256) void gather_kernel(const float* __restrict__ x,
                                                     ush* __restrict__ xh)
{
    __shared__ float sm[32][33];
    const int w = threadIdx.x >> 5, lane = threadIdx.x & 31;
    const int tk0 = blockIdx.x * 32;       // 625 blocks
    const int ch0 = blockIdx.y * 32;       // 8 blocks

    {
        int tk = tk0 + lane;
        int bb = tk / 10000, rr = tk % 10000;
        int win = rr / 625, t = rr % 625;
        int hh = (win >> 2) * 25 + t / 25;
        int ww = (win & 3) * 25 + t % 25;
        int base = bb * 2560000 + hh * 100 + ww;
#pragma unroll
        for (int i = 0; i < 4; i++) {
            int ch = ch0 + w * 4 + i;
            sm[w * 4 + i][lane] = x[base + ch * 10000];
        }
    }
    __syncthreads();

#pragma unroll
    for (int i = 0; i < 4; i++) {
        int tl = w * 4 + i;
        xh[(size_t)(tk0 + tl) * DCH + ch0 + lane] = bfr(sm[lane][tl]);
    }
}

// ---------------------------------------------------------------------------
// plain-bf16 tensor-core GEMM: cp.async double-buffer + ldmatrix.
// C[M,N] = A[M,K] @ B[N,K]^T
// mode 0: C fp32   mode 1: gelu(C+bias) -> bf16   mode 2: scatter+residual
// mode 3: C -> bf16
// ---------------------------------------------------------------------------
#define SB   80           // smem row stride bytes (64 data + 16 pad)
#define PLB  10240        // one matrix tile: 128 rows * SB
#define BUFB 20480        // A + B
#define GEMM_SMEM (2 * BUFB)

__global__ __launch_bounds__(256) void gemm_tc(
    const ush* __restrict__ Ah, const ush* __restrict__ Bh,
    int M, int N, int K, int mode,
    const float* __restrict__ bias, const float* __restrict__ xres,
    float* __restrict__ outF, ush* __restrict__ oh)
{
    extern __shared__ char smem[];
    const uint32_t sbb = smem_u32(smem);
    const int tid = threadIdx.x;
    const int wid = tid >> 5, lane = tid & 31;
    const int g = lane >> 2, t = lane & 3;
    const int wm = (wid & 3) * 32;
    const int wn = (wid >> 2) * 64;
    const int row0 = blockIdx.y * 128, coln0 = blockIdx.x * 128;

    float acc[2][8][4];
#pragma unroll
    for (int i = 0; i < 2; i++)
#pragma unroll
        for (int j = 0; j < 8; j++)
#pragma unroll
            for (int q = 0; q < 4; q++) acc[i][j][q] = 0.f;

    const int nst = K >> 5;

    // loader: 512 16B-slots per matrix; thread covers slot tid and tid+256
    const int lr0 = tid >> 2, lc0 = tid & 3;
    const int lr1 = 64 + (tid >> 2);
    int ga0 = row0 + lr0; if (ga0 > M - 1) ga0 = M - 1;
    int ga1 = row0 + lr1; if (ga1 > M - 1) ga1 = M - 1;

#define ISSUE(s) do {                                                          \
    int _b = (s) & 1;                                                          \
    int _k0 = (s) << 5;                                                        \
    uint32_t _d0 = sbb + _b * BUFB + lr0 * SB + lc0 * 16;                      \
    CP_ASYNC16(_d0,       Ah + (size_t)ga0 * K + _k0 + lc0 * 8);               \
    CP_ASYNC16(_d0 + PLB, Bh + (size_t)(coln0 + lr0) * K + _k0 + lc0 * 8);     \
    uint32_t _d1 = sbb + _b * BUFB + lr1 * SB + lc0 * 16;                      \
    CP_ASYNC16(_d1,       Ah + (size_t)ga1 * K + _k0 + lc0 * 8);               \
    CP_ASYNC16(_d1 + PLB, Bh + (size_t)(coln0 + lr1) * K + _k0 + lc0 * 8);     \
} while (0)

    ISSUE(0); CP_COMMIT();

    const int arow = (lane & 7) + ((lane >> 3) & 1) * 8;
    const int kh = (lane >> 4) * 16;

    for (int s = 0; s < nst; s++) {
        if (s + 1 < nst) { ISSUE(s + 1); CP_COMMIT(); CP_WAIT1(); }
        else             { CP_WAIT0(); }
        __syncthreads();

        const uint32_t pa = sbb + (s & 1) * BUFB;
        const uint32_t pb = pa + PLB;
#pragma unroll
        for (int ks = 0; ks < 2; ks++) {
            const uint32_t cb = ks * 32 + kh;
            uint32_t ah[2][4];
#pragma unroll
            for (int mt = 0; mt < 2; mt++) {
                uint32_t ad = pa + (wm + mt * 16 + arow) * SB + cb;
                ldm_x4(ah[mt][0], ah[mt][1], ah[mt][2], ah[mt][3], ad);
            }
            uint32_t bh[8][2];
#pragma unroll
            for (int p = 0; p < 4; p++) {
                uint32_t bd = pb + (wn + p * 16 + arow) * SB + cb;
                ldm_x4(bh[2 * p][0], bh[2 * p + 1][0], bh[2 * p][1], bh[2 * p + 1][1], bd);
            }
#pragma unroll
            for (int mt = 0; mt < 2; mt++)
#pragma unroll
                for (int nt = 0; nt < 8; nt++)
                    mma16816(acc[mt][nt], ah[mt][0], ah[mt][1], ah[mt][2], ah[mt][3],
                             bh[nt][0], bh[nt][1]);
        }
        __syncthreads();
    }
#undef ISSUE

    // ---- epilogue ----
#pragma unroll
    for (int mt = 0; mt < 2; mt++) {
#pragma unroll
        for (int half = 0; half < 2; half++) {
            int r = row0 + wm + mt * 16 + g + half * 8;
            if (r >= M) continue;
#pragma unroll
            for (int nt = 0; nt < 8; nt++) {
                int col = coln0 + wn + nt * 8 + 2 * t;
                float v0 = acc[mt][nt][half * 2 + 0];
                float v1 = acc[mt][nt][half * 2 + 1];
                if (mode == 0) {
                    *(float2*)(outF + (size_t)r * N + col) = make_float2(v0, v1);
                } else if (mode == 3) {
                    ushort2 hh;
                    hh.x = bfr(v0); hh.y = bfr(v1);
                    *(ushort2*)(oh + (size_t)r * N + col) = hh;
                } else if (mode == 1) {
                    ushort2 hh;
                    hh.x = bfr(gelu_exact(v0 + bias[col]));
                    hh.y = bfr(gelu_exact(v1 + bias[col + 1]));
                    *(ushort2*)(oh + (size_t)r * N + col) = hh;
                } else {
                    int bb = r / 10000, rr = r % 10000;
                    int win = rr / 625, tt = rr % 625;
                    int hh2 = (win >> 2) * 25 + tt / 25;
                    int ww = (win & 3) * 25 + tt % 25;
                    int obase = bb * 2560000 + hh2 * 100 + ww;
                    int oi0 = obase + col * 10000;
                    int oi1 = obase + (col + 1) * 10000;
                    outF[oi0] = xres[oi0] + v0 + bias[col];
                    outF[oi1] = xres[oi1] + v1 + bias[col + 1];
                }
            }
        }
    }
}

// ---------------------------------------------------------------------------
// tensor-core windowed attention, plain bf16, ldmatrix fragment loads.
// grid = (head 8, win 32, qtile 5); CTA 256 thr; warp owns 16 q-rows.
// ---------------------------------------------------------------------------
#define SROW 20
#define SBK  80     // K-tile row stride bytes (= SROW words)
#define VTS  36
#define SBV  144    // V-tile row stride bytes (= VTS words)

__global__ __launch_bounds__(256) void attn_tc(const ush* __restrict__ qh_,
                                               const float* __restrict__ table,
                                               ush* __restrict__ oh)
{
    __shared__ uint32_t QHI[128 * SROW];
    __shared__ uint32_t KHI[64 * SROW];
    __shared__ uint32_t VTH[32 * VTS];
    __shared__ float    BL[2401];
    __shared__ int      SUB[64];
    __shared__ float    VMK[64];

    const int head = blockIdx.x;
    const int win  = blockIdx.y;
    const int qt   = blockIdx.z;
    const int tid  = threadIdx.x;
    const int w = tid >> 5, lane = tid & 31;
    const int g = lane >> 2, t = tid & 3;
    const int tok0 = win * 625;
    const int qbase = qt * 128;
    const int arow = (lane & 7) + ((lane >> 3) & 1) * 8;
    const int kh = (lane >> 4) * 16;
    const uint32_t Kb = smem_u32(KHI);
    const uint32_t Vb = smem_u32(VTH);

    for (int i = tid; i < 2401; i += 256) BL[i] = table[i * 8 + head];

    // Q tile: 128 rows x 4 chunks of 16B
#pragma unroll
    for (int it = 0; it < 2; it++) {
        int idx = it * 256 + tid;
        int r = idx >> 2, c = idx & 3;
        int qi = qbase + r;
        uint4 v = make_uint4(0, 0, 0, 0);
        if (qi < 625)
            v = *(const uint4*)(qh_ + (size_t)(tok0 + qi) * QKVN + head * 32 + c * 8);
        *(uint4*)(QHI + r * SROW + c * 4) = v;
    }
    __syncthreads();

    uint32_t qh[2][4];
    {
        int r0 = w * 16 + g;
#pragma unroll
        for (int kc = 0; kc < 2; kc++) {
            qh[kc][0] = QHI[r0 * SROW + kc * 8 + t];
            qh[kc][1] = QHI[(r0 + 8) * SROW + kc * 8 + t];
            qh[kc][2] = QHI[r0 * SROW + kc * 8 + t + 4];
            qh[kc][3] = QHI[(r0 + 8) * SROW + kc * 8 + t + 4];
        }
    }

    const int qi0 = qbase + w * 16 + g;
    const int qi1 = qi0 + 8;
    const int cq0 = qi0 < 625 ? qi0 : 624;
    const int cq1 = qi1 < 625 ? qi1 : 624;
    const int add0 = (cq0 / 25 + 24) * 49 + (cq0 % 25) + 24;
    const int add1 = (cq1 / 25 + 24) * 49 + (cq1 % 25) + 24;

    float l0 = 0.f, l1 = 0.f;
    float oacc[4][4];
#pragma unroll
    for (int i = 0; i < 4; i++)
#pragma unroll
        for (int j = 0; j < 4; j++) oacc[i][j] = 0.f;

    const float scale = 0.17677669529663687f;

    for (int kb = 0; kb < 10; kb++) {
        __syncthreads();
        // K tile: 64 rows x 4 chunks
        {
            int r = tid >> 2, c = tid & 3;
            int jg = kb * 64 + r;
            uint4 v = make_uint4(0, 0, 0, 0);
            if (jg < 625)
                v = *(const uint4*)(qh_ + (size_t)(tok0 + jg) * QKVN + 256
                                    + head * 32 + c * 8);
            *(uint4*)(KHI + r * SROW + c * 4) = v;
        }
        // V tile transposed: 32 dims x 64 keys (pairs)
#pragma unroll
        for (int it = 0; it < 4; it++) {
            int idx = it * 256 + tid;
            int d = idx & 31, jp = idx >> 5;
            int j0 = kb * 64 + jp * 2;
            size_t base0 = (size_t)(tok0 + j0) * QKVN + 512 + head * 32 + d;
            uint32_t h0 = 0, h1 = 0;
            if (j0 < 625)     h0 = qh_[base0];
            if (j0 + 1 < 625) h1 = qh_[base0 + QKVN];
            VTH[d * VTS + jp] = h0 | (h1 << 16);
        }
        if (tid < 64) {
            int jg = kb * 64 + tid;
            int jj = jg < 625 ? jg : 624;
            SUB[tid] = (jj / 25) * 49 + (jj % 25);
            VMK[tid] = (jg < 625) ? 0.f : -1e30f;
        }
        __syncthreads();

        // ---- S = Q K^T  (ldmatrix K fragments) ----
        float sacc[8][4];
#pragma unroll
        for (int i = 0; i < 8; i++)
#pragma unroll
            for (int j = 0; j < 4; j++) sacc[i][j] = 0.f;

#pragma unroll
        for (int p = 0; p < 4; p++) {
            uint32_t base = Kb + (p * 16 + arow) * SBK + kh;
            uint32_t kA0, kA1, kA2, kA3, kB0, kB1, kB2, kB3;
            ldm_x4(kA0, kA1, kA2, kA3, base);        // kc = 0
            ldm_x4(kB0, kB1, kB2, kB3, base + 32);   // kc = 1
            mma16816(sacc[2 * p],     qh[0][0], qh[0][1], qh[0][2], qh[0][3], kA0, kA2);
            mma16816(sacc[2 * p + 1], qh[0][0], qh[0][1], qh[0][2], qh[0][3], kA1, kA3);
            mma16816(sacc[2 * p],     qh[1][0], qh[1][1], qh[1][2], qh[1][3], kB0, kB2);
            mma16816(sacc[2 * p + 1], qh[1][0], qh[1][1], qh[1][2], qh[1][3], kB1, kB3);
        }

        // ---- bias + exp + pack P ----
        uint32_t pha[8][2];
#pragma unroll
        for (int nt = 0; nt < 8; nt++) {
            int jl0 = nt * 8 + 2 * t;
            int jl1 = jl0 + 1;
            int s0i = SUB[jl0], s1i = SUB[jl1];
            float m0 = VMK[jl0], m1 = VMK[jl1];
            float p0 = __expf(sacc[nt][0] * scale + BL[add0 - s0i] + m0);
            float p1 = __expf(sacc[nt][1] * scale + BL[add0 - s1i] + m1);
            float p2 = __expf(sacc[nt][2] * scale + BL[add1 - s0i] + m0);
            float p3 = __expf(sacc[nt][3] * scale + BL[add1 - s1i] + m1);
            l0 += p0 + p1;
            l1 += p2 + p3;
            pha[nt][0] = pack2bf(p0, p1);
            pha[nt][1] = pack2bf(p2, p3);
        }

        // ---- O += P V  (ldmatrix V fragments) ----
#pragma unroll
        for (int p2 = 0; p2 < 2; p2++) {
            uint32_t vbase = Vb + (p2 * 16 + arow) * SBV + kh;
#pragma unroll
            for (int kc2 = 0; kc2 < 4; kc2++) {
                uint32_t v0, v1, v2, v3;
                ldm_x4(v0, v1, v2, v3, vbase + kc2 * 32);
                mma16816(oacc[2 * p2], pha[2 * kc2][0], pha[2 * kc2][1],
                         pha[2 * kc2 + 1][0], pha[2 * kc2 + 1][1], v0, v2);
                mma16816(oacc[2 * p2 + 1], pha[2 * kc2][0], pha[2 * kc2][1],
                         pha[2 * kc2 + 1][0], pha[2 * kc2 + 1][1], v1, v3);
            }
        }
    }

    l0 += __shfl_xor_sync(0xffffffffu, l0, 1);
    l0 += __shfl_xor_sync(0xffffffffu, l0, 2);
    l1 += __shfl_xor_sync(0xffffffffu, l1, 1);
    l1 += __shfl_xor_sync(0xffffffffu, l1, 2);
    float inv0 = 1.f / l0, inv1 = 1.f / l1;

    if (qi0 < 625) {
        size_t o = (size_t)(tok0 + qi0) * DCH + head * 32;
#pragma unroll
        for (int nt2 = 0; nt2 < 4; nt2++) {
            int d = nt2 * 8 + 2 * t;
            ushort2 hh;
            hh.x = bfr(oacc[nt2][0] * inv0);
            hh.y = bfr(oacc[nt2][1] * inv0);
            *(ushort2*)(oh + o + d) = hh;
        }
    }
    if (qi1 < 625) {
        size_t o = (size_t)(tok0 + qi1) * DCH + head * 32;
#pragma unroll
        for (int nt2 = 0; nt2 < 4; nt2++) {
            int d = nt2 * 8 + 2 * t;
            ushort2 hh;
            hh.x = bfr(oacc[nt2][2] * inv1);
            hh.y = bfr(oacc[nt2][3] * inv1);
            *(ushort2*)(oh + o + d) = hh;
        }
    }
}

// ---------------------------------------------------------------------------
// LayerNorm over d=256: one warp per token; output bf16
// ---------------------------------------------------------------------------
__global__ __launch_bounds__(256) void ln_kernel(const float* __restrict__ in,
                                                 ush* __restrict__ oh,
                                                 const float* __restrict__ g,
                                                 const float* __restrict__ b)
{
    int wid = threadIdx.x >> 5, lane = threadIdx.x & 31;
    int t = blockIdx.x * 8 + wid;
    const float4* p = (const float4*)(in + (size_t)t * DCH);
    float4 v0 = p[lane];
    float4 v1 = p[lane + 32];
    float s  = v0.x + v0.y + v0.z + v0.w + v1.x + v1.y + v1.z + v1.w;
    float ss = v0.x * v0.x + v0.y * v0.y + v0.z * v0.z + v0.w * v0.w
             + v1.x * v1.x + v1.y * v1.y + v1.z * v1.z + v1.w * v1.w;
#pragma unroll
    for (int off = 16; off > 0; off >>= 1) {
        s  += __shfl_xor_sync(0xffffffffu, s, off);
        ss += __shfl_xor_sync(0xffffffffu, ss, off);
    }
    float mean = s * (1.f / 256.f);
    float var  = ss * (1.f / 256.f) - mean * mean;
    float rstd = rsqrtf(var + 1e-5f);

    const float4* g4 = (const float4*)g;
    const float4* b4 = (const float4*)b;
    float4 ga = g4[lane], gb = g4[lane + 32];
    float4 ba = b4[lane], bb = b4[lane + 32];

    ushort4 h0, h1;
    h0.x = bfr((v0.x - mean) * rstd * ga.x + ba.x);
    h0.y = bfr((v0.y - mean) * rstd * ga.y + ba.y);
    h0.z = bfr((v0.z - mean) * rstd * ga.z + ba.z);
    h0.w = bfr((v0.w - mean) * rstd * ga.w + ba.w);
    h1.x = bfr((v1.x - mean) * rstd * gb.x + bb.x);
    h1.y = bfr((v1.y - mean) * rstd * gb.y + bb.y);
    h1.z = bfr((v1.z - mean) * rstd * gb.z + bb.z);
    h1.w = bfr((v1.w - mean) * rstd * gb.w + bb.w);

    size_t o = (size_t)t * DCH;
    *(ushort4*)(oh + o + lane * 4)       = h0;
    *(ushort4*)(oh + o + 128 + lane * 4) = h1;
}

// ---------------------------------------------------------------------------
extern "C" void kernel_launch(void* const* d_in, const int* in_sizes, int n_in,
                              void* d_out, int out_size)
{
    const float* x      = (const float*)d_in[0];
    const float* w_qkv  = (const float*)d_in[1];
    const float* w_out  = (const float*)d_in[2];
    const float* table  = (const float*)d_in[3];
    const float* gamma2 = (const float*)d_in[4];
    const float* beta2  = (const float*)d_in[5];
    const float* w1     = (const float*)d_in[6];
    const float* b1     = (const float*)d_in[7];
    const float* w2     = (const float*)d_in[8];
    const float* b2     = (const float*)d_in[9];
    float* out = (float*)d_out;

    ush *xw, *qkv, *att, *ln, *hid, *wv;
    float *proj;
    cudaGetSymbolAddress((void**)&xw,  g_xw);
    cudaGetSymbolAddress((void**)&qkv, g_qkv);
    cudaGetSymbolAddress((void**)&att, g_att);
    cudaGetSymbolAddress((void**)&proj, g_proj);
    cudaGetSymbolAddress((void**)&ln,  g_ln);
    cudaGetSymbolAddress((void**)&hid, g_hid);
    cudaGetSymbolAddress((void**)&wv,  g_w);

    cudaFuncSetAttribute(gemm_tc, cudaFuncAttributeMaxDynamicSharedMemorySize, GEMM_SMEM);

    // 0) weights -> bf16 plane (one launch)
    cvt4_kernel<<<WTOT / 4 / 256, 256>>>(w_qkv, w_out, w1, w2, wv);

    // 1) window partition (transposed, coalesced)
    gather_kernel<<<dim3(625, 8), 256>>>(x, xw);
    // 2) QKV projection -> bf16
    gemm_tc<<<dim3(6, 157), 256, GEMM_SMEM>>>(xw, wv + WQ,
        TOK, QKVN, DCH, 3, nullptr, nullptr, nullptr, qkv);
    // 3) tensor-core windowed attention -> bf16
    attn_tc<<<dim3(8, 32, 5), 256>>>(qkv, table, att);
    // 4) output projection -> fp32
    gemm_tc<<<dim3(2, 157), 256, GEMM_SMEM>>>(att, wv + WO,
        TOK, DCH, DCH, 0, nullptr, nullptr, proj, nullptr);
    // 5) layernorm -> bf16
    ln_kernel<<<2500, 256>>>(proj, ln, gamma2, beta2);
    // 6) MLP fc1 + exact GELU -> bf16
    gemm_tc<<<dim3(4, 157), 256, GEMM_SMEM>>>(ln, wv + W1,
        TOK, HID, DCH, 1, b1, nullptr, nullptr, hid);
    // 7) MLP fc2 + bias + un-partition + residual -> d_out
    gemm_tc<<<dim3(2, 157), 256, GEMM_SMEM>>>(hid, wv + W2,
        TOK, DCH, HID, 2, b2, x, out, nullptr);
}

// round 8
// speedup vs baseline: 2.2293x; 1.0511x over previous
#include <cuda_runtime.h>
#include <cuda_bf16.h>
#include <cstdint>
#include <math.h>

#define TOK 20000      // 2 * 16 windows * 625 tokens
#define DCH 256
#define QKVN 768
#define HID 512

typedef unsigned short ush;

// ---- scratch: plain bf16 planes ----
__device__ ush g_xw  [TOK * DCH];
__device__ ush g_qkv [TOK * QKVN];
__device__ ush g_att [TOK * DCH];
__device__ float g_proj[TOK * DCH];
__device__ ush g_ln  [TOK * DCH];
__device__ ush g_hid [TOK * HID];
// all four weight matrices concatenated: wqkv | wout | w1 | w2
#define WQ 0
#define WO 196608
#define W1 262144
#define W2 393216
#define WTOT 524288
__device__ ush g_w[WTOT];

// ---------------------------------------------------------------------------
// helpers
// ---------------------------------------------------------------------------
__device__ __forceinline__ uint32_t smem_u32(const void* p) {
    uint32_t a;
    asm("{ .reg .u64 t; cvta.to.shared.u64 t, %1; cvt.u32.u64 %0, t; }" : "=r"(a) : "l"(p));
    return a;
}
#define CP_ASYNC16(dst, src) \
    asm volatile("cp.async.cg.shared.global [%0], [%1], 16;" :: "r"(dst), "l"(src))
#define CP_COMMIT() asm volatile("cp.async.commit_group;")
#define CP_WAIT1()  asm volatile("cp.async.wait_group 1;")
#define CP_WAIT0()  asm volatile("cp.async.wait_group 0;")

__device__ __forceinline__ void ldm_x4(uint32_t& d0, uint32_t& d1, uint32_t& d2,
                                       uint32_t& d3, uint32_t addr)
{
    asm volatile("ldmatrix.sync.aligned.m8n8.x4.shared.b16 {%0,%1,%2,%3}, [%4];"
                 : "=r"(d0), "=r"(d1), "=r"(d2), "=r"(d3) : "r"(addr));
}

__device__ __forceinline__ void mma16816(float c[4], uint32_t a0, uint32_t a1,
                                         uint32_t a2, uint32_t a3,
                                         uint32_t b0, uint32_t b1)
{
    asm volatile(
        "mma.sync.aligned.m16n8k16.row.col.f32.bf16.bf16.f32 "
        "{%0,%1,%2,%3}, {%4,%5,%6,%7}, {%8,%9}, {%0,%1,%2,%3};"
        : "+f"(c[0]), "+f"(c[1]), "+f"(c[2]), "+f"(c[3])
        : "r"(a0), "r"(a1), "r"(a2), "r"(a3), "r"(b0), "r"(b1));
}

__device__ __forceinline__ ush bfr(float f) {
    return __bfloat16_as_ushort(__float2bfloat16_rn(f));
}
// pack 2 floats -> bf16x2 in ONE cvt (lo = first arg)
__device__ __forceinline__ uint32_t pack2bf(float lo, float hi) {
    uint32_t r;
    asm("cvt.rn.bf16x2.f32 %0, %1, %2;" : "=r"(r) : "f"(hi), "f"(lo));
    return r;
}
__device__ __forceinline__ float ex2(float x) {
    float r;
    asm("ex2.approx.f32 %0, %1;" : "=f"(r) : "f"(x));
    return r;
}

__device__ __forceinline__ float gelu_exact(float v)
{
    return 0.5f * v * (1.0f + erff(v * 0.70710678118654752f));
}

// ---------------------------------------------------------------------------
// merged weight conversion: 4 fp32 weight tensors -> one concatenated bf16 plane
// ---------------------------------------------------------------------------
__global__ __launch_bounds__(256) void cvt4_kernel(
    const float* __restrict__ s0, const float* __restrict__ s1,
    const float* __restrict__ s2, const float* __restrict__ s3,
    ush* __restrict__ h)
{
    int base = (blockIdx.x * blockDim.x + threadIdx.x) * 4;
    if (base >= WTOT) return;
    const float* src;
    int off;
    if (base < WO)      { src = s0; off = base; }
    else if (base < W1) { src = s1; off = base - WO; }
    else if (base < W2) { src = s2; off = base - W1; }
    else                { src = s3; off = base - W2; }
    float4 v = *(const float4*)(src + off);
    uint2 o;
    o.x = pack2bf(v.x, v.y);
    o.y = pack2bf(v.z, v.w);
    *(uint2*)(h + base) = o;
}

// ---------------------------------------------------------------------------
// window partition with smem transpose: x (2,256,100,100) -> bf16 (20000,256)
// ---------------------------------------------------------------------------
__global__ __launch_bounds__(256) void gather_kernel(const float* __restrict__ x,
                                                     ush* __restrict__ xh)
{
    __shared__ float sm[32][33];
    const int w = threadIdx.x >> 5, lane = threadIdx.x & 31;
    const int tk0 = blockIdx.x * 32;       // 625 blocks
    const int ch0 = blockIdx.y * 32;       // 8 blocks

    {
        int tk = tk0 + lane;
        int bb = tk / 10000, rr = tk % 10000;
        int win = rr / 625, t = rr % 625;
        int hh = (win >> 2) * 25 + t / 25;
        int ww = (win & 3) * 25 + t % 25;
        int base = bb * 2560000 + hh * 100 + ww;
#pragma unroll
        for (int i = 0; i < 4; i++) {
            int ch = ch0 + w * 4 + i;
            sm[w * 4 + i][lane] = x[base + ch * 10000];
        }
    }
    __syncthreads();

#pragma unroll
    for (int i = 0; i < 4; i++) {
        int tl = w * 4 + i;
        xh[(size_t)(tk0 + tl) * DCH + ch0 + lane] = bfr(sm[lane][tl]);
    }
}

// ---------------------------------------------------------------------------
// plain-bf16 tensor-core GEMM: cp.async double-buffer + ldmatrix.
// C[M,N] = A[M,K] @ B[N,K]^T
// mode 0: C fp32   mode 1: gelu(C+bias) -> bf16   mode 2: scatter+residual
// mode 3: C -> bf16
// ---------------------------------------------------------------------------
#define SB   80           // smem row stride bytes (64 data + 16 pad)
#define PLB  10240        // one matrix tile: 128 rows * SB
#define BUFB 20480        // A + B
#define GEMM_SMEM (2 * BUFB)

__global__ __launch_bounds__(256) void gemm_tc(
    const ush* __restrict__ Ah, const ush* __restrict__ Bh,
    int M, int N, int K, int mode,
    const float* __restrict__ bias, const float* __restrict__ xres,
    float* __restrict__ outF, ush* __restrict__ oh)
{
    extern __shared__ char smem[];
    const uint32_t sbb = smem_u32(smem);
    const int tid = threadIdx.x;
    const int wid = tid >> 5, lane = tid & 31;
    const int g = lane >> 2, t = lane & 3;
    const int wm = (wid & 3) * 32;
    const int wn = (wid >> 2) * 64;
    const int row0 = blockIdx.y * 128, coln0 = blockIdx.x * 128;

    float acc[2][8][4];
#pragma unroll
    for (int i = 0; i < 2; i++)
#pragma unroll
        for (int j = 0; j < 8; j++)
#pragma unroll
            for (int q = 0; q < 4; q++) acc[i][j][q] = 0.f;

    const int nst = K >> 5;

    const int lr0 = tid >> 2, lc0 = tid & 3;
    const int lr1 = 64 + (tid >> 2);
    int ga0 = row0 + lr0; if (ga0 > M - 1) ga0 = M - 1;
    int ga1 = row0 + lr1; if (ga1 > M - 1) ga1 = M - 1;

#define ISSUE(s) do {                                                          \
    int _b = (s) & 1;                                                          \
    int _k0 = (s) << 5;                                                        \
    uint32_t _d0 = sbb + _b * BUFB + lr0 * SB + lc0 * 16;                      \
    CP_ASYNC16(_d0,       Ah + (size_t)ga0 * K + _k0 + lc0 * 8);               \
    CP_ASYNC16(_d0 + PLB, Bh + (size_t)(coln0 + lr0) * K + _k0 + lc0 * 8);     \
    uint32_t _d1 = sbb + _b * BUFB + lr1 * SB + lc0 * 16;                      \
    CP_ASYNC16(_d1,       Ah + (size_t)ga1 * K + _k0 + lc0 * 8);               \
    CP_ASYNC16(_d1 + PLB, Bh + (size_t)(coln0 + lr1) * K + _k0 + lc0 * 8);     \
} while (0)

    ISSUE(0); CP_COMMIT();

    const int arow = (lane & 7) + ((lane >> 3) & 1) * 8;
    const int kh = (lane >> 4) * 16;

    for (int s = 0; s < nst; s++) {
        if (s + 1 < nst) { ISSUE(s + 1); CP_COMMIT(); CP_WAIT1(); }
        else             { CP_WAIT0(); }
        __syncthreads();

        const uint32_t pa = sbb + (s & 1) * BUFB;
        const uint32_t pb = pa + PLB;
#pragma unroll
        for (int ks = 0; ks < 2; ks++) {
            const uint32_t cb = ks * 32 + kh;
            uint32_t ah[2][4];
#pragma unroll
            for (int mt = 0; mt < 2; mt++) {
                uint32_t ad = pa + (wm + mt * 16 + arow) * SB + cb;
                ldm_x4(ah[mt][0], ah[mt][1], ah[mt][2], ah[mt][3], ad);
            }
            uint32_t bh[8][2];
#pragma unroll
            for (int p = 0; p < 4; p++) {
                uint32_t bd = pb + (wn + p * 16 + arow) * SB + cb;
                ldm_x4(bh[2 * p][0], bh[2 * p + 1][0], bh[2 * p][1], bh[2 * p + 1][1], bd);
            }
#pragma unroll
            for (int mt = 0; mt < 2; mt++)
#pragma unroll
                for (int nt = 0; nt < 8; nt++)
                    mma16816(acc[mt][nt], ah[mt][0], ah[mt][1], ah[mt][2], ah[mt][3],
                             bh[nt][0], bh[nt][1]);
        }
        __syncthreads();
    }
#undef ISSUE

    // ---- epilogue ----
#pragma unroll
    for (int mt = 0; mt < 2; mt++) {
#pragma unroll
        for (int half = 0; half < 2; half++) {
            int r = row0 + wm + mt * 16 + g + half * 8;
            if (r >= M) continue;
#pragma unroll
            for (int nt = 0; nt < 8; nt++) {
                int col = coln0 + wn + nt * 8 + 2 * t;
                float v0 = acc[mt][nt][half * 2 + 0];
                float v1 = acc[mt][nt][half * 2 + 1];
                if (mode == 0) {
                    *(float2*)(outF + (size_t)r * N + col) = make_float2(v0, v1);
                } else if (mode == 3) {
                    *(uint32_t*)(oh + (size_t)r * N + col) = pack2bf(v0, v1);
                } else if (mode == 1) {
                    *(uint32_t*)(oh + (size_t)r * N + col) =
                        pack2bf(gelu_exact(v0 + bias[col]),
                                gelu_exact(v1 + bias[col + 1]));
                } else {
                    int bb = r / 10000, rr = r % 10000;
                    int win = rr / 625, tt = rr % 625;
                    int hh2 = (win >> 2) * 25 + tt / 25;
                    int ww = (win & 3) * 25 + tt % 25;
                    int obase = bb * 2560000 + hh2 * 100 + ww;
                    int oi0 = obase + col * 10000;
                    int oi1 = obase + (col + 1) * 10000;
                    outF[oi0] = xres[oi0] + v0 + bias[col];
                    outF[oi1] = xres[oi1] + v1 + bias[col + 1];
                }
            }
        }
    }
}

// ---------------------------------------------------------------------------
// tensor-core windowed attention, plain bf16, ldmatrix, lean softmax.
// grid = (head 8, win 32, qtile 5); CTA 256 thr; warp owns 16 q-rows.
// BL pre-scaled by log2e; p = ex2(fma(s, scale*log2e, bl)).
// sub(j) = j + 24*((j*1311)>>15)  (exact integer j/25 fold for j<640).
// Last k-tile handled by a templated step with multiply-masking.
// ---------------------------------------------------------------------------
#define SROW 20
#define SBK  80     // K-tile row stride bytes
#define VTS  36
#define SBV  144    // V-tile row stride bytes
#define SL2  0.25503487f   // (1/sqrt(32)) * log2(e)

template<bool LAST>
__device__ __forceinline__ void attn_step(
    int kb, const ush* __restrict__ qh_, int tok0, int head,
    int tid, int t, int arow, int kh,
    uint32_t Kb, uint32_t Vb, uint32_t* KHI, uint32_t* VTH,
    const float* BL, int add0, int add1,
    const uint32_t qh[2][4], float& l0, float& l1, float oacc[4][4])
{
    __syncthreads();
    // ---- K tile: 64 rows x 4 chunks of 16B ----
    {
        int r = tid >> 2, c = tid & 3;
        int jg = kb * 64 + r;
        uint4 v = make_uint4(0, 0, 0, 0);
        if (!LAST || jg < 625)
            v = *(const uint4*)(qh_ + (size_t)(tok0 + jg) * QKVN + 256
                                + head * 32 + c * 8);
        *(uint4*)(KHI + r * SROW + c * 4) = v;
    }
    // ---- V tile transposed: 32 dims x 64 keys (pairs) ----
#pragma unroll
    for (int it = 0; it < 4; it++) {
        int idx = it * 256 + tid;
        int d = idx & 31, jp = idx >> 5;
        int j0 = kb * 64 + jp * 2;
        size_t base0 = (size_t)(tok0 + j0) * QKVN + 512 + head * 32 + d;
        uint32_t h0 = 0, h1 = 0;
        if (!LAST || j0 < 625)     h0 = qh_[base0];
        if (!LAST || j0 + 1 < 625) h1 = qh_[base0 + QKVN];
        VTH[d * VTS + jp] = h0 | (h1 << 16);
    }
    __syncthreads();

    // ---- S = Q K^T ----
    float sacc[8][4];
#pragma unroll
    for (int i = 0; i < 8; i++)
#pragma unroll
        for (int j = 0; j < 4; j++) sacc[i][j] = 0.f;

#pragma unroll
    for (int p = 0; p < 4; p++) {
        uint32_t base = Kb + (p * 16 + arow) * SBK + kh;
        uint32_t kA0, kA1, kA2, kA3, kB0, kB1, kB2, kB3;
        ldm_x4(kA0, kA1, kA2, kA3, base);
        ldm_x4(kB0, kB1, kB2, kB3, base + 32);
        mma16816(sacc[2 * p],     qh[0][0], qh[0][1], qh[0][2], qh[0][3], kA0, kA2);
        mma16816(sacc[2 * p + 1], qh[0][0], qh[0][1], qh[0][2], qh[0][3], kA1, kA3);
        mma16816(sacc[2 * p],     qh[1][0], qh[1][1], qh[1][2], qh[1][3], kB0, kB2);
        mma16816(sacc[2 * p + 1], qh[1][0], qh[1][1], qh[1][2], qh[1][3], kB1, kB3);
    }

    // ---- bias + ex2 + pack P ----
    const int kbase = kb * 64;
    uint32_t pha[8][2];
#pragma unroll
    for (int nt = 0; nt < 8; nt++) {
        int jl0 = nt * 8 + 2 * t;
        int jg0 = kbase + jl0;
        int jg1 = jg0 + 1;
        int jc0 = LAST ? (jg0 < 624 ? jg0 : 624) : jg0;
        int jc1 = LAST ? (jg1 < 624 ? jg1 : 624) : jg1;
        int sub0 = jc0 + 24 * ((jc0 * 1311) >> 15);
        int sub1 = jc1 + 24 * ((jc1 * 1311) >> 15);
        float b00 = BL[add0 - sub0], b01 = BL[add0 - sub1];
        float b10 = BL[add1 - sub0], b11 = BL[add1 - sub1];
        float p0 = ex2(fmaf(sacc[nt][0], SL2, b00));
        float p1 = ex2(fmaf(sacc[nt][1], SL2, b01));
        float p2 = ex2(fmaf(sacc[nt][2], SL2, b10));
        float p3 = ex2(fmaf(sacc[nt][3], SL2, b11));
        if (LAST) {
            if (jg0 >= 625) { p0 = 0.f; p2 = 0.f; }
            if (jg1 >= 625) { p1 = 0.f; p3 = 0.f; }
        }
        l0 += p0 + p1;
        l1 += p2 + p3;
        pha[nt][0] = pack2bf(p0, p1);
        pha[nt][1] = pack2bf(p2, p3);
    }

    // ---- O += P V ----
#pragma unroll
    for (int p2 = 0; p2 < 2; p2++) {
        uint32_t vbase = Vb + (p2 * 16 + arow) * SBV + kh;
#pragma unroll
        for (int kc2 = 0; kc2 < 4; kc2++) {
            uint32_t v0, v1, v2, v3;
            ldm_x4(v0, v1, v2, v3, vbase + kc2 * 32);
            mma16816(oacc[2 * p2], pha[2 * kc2][0], pha[2 * kc2][1],
                     pha[2 * kc2 + 1][0], pha[2 * kc2 + 1][1], v0, v2);
            mma16816(oacc[2 * p2 + 1], pha[2 * kc2][0], pha[2 * kc2][1],
                     pha[2 * kc2 + 1][0], pha[2 * kc2 + 1][1], v1, v3);
        }
    }
}

__global__ __launch_bounds__(256) void attn_tc(const ush* __restrict__ qh_,
                                               const float* __restrict__ table,
                                               ush* __restrict__ oh)
{
    __shared__ uint32_t QHI[128 * SROW];
    __shared__ uint32_t KHI[64 * SROW];
    __shared__ uint32_t VTH[32 * VTS];
    __shared__ float    BL[2401];

    const int head = blockIdx.x;
    const int win  = blockIdx.y;
    const int qt   = blockIdx.z;
    const int tid  = threadIdx.x;
    const int w = tid >> 5, lane = tid & 31;
    const int g = lane >> 2, t = tid & 3;
    const int tok0 = win * 625;
    const int qbase = qt * 128;
    const int arow = (lane & 7) + ((lane >> 3) & 1) * 8;
    const int kh = (lane >> 4) * 16;
    const uint32_t Kb = smem_u32(KHI);
    const uint32_t Vb = smem_u32(VTH);

    // bias pre-scaled by log2(e)
    for (int i = tid; i < 2401; i += 256)
        BL[i] = table[i * 8 + head] * 1.4426950408889634f;

    // Q tile: 128 rows x 4 chunks of 16B
#pragma unroll
    for (int it = 0; it < 2; it++) {
        int idx = it * 256 + tid;
        int r = idx >> 2, c = idx & 3;
        int qi = qbase + r;
        uint4 v = make_uint4(0, 0, 0, 0);
        if (qi < 625)
            v = *(const uint4*)(qh_ + (size_t)(tok0 + qi) * QKVN + head * 32 + c * 8);
        *(uint4*)(QHI + r * SROW + c * 4) = v;
    }
    __syncthreads();

    uint32_t qh[2][4];
    {
        int r0 = w * 16 + g;
#pragma unroll
        for (int kc = 0; kc < 2; kc++) {
            qh[kc][0] = QHI[r0 * SROW + kc * 8 + t];
            qh[kc][1] = QHI[(r0 + 8) * SROW + kc * 8 + t];
            qh[kc][2] = QHI[r0 * SROW + kc * 8 + t + 4];
            qh[kc][3] = QHI[(r0 + 8) * SROW + kc * 8 + t + 4];
        }
    }

    const int qi0 = qbase + w * 16 + g;
    const int qi1 = qi0 + 8;
    const int cq0 = qi0 < 625 ? qi0 : 624;
    const int cq1 = qi1 < 625 ? qi1 : 624;
    const int add0 = (cq0 / 25 + 24) * 49 + (cq0 % 25) + 24;
    const int add1 = (cq1 / 25 + 24) * 49 + (cq1 % 25) + 24;

    float l0 = 0.f, l1 = 0.f;
    float oacc[4][4];
#pragma unroll
    for (int i = 0; i < 4; i++)
#pragma unroll
        for (int j = 0; j < 4; j++) oacc[i][j] = 0.f;

#pragma unroll 1
    for (int kb = 0; kb < 9; kb++)
        attn_step<false>(kb, qh_, tok0, head, tid, t, arow, kh,
                         Kb, Vb, KHI, VTH, BL, add0, add1, qh, l0, l1, oacc);
    attn_step<true>(9, qh_, tok0, head, tid, t, arow, kh,
                    Kb, Vb, KHI, VTH, BL, add0, add1, qh, l0, l1, oacc);

    l0 += __shfl_xor_sync(0xffffffffu, l0, 1);
    l0 += __shfl_xor_sync(0xffffffffu, l0, 2);
    l1 += __shfl_xor_sync(0xffffffffu, l1, 1);
    l1 += __shfl_xor_sync(0xffffffffu, l1, 2);
    float inv0 = 1.f / l0, inv1 = 1.f / l1;

    if (qi0 < 625) {
        size_t o = (size_t)(tok0 + qi0) * DCH + head * 32;
#pragma unroll
        for (int nt2 = 0; nt2 < 4; nt2++) {
            int d = nt2 * 8 + 2 * t;
            *(uint32_t*)(oh + o + d) = pack2bf(oacc[nt2][0] * inv0,
                                               oacc[nt2][1] * inv0);
        }
    }
    if (qi1 < 625) {
        size_t o = (size_t)(tok0 + qi1) * DCH + head * 32;
#pragma unroll
        for (int nt2 = 0; nt2 < 4; nt2++) {
            int d = nt2 * 8 + 2 * t;
            *(uint32_t*)(oh + o + d) = pack2bf(oacc[nt2][2] * inv1,
                                               oacc[nt2][3] * inv1);
        }
    }
}

// ---------------------------------------------------------------------------
// LayerNorm over d=256: one warp per token; output bf16
// ---------------------------------------------------------------------------
__global__ __launch_bounds__(256) void ln_kernel(const float* __restrict__ in,
                                                 ush* __restrict__ oh,
                                                 const float* __restrict__ g,
                                                 const float* __restrict__ b)
{
    int wid = threadIdx.x >> 5, lane = threadIdx.x & 31;
    int t = blockIdx.x * 8 + wid;
    const float4* p = (const float4*)(in + (size_t)t * DCH);
    float4 v0 = p[lane];
    float4 v1 = p[lane + 32];
    float s  = v0.x + v0.y + v0.z + v0.w + v1.x + v1.y + v1.z + v1.w;
    float ss = v0.x * v0.x + v0.y * v0.y + v0.z * v0.z + v0.w * v0.w
             + v1.x * v1.x + v1.y * v1.y + v1.z * v1.z + v1.w * v1.w;
#pragma unroll
    for (int off = 16; off > 0; off >>= 1) {
        s  += __shfl_xor_sync(0xffffffffu, s, off);
        ss += __shfl_xor_sync(0xffffffffu, ss, off);
    }
    float mean = s * (1.f / 256.f);
    float var  = ss * (1.f / 256.f) - mean * mean;
    float rstd = rsqrtf(var + 1e-5f);

    const float4* g4 = (const float4*)g;
    const float4* b4 = (const float4*)b;
    float4 ga = g4[lane], gb = g4[lane + 32];
    float4 ba = b4[lane], bb = b4[lane + 32];

    uint2 o0, o1;
    o0.x = pack2bf((v0.x - mean) * rstd * ga.x + ba.x,
                   (v0.y - mean) * rstd * ga.y + ba.y);
    o0.y = pack2bf((v0.z - mean) * rstd * ga.z + ba.z,
                   (v0.w - mean) * rstd * ga.w + ba.w);
    o1.x = pack2bf((v1.x - mean) * rstd * gb.x + bb.x,
                   (v1.y - mean) * rstd * gb.y + bb.y);
    o1.y = pack2bf((v1.z - mean) * rstd * gb.z + bb.z,
                   (v1.w - mean) * rstd * gb.w + bb.w);

    size_t o = (size_t)t * DCH;
    *(uint2*)(oh + o + lane * 4)       = o0;
    *(uint2*)(oh + o + 128 + lane * 4) = o1;
}

// ---------------------------------------------------------------------------
extern "C" void kernel_launch(void* const* d_in, const int* in_sizes, int n_in,
                              void* d_out, int out_size)
{
    const float* x      = (const float*)d_in[0];
    const float* w_qkv  = (const float*)d_in[1];
    const float* w_out  = (const float*)d_in[2];
    const float* table  = (const float*)d_in[3];
    const float* gamma2 = (const float*)d_in[4];
    const float* beta2  = (const float*)d_in[5];
    const float* w1     = (const float*)d_in[6];
    const float* b1     = (const float*)d_in[7];
    const float* w2     = (const float*)d_in[8];
    const float* b2     = (const float*)d_in[9];
    float* out = (float*)d_out;

    ush *xw, *qkv, *att, *ln, *hid, *wv;
    float *proj;
    cudaGetSymbolAddress((void**)&xw,  g_xw);
    cudaGetSymbolAddress((void**)&qkv, g_qkv);
    cudaGetSymbolAddress((void**)&att, g_att);
    cudaGetSymbolAddress((void**)&proj, g_proj);
    cudaGetSymbolAddress((void**)&ln,  g_ln);
    cudaGetSymbolAddress((void**)&hid, g_hid);
    cudaGetSymbolAddress((void**)&wv,  g_w);

    cudaFuncSetAttribute(gemm_tc, cudaFuncAttributeMaxDynamicSharedMemorySize, GEMM_SMEM);

    // 0) weights -> bf16 plane (one launch)
    cvt4_kernel<<<WTOT / 4 / 256, 256>>>(w_qkv, w_out, w1, w2, wv);

    // 1) window partition (transposed, coalesced)
    gather_kernel<<<dim3(625, 8), 256>>>(x, xw);
    // 2) QKV projection -> bf16
    gemm_tc<<<dim3(6, 157), 256, GEMM_SMEM>>>(xw, wv + WQ,
        TOK, QKVN, DCH, 3, nullptr, nullptr, nullptr, qkv);
    // 3) tensor-core windowed attention -> bf16
    attn_tc<<<dim3(8, 32, 5), 256>>>(qkv, table, att);
    // 4) output projection -> fp32
    gemm_tc<<<dim3(2, 157), 256, GEMM_SMEM>>>(att, wv + WO,
        TOK, DCH, DCH, 0, nullptr, nullptr, proj, nullptr);
    // 5) layernorm -> bf16
    ln_kernel<<<2500, 256>>>(proj, ln, gamma2, beta2);
    // 6) MLP fc1 + exact GELU -> bf16
    gemm_tc<<<dim3(4, 157), 256, GEMM_SMEM>>>(ln, wv + W1,
        TOK, HID, DCH, 1, b1, nullptr, nullptr, hid);
    // 7) MLP fc2 + bias + un-partition + residual -> d_out
    gemm_tc<<<dim3(2, 157), 256, GEMM_SMEM>>>(hid, wv + W2,
        TOK, DCH, HID, 2, b2, x, out, nullptr);
}

// round 9
// speedup vs baseline: 2.3439x; 1.0514x over previous
#include <cuda_runtime.h>
#include <cuda_bf16.h>
#include <cstdint>
#include <math.h>

#define TOK 20000      // 2 * 16 windows * 625 tokens
#define DCH 256
#define QKVN 768
#define HID 512

typedef unsigned short ush;

// ---- scratch: plain bf16 planes ----
__device__ ush g_xw  [TOK * DCH];
__device__ ush g_qkv [TOK * QKVN];
__device__ ush g_att [TOK * DCH];
__device__ float g_proj[TOK * DCH];
__device__ ush g_ln  [TOK * DCH];
__device__ ush g_hid [TOK * HID];
// all four weight matrices concatenated: wqkv | wout | w1 | w2
#define WQ 0
#define WO 196608
#define W1 262144
#define W2 393216
#define WTOT 524288
__device__ ush g_w[WTOT];

// ---------------------------------------------------------------------------
// helpers
// ---------------------------------------------------------------------------
__device__ __forceinline__ uint32_t smem_u32(const void* p) {
    uint32_t a;
    asm("{ .reg .u64 t; cvta.to.shared.u64 t, %1; cvt.u32.u64 %0, t; }" : "=r"(a) : "l"(p));
    return a;
}
#define CP_ASYNC16(dst, src) \
    asm volatile("cp.async.cg.shared.global [%0], [%1], 16;" :: "r"(dst), "l"(src))
#define CP_COMMIT() asm volatile("cp.async.commit_group;")
#define CP_WAIT2()  asm volatile("cp.async.wait_group 2;")
#define CP_WAIT1()  asm volatile("cp.async.wait_group 1;")
#define CP_WAIT0()  asm volatile("cp.async.wait_group 0;")

__device__ __forceinline__ void ldm_x4(uint32_t& d0, uint32_t& d1, uint32_t& d2,
                                       uint32_t& d3, uint32_t addr)
{
    asm volatile("ldmatrix.sync.aligned.m8n8.x4.shared.b16 {%0,%1,%2,%3}, [%4];"
                 : "=r"(d0), "=r"(d1), "=r"(d2), "=r"(d3) : "r"(addr));
}
__device__ __forceinline__ void ldm_x4t(uint32_t& d0, uint32_t& d1, uint32_t& d2,
                                        uint32_t& d3, uint32_t addr)
{
    asm volatile("ldmatrix.sync.aligned.m8n8.x4.trans.shared.b16 {%0,%1,%2,%3}, [%4];"
                 : "=r"(d0), "=r"(d1), "=r"(d2), "=r"(d3) : "r"(addr));
}

__device__ __forceinline__ void mma16816(float c[4], uint32_t a0, uint32_t a1,
                                         uint32_t a2, uint32_t a3,
                                         uint32_t b0, uint32_t b1)
{
    asm volatile(
        "mma.sync.aligned.m16n8k16.row.col.f32.bf16.bf16.f32 "
        "{%0,%1,%2,%3}, {%4,%5,%6,%7}, {%8,%9}, {%0,%1,%2,%3};"
        : "+f"(c[0]), "+f"(c[1]), "+f"(c[2]), "+f"(c[3])
        : "r"(a0), "r"(a1), "r"(a2), "r"(a3), "r"(b0), "r"(b1));
}

__device__ __forceinline__ ush bfr(float f) {
    return __bfloat16_as_ushort(__float2bfloat16_rn(f));
}
// pack 2 floats -> bf16x2 in ONE cvt (lo = first arg)
__device__ __forceinline__ uint32_t pack2bf(float lo, float hi) {
    uint32_t r;
    asm("cvt.rn.bf16x2.f32 %0, %1, %2;" : "=r"(r) : "f"(hi), "f"(lo));
    return r;
}
__device__ __forceinline__ float ex2(float x) {
    float r;
    asm("ex2.approx.f32 %0, %1;" : "=f"(r) : "f"(x));
    return r;
}

__device__ __forceinline__ float gelu_exact(float v)
{
    return 0.5f * v * (1.0f + erff(v * 0.70710678118654752f));
}

// ---------------------------------------------------------------------------
// merged weight conversion
// ---------------------------------------------------------------------------
__global__ __launch_bounds__(256) void cvt4_kernel(
    const float* __restrict__ s0, const float* __restrict__ s1,
    const float* __restrict__ s2, const float* __restrict__ s3,
    ush* __restrict__ h)
{
    int base = (blockIdx.x * blockDim.x + threadIdx.x) * 4;
    if (base >= WTOT) return;
    const float* src;
    int off;
    if (base < WO)      { src = s0; off = base; }
    else if (base < W1) { src = s1; off = base - WO; }
    else if (base < W2) { src = s2; off = base - W1; }
    else                { src = s3; off = base - W2; }
    float4 v = *(const float4*)(src + off);
    uint2 o;
    o.x = pack2bf(v.x, v.y);
    o.y = pack2bf(v.z, v.w);
    *(uint2*)(h + base) = o;
}

// ---------------------------------------------------------------------------
// window partition with smem transpose
// ---------------------------------------------------------------------------
__global__ __launch_bounds__(256) void gather_kernel(const float* __restrict__ x,
                                                     ush* __restrict__ xh)
{
    __shared__ float sm[32][33];
    const int w = threadIdx.x >> 5, lane = threadIdx.x & 31;
    const int tk0 = blockIdx.x * 32;
    const int ch0 = blockIdx.y * 32;

    {
        int tk = tk0 + lane;
        int bb = tk / 10000, rr = tk % 10000;
        int win = rr / 625, t = rr % 625;
        int hh = (win >> 2) * 25 + t / 25;
        int ww = (win & 3) * 25 + t % 25;
        int base = bb * 2560000 + hh * 100 + ww;
#pragma unroll
        for (int i = 0; i < 4; i++) {
            int ch = ch0 + w * 4 + i;
            sm[w * 4 + i][lane] = x[base + ch * 10000];
        }
    }
    __syncthreads();

#pragma unroll
    for (int i = 0; i < 4; i++) {
        int tl = w * 4 + i;
        xh[(size_t)(tk0 + tl) * DCH + ch0 + lane] = bfr(sm[lane][tl]);
    }
}

// ---------------------------------------------------------------------------
// plain-bf16 tensor-core GEMM: 4-stage cp.async pipeline + ldmatrix.
// C[M,N] = A[M,K] @ B[N,K]^T
// mode 0: C fp32   mode 1: gelu(C+bias) -> bf16   mode 2: scatter+residual
// mode 3: C -> bf16
// ---------------------------------------------------------------------------
#define SB   80           // smem row stride bytes (64 data + 16 pad)
#define PLB  10240        // one matrix tile: 128 rows * SB
#define BUFB 20480        // A + B
#define NSTG 4
#define GEMM_SMEM (NSTG * BUFB)

__global__ __launch_bounds__(256) void gemm_tc(
    const ush* __restrict__ Ah, const ush* __restrict__ Bh,
    int M, int N, int K, int mode,
    const float* __restrict__ bias, const float* __restrict__ xres,
    float* __restrict__ outF, ush* __restrict__ oh)
{
    extern __shared__ char smem[];
    const uint32_t sbb = smem_u32(smem);
    const int tid = threadIdx.x;
    const int wid = tid >> 5, lane = tid & 31;
    const int g = lane >> 2, t = lane & 3;
    const int wm = (wid & 3) * 32;
    const int wn = (wid >> 2) * 64;
    const int row0 = blockIdx.y * 128, coln0 = blockIdx.x * 128;

    float acc[2][8][4];
#pragma unroll
    for (int i = 0; i < 2; i++)
#pragma unroll
        for (int j = 0; j < 8; j++)
#pragma unroll
            for (int q = 0; q < 4; q++) acc[i][j][q] = 0.f;

    const int nst = K >> 5;

    const int lr0 = tid >> 2, lc0 = tid & 3;
    const int lr1 = 64 + (tid >> 2);
    int ga0 = row0 + lr0; if (ga0 > M - 1) ga0 = M - 1;
    int ga1 = row0 + lr1; if (ga1 > M - 1) ga1 = M - 1;

#define ISSUE(s) do {                                                          \
    int _b = (s) & (NSTG - 1);                                                 \
    int _k0 = (s) << 5;                                                        \
    uint32_t _d0 = sbb + _b * BUFB + lr0 * SB + lc0 * 16;                      \
    CP_ASYNC16(_d0,       Ah + (size_t)ga0 * K + _k0 + lc0 * 8);               \
    CP_ASYNC16(_d0 + PLB, Bh + (size_t)(coln0 + lr0) * K + _k0 + lc0 * 8);     \
    uint32_t _d1 = sbb + _b * BUFB + lr1 * SB + lc0 * 16;                      \
    CP_ASYNC16(_d1,       Ah + (size_t)ga1 * K + _k0 + lc0 * 8);               \
    CP_ASYNC16(_d1 + PLB, Bh + (size_t)(coln0 + lr1) * K + _k0 + lc0 * 8);     \
} while (0)

    ISSUE(0); CP_COMMIT();
    ISSUE(1); CP_COMMIT();
    ISSUE(2); CP_COMMIT();

    const int arow = (lane & 7) + ((lane >> 3) & 1) * 8;
    const int kh = (lane >> 4) * 16;

    for (int s = 0; s < nst; s++) {
        // wait until stage s's group has landed
        if (s + 3 <= nst)      CP_WAIT2();
        else if (s + 2 == nst) CP_WAIT1();
        else                   CP_WAIT0();
        __syncthreads();          // data visible + stage s-1 buffer free
        if (s + 3 < nst) { ISSUE(s + 3); CP_COMMIT(); }

        const uint32_t pa = sbb + (s & (NSTG - 1)) * BUFB;
        const uint32_t pb = pa + PLB;
#pragma unroll
        for (int ks = 0; ks < 2; ks++) {
            const uint32_t cb = ks * 32 + kh;
            uint32_t ah[2][4];
#pragma unroll
            for (int mt = 0; mt < 2; mt++) {
                uint32_t ad = pa + (wm + mt * 16 + arow) * SB + cb;
                ldm_x4(ah[mt][0], ah[mt][1], ah[mt][2], ah[mt][3], ad);
            }
            uint32_t bh[8][2];
#pragma unroll
            for (int p = 0; p < 4; p++) {
                uint32_t bd = pb + (wn + p * 16 + arow) * SB + cb;
                ldm_x4(bh[2 * p][0], bh[2 * p + 1][0], bh[2 * p][1], bh[2 * p + 1][1], bd);
            }
#pragma unroll
            for (int mt = 0; mt < 2; mt++)
#pragma unroll
                for (int nt = 0; nt < 8; nt++)
                    mma16816(acc[mt][nt], ah[mt][0], ah[mt][1], ah[mt][2], ah[mt][3],
                             bh[nt][0], bh[nt][1]);
        }
    }
#undef ISSUE

    // ---- epilogue ----
#pragma unroll
    for (int mt = 0; mt < 2; mt++) {
#pragma unroll
        for (int half = 0; half < 2; half++) {
            int r = row0 + wm + mt * 16 + g + half * 8;
            if (r >= M) continue;
#pragma unroll
            for (int nt = 0; nt < 8; nt++) {
                int col = coln0 + wn + nt * 8 + 2 * t;
                float v0 = acc[mt][nt][half * 2 + 0];
                float v1 = acc[mt][nt][half * 2 + 1];
                if (mode == 0) {
                    *(float2*)(outF + (size_t)r * N + col) = make_float2(v0, v1);
                } else if (mode == 3) {
                    *(uint32_t*)(oh + (size_t)r * N + col) = pack2bf(v0, v1);
                } else if (mode == 1) {
                    *(uint32_t*)(oh + (size_t)r * N + col) =
                        pack2bf(gelu_exact(v0 + bias[col]),
                                gelu_exact(v1 + bias[col + 1]));
                } else {
                    int bb = r / 10000, rr = r % 10000;
                    int win = rr / 625, tt = rr % 625;
                    int hh2 = (win >> 2) * 25 + tt / 25;
                    int ww = (win & 3) * 25 + tt % 25;
                    int obase = bb * 2560000 + hh2 * 100 + ww;
                    int oi0 = obase + col * 10000;
                    int oi1 = obase + (col + 1) * 10000;
                    outF[oi0] = xres[oi0] + v0 + bias[col];
                    outF[oi1] = xres[oi1] + v1 + bias[col + 1];
                }
            }
        }
    }
}

// ---------------------------------------------------------------------------
// tensor-core windowed attention: plain bf16, ldmatrix (V via .trans),
// lean softmax. grid = (head 8, win 32, qtile 5); CTA 256 thr.
// ---------------------------------------------------------------------------
#define SROW 20
#define SBK  80     // row stride bytes for K/V tiles
#define SL2  0.25503487f   // (1/sqrt(32)) * log2(e)

template<bool LAST>
__device__ __forceinline__ void attn_step(
    int kb, const ush* __restrict__ qh_, int tok0, int head,
    int tid, int t, int arow, int kh,
    uint32_t Kb, uint32_t Vb, uint32_t* KHI, uint32_t* VHI,
    const float* BL, int add0, int add1,
    const uint32_t qh[2][4], float& l0, float& l1, float oacc[4][4])
{
    __syncthreads();
    const int r = tid >> 2, c = tid & 3;
    const int jg = kb * 64 + r;
    // ---- K tile: 64 rows x 4 chunks of 16B ----
    {
        uint4 v = make_uint4(0, 0, 0, 0);
        if (!LAST || jg < 625)
            v = *(const uint4*)(qh_ + (size_t)(tok0 + jg) * QKVN + 256
                                + head * 32 + c * 8);
        *(uint4*)(KHI + r * SROW + c * 4) = v;
    }
    // ---- V tile: 64 rows (keys) x 32 dims, row-major (transposed at read) ----
    {
        uint4 v = make_uint4(0, 0, 0, 0);
        if (!LAST || jg < 625)
            v = *(const uint4*)(qh_ + (size_t)(tok0 + jg) * QKVN + 512
                                + head * 32 + c * 8);
        *(uint4*)(VHI + r * SROW + c * 4) = v;
    }
    __syncthreads();

    // ---- S = Q K^T ----
    float sacc[8][4];
#pragma unroll
    for (int i = 0; i < 8; i++)
#pragma unroll
        for (int j = 0; j < 4; j++) sacc[i][j] = 0.f;

#pragma unroll
    for (int p = 0; p < 4; p++) {
        uint32_t base = Kb + (p * 16 + arow) * SBK + kh;
        uint32_t kA0, kA1, kA2, kA3, kB0, kB1, kB2, kB3;
        ldm_x4(kA0, kA1, kA2, kA3, base);
        ldm_x4(kB0, kB1, kB2, kB3, base + 32);
        mma16816(sacc[2 * p],     qh[0][0], qh[0][1], qh[0][2], qh[0][3], kA0, kA2);
        mma16816(sacc[2 * p + 1], qh[0][0], qh[0][1], qh[0][2], qh[0][3], kA1, kA3);
        mma16816(sacc[2 * p],     qh[1][0], qh[1][1], qh[1][2], qh[1][3], kB0, kB2);
        mma16816(sacc[2 * p + 1], qh[1][0], qh[1][1], qh[1][2], qh[1][3], kB1, kB3);
    }

    // ---- bias + ex2 + pack P ----
    const int kbase = kb * 64;
    uint32_t pha[8][2];
#pragma unroll
    for (int nt = 0; nt < 8; nt++) {
        int jl0 = nt * 8 + 2 * t;
        int jg0 = kbase + jl0;
        int jg1 = jg0 + 1;
        int jc0 = LAST ? (jg0 < 624 ? jg0 : 624) : jg0;
        int jc1 = LAST ? (jg1 < 624 ? jg1 : 624) : jg1;
        int sub0 = jc0 + 24 * ((jc0 * 1311) >> 15);
        int sub1 = jc1 + 24 * ((jc1 * 1311) >> 15);
        float b00 = BL[add0 - sub0], b01 = BL[add0 - sub1];
        float b10 = BL[add1 - sub0], b11 = BL[add1 - sub1];
        float p0 = ex2(fmaf(sacc[nt][0], SL2, b00));
        float p1 = ex2(fmaf(sacc[nt][1], SL2, b01));
        float p2 = ex2(fmaf(sacc[nt][2], SL2, b10));
        float p3 = ex2(fmaf(sacc[nt][3], SL2, b11));
        if (LAST) {
            if (jg0 >= 625) { p0 = 0.f; p2 = 0.f; }
            if (jg1 >= 625) { p1 = 0.f; p3 = 0.f; }
        }
        l0 += p0 + p1;
        l1 += p2 + p3;
        pha[nt][0] = pack2bf(p0, p1);
        pha[nt][1] = pack2bf(p2, p3);
    }

    // ---- O += P V  (ldmatrix.trans on row-major V) ----
#pragma unroll
    for (int p2 = 0; p2 < 2; p2++) {        // dim 16-chunk
#pragma unroll
        for (int kc2 = 0; kc2 < 4; kc2++) { // key 16-chunk
            uint32_t d0, d1, d2, d3;
            ldm_x4t(d0, d1, d2, d3, Vb + (kc2 * 16 + arow) * SBK + p2 * 32 + kh);
            mma16816(oacc[2 * p2],     pha[2 * kc2][0], pha[2 * kc2][1],
                     pha[2 * kc2 + 1][0], pha[2 * kc2 + 1][1], d0, d1);
            mma16816(oacc[2 * p2 + 1], pha[2 * kc2][0], pha[2 * kc2][1],
                     pha[2 * kc2 + 1][0], pha[2 * kc2 + 1][1], d2, d3);
        }
    }
}

__global__ __launch_bounds__(256) void attn_tc(const ush* __restrict__ qh_,
                                               const float* __restrict__ table,
                                               ush* __restrict__ oh)
{
    __shared__ uint32_t QHI[128 * SROW];
    __shared__ uint32_t KHI[64 * SROW];
    __shared__ uint32_t VHI[64 * SROW];
    __shared__ float    BL[2401];

    const int head = blockIdx.x;
    const int win  = blockIdx.y;
    const int qt   = blockIdx.z;
    const int tid  = threadIdx.x;
    const int w = tid >> 5, lane = tid & 31;
    const int g = lane >> 2, t = tid & 3;
    const int tok0 = win * 625;
    const int qbase = qt * 128;
    const int arow = (lane & 7) + ((lane >> 3) & 1) * 8;
    const int kh = (lane >> 4) * 16;
    const uint32_t Kb = smem_u32(KHI);
    const uint32_t Vb = smem_u32(VHI);

    for (int i = tid; i < 2401; i += 256)
        BL[i] = table[i * 8 + head] * 1.4426950408889634f;

#pragma unroll
    for (int it = 0; it < 2; it++) {
        int idx = it * 256 + tid;
        int r = idx >> 2, c = idx & 3;
        int qi = qbase + r;
        uint4 v = make_uint4(0, 0, 0, 0);
        if (qi < 625)
            v = *(const uint4*)(qh_ + (size_t)(tok0 + qi) * QKVN + head * 32 + c * 8);
        *(uint4*)(QHI + r * SROW + c * 4) = v;
    }
    __syncthreads();

    uint32_t qh[2][4];
    {
        int r0 = w * 16 + g;
#pragma unroll
        for (int kc = 0; kc < 2; kc++) {
            qh[kc][0] = QHI[r0 * SROW + kc * 8 + t];
            qh[kc][1] = QHI[(r0 + 8) * SROW + kc * 8 + t];
            qh[kc][2] = QHI[r0 * SROW + kc * 8 + t + 4];
            qh[kc][3] = QHI[(r0 + 8) * SROW + kc * 8 + t + 4];
        }
    }

    const int qi0 = qbase + w * 16 + g;
    const int qi1 = qi0 + 8;
    const int cq0 = qi0 < 625 ? qi0 : 624;
    const int cq1 = qi1 < 625 ? qi1 : 624;
    const int add0 = (cq0 / 25 + 24) * 49 + (cq0 % 25) + 24;
    const int add1 = (cq1 / 25 + 24) * 49 + (cq1 % 25) + 24;

    float l0 = 0.f, l1 = 0.f;
    float oacc[4][4];
#pragma unroll
    for (int i = 0; i < 4; i++)
#pragma unroll
        for (int j = 0; j < 4; j++) oacc[i][j] = 0.f;

#pragma unroll 1
    for (int kb = 0; kb < 9; kb++)
        attn_step<false>(kb, qh_, tok0, head, tid, t, arow, kh,
                         Kb, Vb, KHI, VHI, BL, add0, add1, qh, l0, l1, oacc);
    attn_step<true>(9, qh_, tok0, head, tid, t, arow, kh,
                    Kb, Vb, KHI, VHI, BL, add0, add1, qh, l0, l1, oacc);

    l0 += __shfl_xor_sync(0xffffffffu, l0, 1);
    l0 += __shfl_xor_sync(0xffffffffu, l0, 2);
    l1 += __shfl_xor_sync(0xffffffffu, l1, 1);
    l1 += __shfl_xor_sync(0xffffffffu, l1, 2);
    float inv0 = 1.f / l0, inv1 = 1.f / l1;

    if (qi0 < 625) {
        size_t o = (size_t)(tok0 + qi0) * DCH + head * 32;
#pragma unroll
        for (int nt2 = 0; nt2 < 4; nt2++) {
            int d = nt2 * 8 + 2 * t;
            *(uint32_t*)(oh + o + d) = pack2bf(oacc[nt2][0] * inv0,
                                               oacc[nt2][1] * inv0);
        }
    }
    if (qi1 < 625) {
        size_t o = (size_t)(tok0 + qi1) * DCH + head * 32;
#pragma unroll
        for (int nt2 = 0; nt2 < 4; nt2++) {
            int d = nt2 * 8 + 2 * t;
            *(uint32_t*)(oh + o + d) = pack2bf(oacc[nt2][2] * inv1,
                                               oacc[nt2][3] * inv1);
        }
    }
}

// ---------------------------------------------------------------------------
// LayerNorm over d=256: one warp per token; output bf16
// ---------------------------------------------------------------------------
__global__ __launch_bounds__(256) void ln_kernel(const float* __restrict__ in,
                                                 ush* __restrict__ oh,
                                                 const float* __restrict__ g,
                                                 const float* __restrict__ b)
{
    int wid = threadIdx.x >> 5, lane = threadIdx.x & 31;
    int t = blockIdx.x * 8 + wid;
    const float4* p = (const float4*)(in + (size_t)t * DCH);
    float4 v0 = p[lane];
    float4 v1 = p[lane + 32];
    float s  = v0.x + v0.y + v0.z + v0.w + v1.x + v1.y + v1.z + v1.w;
    float ss = v0.x * v0.x + v0.y * v0.y + v0.z * v0.z + v0.w * v0.w
             + v1.x * v1.x + v1.y * v1.y + v1.z * v1.z + v1.w * v1.w;
#pragma unroll
    for (int off = 16; off > 0; off >>= 1) {
        s  += __shfl_xor_sync(0xffffffffu, s, off);
        ss += __shfl_xor_sync(0xffffffffu, ss, off);
    }
    float mean = s * (1.f / 256.f);
    float var  = ss * (1.f / 256.f) - mean * mean;
    float rstd = rsqrtf(var + 1e-5f);

    const float4* g4 = (const float4*)g;
    const float4* b4 = (const float4*)b;
    float4 ga = g4[lane], gb = g4[lane + 32];
    float4 ba = b4[lane], bb = b4[lane + 32];

    uint2 o0, o1;
    o0.x = pack2bf((v0.x - mean) * rstd * ga.x + ba.x,
                   (v0.y - mean) * rstd * ga.y + ba.y);
    o0.y = pack2bf((v0.z - mean) * rstd * ga.z + ba.z,
                   (v0.w - mean) * rstd * ga.w + ba.w);
    o1.x = pack2bf((v1.x - mean) * rstd * gb.x + bb.x,
                   (v1.y - mean) * rstd * gb.y + bb.y);
    o1.y = pack2bf((v1.z - mean) * rstd * gb.z + bb.z,
                   (v1.w - mean) * rstd * gb.w + bb.w);

    size_t o = (size_t)t * DCH;
    *(uint2*)(oh + o + lane * 4)       = o0;
    *(uint2*)(oh + o + 128 + lane * 4) = o1;
}

// ---------------------------------------------------------------------------
extern "C" void kernel_launch(void* const* d_in, const int* in_sizes, int n_in,
                              void* d_out, int out_size)
{
    const float* x      = (const float*)d_in[0];
    const float* w_qkv  = (const float*)d_in[1];
    const float* w_out  = (const float*)d_in[2];
    const float* table  = (const float*)d_in[3];
    const float* gamma2 = (const float*)d_in[4];
    const float* beta2  = (const float*)d_in[5];
    const float* w1     = (const float*)d_in[6];
    const float* b1     = (const float*)d_in[7];
    const float* w2     = (const float*)d_in[8];
    const float* b2     = (const float*)d_in[9];
    float* out = (float*)d_out;

    ush *xw, *qkv, *att, *ln, *hid, *wv;
    float *proj;
    cudaGetSymbolAddress((void**)&xw,  g_xw);
    cudaGetSymbolAddress((void**)&qkv, g_qkv);
    cudaGetSymbolAddress((void**)&att, g_att);
    cudaGetSymbolAddress((void**)&proj, g_proj);
    cudaGetSymbolAddress((void**)&ln,  g_ln);
    cudaGetSymbolAddress((void**)&hid, g_hid);
    cudaGetSymbolAddress((void**)&wv,  g_w);

    cudaFuncSetAttribute(gemm_tc, cudaFuncAttributeMaxDynamicSharedMemorySize, GEMM_SMEM);

    // 0) weights -> bf16 plane (one launch)
    cvt4_kernel<<<WTOT / 4 / 256, 256>>>(w_qkv, w_out, w1, w2, wv);

    // 1) window partition (transposed, coalesced)
    gather_kernel<<<dim3(625, 8), 256>>>(x, xw);
    // 2) QKV projection -> bf16
    gemm_tc<<<dim3(6, 157), 256, GEMM_SMEM>>>(xw, wv + WQ,
        TOK, QKVN, DCH, 3, nullptr, nullptr, nullptr, qkv);
    // 3) tensor-core windowed attention -> bf16
    attn_tc<<<dim3(8, 32, 5), 256>>>(qkv, table, att);
    // 4) output projection -> fp32
    gemm_tc<<<dim3(2, 157), 256, GEMM_SMEM>>>(att, wv + WO,
        TOK, DCH, DCH, 0, nullptr, nullptr, proj, nullptr);
    // 5) layernorm -> bf16
    ln_kernel<<<2500, 256>>>(proj, ln, gamma2, beta2);
    // 6) MLP fc1 + exact GELU -> bf16
    gemm_tc<<<dim3(4, 157), 256, GEMM_SMEM>>>(ln, wv + W1,
        TOK, HID, DCH, 1, b1, nullptr, nullptr, hid);
    // 7) MLP fc2 + bias + un-partition + residual -> d_out
    gemm_tc<<<dim3(2, 157), 256, GEMM_SMEM>>>(hid, wv + W2,
        TOK, DCH, HID, 2, b2, x, out, nullptr);
}

// round 10
// speedup vs baseline: 2.3861x; 1.0180x over previous
#include <cuda_runtime.h>
#include <cuda_bf16.h>
#include <cstdint>
#include <math.h>

#define TOK 20000      // 2 * 16 windows * 625 tokens
#define DCH 256
#define QKVN 768
#define HID 512

typedef unsigned short ush;

// ---- scratch: plain bf16 planes ----
__device__ ush g_xw  [TOK * DCH];
__device__ ush g_qkv [TOK * QKVN];
__device__ ush g_att [TOK * DCH];
__device__ float g_proj[TOK * DCH];
__device__ ush g_ln  [TOK * DCH];
__device__ ush g_hid [TOK * HID];
// all four weight matrices concatenated: wqkv | wout | w1 | w2
#define WQ 0
#define WO 196608
#define W1 262144
#define W2 393216
#define WTOT 524288
__device__ ush g_w[WTOT];

// ---------------------------------------------------------------------------
// helpers
// ---------------------------------------------------------------------------
__device__ __forceinline__ uint32_t smem_u32(const void* p) {
    uint32_t a;
    asm("{ .reg .u64 t; cvta.to.shared.u64 t, %1; cvt.u32.u64 %0, t; }" : "=r"(a) : "l"(p));
    return a;
}
#define CP_ASYNC16(dst, src) \
    asm volatile("cp.async.cg.shared.global [%0], [%1], 16;" :: "r"(dst), "l"(src))
#define CP_COMMIT() asm volatile("cp.async.commit_group;")
#define CP_WAIT2()  asm volatile("cp.async.wait_group 2;")
#define CP_WAIT1()  asm volatile("cp.async.wait_group 1;")
#define CP_WAIT0()  asm volatile("cp.async.wait_group 0;")

__device__ __forceinline__ void ldm_x4(uint32_t& d0, uint32_t& d1, uint32_t& d2,
                                       uint32_t& d3, uint32_t addr)
{
    asm volatile("ldmatrix.sync.aligned.m8n8.x4.shared.b16 {%0,%1,%2,%3}, [%4];"
                 : "=r"(d0), "=r"(d1), "=r"(d2), "=r"(d3) : "r"(addr));
}
__device__ __forceinline__ void ldm_x4t(uint32_t& d0, uint32_t& d1, uint32_t& d2,
                                        uint32_t& d3, uint32_t addr)
{
    asm volatile("ldmatrix.sync.aligned.m8n8.x4.trans.shared.b16 {%0,%1,%2,%3}, [%4];"
                 : "=r"(d0), "=r"(d1), "=r"(d2), "=r"(d3) : "r"(addr));
}

__device__ __forceinline__ void mma16816(float c[4], uint32_t a0, uint32_t a1,
                                         uint32_t a2, uint32_t a3,
                                         uint32_t b0, uint32_t b1)
{
    asm volatile(
        "mma.sync.aligned.m16n8k16.row.col.f32.bf16.bf16.f32 "
        "{%0,%1,%2,%3}, {%4,%5,%6,%7}, {%8,%9}, {%0,%1,%2,%3};"
        : "+f"(c[0]), "+f"(c[1]), "+f"(c[2]), "+f"(c[3])
        : "r"(a0), "r"(a1), "r"(a2), "r"(a3), "r"(b0), "r"(b1));
}

__device__ __forceinline__ ush bfr(float f) {
    return __bfloat16_as_ushort(__float2bfloat16_rn(f));
}
// pack 2 floats -> bf16x2 in ONE cvt (lo = first arg)
__device__ __forceinline__ uint32_t pack2bf(float lo, float hi) {
    uint32_t r;
    asm("cvt.rn.bf16x2.f32 %0, %1, %2;" : "=r"(r) : "f"(hi), "f"(lo));
    return r;
}
__device__ __forceinline__ float ex2(float x) {
    float r;
    asm("ex2.approx.f32 %0, %1;" : "=f"(r) : "f"(x));
    return r;
}

__device__ __forceinline__ float gelu_exact(float v)
{
    return 0.5f * v * (1.0f + erff(v * 0.70710678118654752f));
}

// ---------------------------------------------------------------------------
// merged weight conversion
// ---------------------------------------------------------------------------
__global__ __launch_bounds__(256) void cvt4_kernel(
    const float* __restrict__ s0, const float* __restrict__ s1,
    const float* __restrict__ s2, const float* __restrict__ s3,
    ush* __restrict__ h)
{
    int base = (blockIdx.x * blockDim.x + threadIdx.x) * 4;
    if (base >= WTOT) return;
    const float* src;
    int off;
    if (base < WO)      { src = s0; off = base; }
    else if (base < W1) { src = s1; off = base - WO; }
    else if (base < W2) { src = s2; off = base - W1; }
    else                { src = s3; off = base - W2; }
    float4 v = *(const float4*)(src + off);
    uint2 o;
    o.x = pack2bf(v.x, v.y);
    o.y = pack2bf(v.z, v.w);
    *(uint2*)(h + base) = o;
}

// ---------------------------------------------------------------------------
// window partition with smem transpose: x (2,256,100,100) -> bf16 (20000,256)
// ---------------------------------------------------------------------------
__global__ __launch_bounds__(256) void gather_kernel(const float* __restrict__ x,
                                                     ush* __restrict__ xh)
{
    __shared__ float sm[32][33];
    const int w = threadIdx.x >> 5, lane = threadIdx.x & 31;
    const int tk0 = blockIdx.x * 32;
    const int ch0 = blockIdx.y * 32;

    {
        int tk = tk0 + lane;
        int bb = tk / 10000, rr = tk % 10000;
        int win = rr / 625, t = rr % 625;
        int hh = (win >> 2) * 25 + t / 25;
        int ww = (win & 3) * 25 + t % 25;
        int base = bb * 2560000 + hh * 100 + ww;
#pragma unroll
        for (int i = 0; i < 4; i++) {
            int ch = ch0 + w * 4 + i;
            sm[w * 4 + i][lane] = x[base + ch * 10000];
        }
    }
    __syncthreads();

#pragma unroll
    for (int i = 0; i < 4; i++) {
        int tl = w * 4 + i;
        xh[(size_t)(tk0 + tl) * DCH + ch0 + lane] = bfr(sm[lane][tl]);
    }
}

// ---------------------------------------------------------------------------
// un-partition + residual: proj (20000,256 token-major, already + bias)
// -> out NCHW + x.  Coalesced both sides via 32x32 smem transpose.
// ---------------------------------------------------------------------------
__global__ __launch_bounds__(256) void scatter_res(const float* __restrict__ proj,
                                                   const float* __restrict__ x,
                                                   float* __restrict__ out)
{
    __shared__ float sm[32][33];
    const int w = threadIdx.x >> 5, lane = threadIdx.x & 31;
    const int tk0 = blockIdx.x * 32;
    const int ch0 = blockIdx.y * 32;

    // coalesced read: lane across channels for one token
#pragma unroll
    for (int i = 0; i < 4; i++) {
        int tl = w * 4 + i;
        sm[lane][tl] = proj[(size_t)(tk0 + tl) * DCH + ch0 + lane];
    }
    __syncthreads();

    // coalesced write: lane across tokens for one channel
    {
        int tk = tk0 + lane;
        int bb = tk / 10000, rr = tk % 10000;
        int win = rr / 625, t = rr % 625;
        int hh = (win >> 2) * 25 + t / 25;
        int ww = (win & 3) * 25 + t % 25;
        int base = bb * 2560000 + hh * 100 + ww;
#pragma unroll
        for (int i = 0; i < 4; i++) {
            int ch = ch0 + w * 4 + i;
            int addr = base + ch * 10000;
            out[addr] = x[addr] + sm[w * 4 + i][lane];
        }
    }
}

// ---------------------------------------------------------------------------
// plain-bf16 tensor-core GEMM: 4-stage cp.async pipeline + ldmatrix.
// mode 0: C fp32            mode 1: gelu(C+bias) -> bf16
// mode 3: C -> bf16         mode 4: C + bias -> fp32 (token-major, coalesced)
// ---------------------------------------------------------------------------
#define SB   80           // smem row stride bytes (64 data + 16 pad)
#define PLB  10240        // one matrix tile: 128 rows * SB
#define BUFB 20480        // A + B
#define NSTG 4
#define GEMM_SMEM (NSTG * BUFB)

__global__ __launch_bounds__(256) void gemm_tc(
    const ush* __restrict__ Ah, const ush* __restrict__ Bh,
    int M, int N, int K, int mode,
    const float* __restrict__ bias,
    float* __restrict__ outF, ush* __restrict__ oh)
{
    extern __shared__ char smem[];
    const uint32_t sbb = smem_u32(smem);
    const int tid = threadIdx.x;
    const int wid = tid >> 5, lane = tid & 31;
    const int g = lane >> 2, t = lane & 3;
    const int wm = (wid & 3) * 32;
    const int wn = (wid >> 2) * 64;
    const int row0 = blockIdx.y * 128, coln0 = blockIdx.x * 128;

    float acc[2][8][4];
#pragma unroll
    for (int i = 0; i < 2; i++)
#pragma unroll
        for (int j = 0; j < 8; j++)
#pragma unroll
            for (int q = 0; q < 4; q++) acc[i][j][q] = 0.f;

    const int nst = K >> 5;

    const int lr0 = tid >> 2, lc0 = tid & 3;
    const int lr1 = 64 + (tid >> 2);
    int ga0 = row0 + lr0; if (ga0 > M - 1) ga0 = M - 1;
    int ga1 = row0 + lr1; if (ga1 > M - 1) ga1 = M - 1;

#define ISSUE(s) do {                                                          \
    int _b = (s) & (NSTG - 1);                                                 \
    int _k0 = (s) << 5;                                                        \
    uint32_t _d0 = sbb + _b * BUFB + lr0 * SB + lc0 * 16;                      \
    CP_ASYNC16(_d0,       Ah + (size_t)ga0 * K + _k0 + lc0 * 8);               \
    CP_ASYNC16(_d0 + PLB, Bh + (size_t)(coln0 + lr0) * K + _k0 + lc0 * 8);     \
    uint32_t _d1 = sbb + _b * BUFB + lr1 * SB + lc0 * 16;                      \
    CP_ASYNC16(_d1,       Ah + (size_t)ga1 * K + _k0 + lc0 * 8);               \
    CP_ASYNC16(_d1 + PLB, Bh + (size_t)(coln0 + lr1) * K + _k0 + lc0 * 8);     \
} while (0)

    ISSUE(0); CP_COMMIT();
    ISSUE(1); CP_COMMIT();
    ISSUE(2); CP_COMMIT();

    const int arow = (lane & 7) + ((lane >> 3) & 1) * 8;
    const int kh = (lane >> 4) * 16;

    for (int s = 0; s < nst; s++) {
        if (s + 3 <= nst)      CP_WAIT2();
        else if (s + 2 == nst) CP_WAIT1();
        else                   CP_WAIT0();
        __syncthreads();
        if (s + 3 < nst) { ISSUE(s + 3); CP_COMMIT(); }

        const uint32_t pa = sbb + (s & (NSTG - 1)) * BUFB;
        const uint32_t pb = pa + PLB;
#pragma unroll
        for (int ks = 0; ks < 2; ks++) {
            const uint32_t cb = ks * 32 + kh;
            uint32_t ah[2][4];
#pragma unroll
            for (int mt = 0; mt < 2; mt++) {
                uint32_t ad = pa + (wm + mt * 16 + arow) * SB + cb;
                ldm_x4(ah[mt][0], ah[mt][1], ah[mt][2], ah[mt][3], ad);
            }
            uint32_t bh[8][2];
#pragma unroll
            for (int p = 0; p < 4; p++) {
                uint32_t bd = pb + (wn + p * 16 + arow) * SB + cb;
                ldm_x4(bh[2 * p][0], bh[2 * p + 1][0], bh[2 * p][1], bh[2 * p + 1][1], bd);
            }
#pragma unroll
            for (int mt = 0; mt < 2; mt++)
#pragma unroll
                for (int nt = 0; nt < 8; nt++)
                    mma16816(acc[mt][nt], ah[mt][0], ah[mt][1], ah[mt][2], ah[mt][3],
                             bh[nt][0], bh[nt][1]);
        }
    }
#undef ISSUE

    // ---- epilogue ----
#pragma unroll
    for (int mt = 0; mt < 2; mt++) {
#pragma unroll
        for (int half = 0; half < 2; half++) {
            int r = row0 + wm + mt * 16 + g + half * 8;
            if (r >= M) continue;
#pragma unroll
            for (int nt = 0; nt < 8; nt++) {
                int col = coln0 + wn + nt * 8 + 2 * t;
                float v0 = acc[mt][nt][half * 2 + 0];
                float v1 = acc[mt][nt][half * 2 + 1];
                if (mode == 0) {
                    *(float2*)(outF + (size_t)r * N + col) = make_float2(v0, v1);
                } else if (mode == 3) {
                    *(uint32_t*)(oh + (size_t)r * N + col) = pack2bf(v0, v1);
                } else if (mode == 1) {
                    *(uint32_t*)(oh + (size_t)r * N + col) =
                        pack2bf(gelu_exact(v0 + bias[col]),
                                gelu_exact(v1 + bias[col + 1]));
                } else { // mode 4: C + bias, fp32 token-major
                    *(float2*)(outF + (size_t)r * N + col) =
                        make_float2(v0 + bias[col], v1 + bias[col + 1]);
                }
            }
        }
    }
}

// ---------------------------------------------------------------------------
// tensor-core windowed attention: bf16, cp.async double-buffered K/V,
// ldmatrix (V via .trans), lean softmax.
// grid = (head 8, win 32, qtile 5); CTA 256 thr.
// ---------------------------------------------------------------------------
#define SROW 20
#define SBK  80     // row stride bytes for K/V tiles
#define KVB  (64 * SROW)    // one K or V tile in words
#define SL2  0.25503487f    // (1/sqrt(32)) * log2(e)

template<bool LAST>
__device__ __forceinline__ void attn_compute(
    int kb, int t, int arow, int kh,
    uint32_t Kb, uint32_t Vb,
    const float* BL, int add0, int add1,
    const uint32_t qh[2][4], float& l0, float& l1, float oacc[4][4])
{
    // ---- S = Q K^T ----
    float sacc[8][4];
#pragma unroll
    for (int i = 0; i < 8; i++)
#pragma unroll
        for (int j = 0; j < 4; j++) sacc[i][j] = 0.f;

#pragma unroll
    for (int p = 0; p < 4; p++) {
        uint32_t base = Kb + (p * 16 + arow) * SBK + kh;
        uint32_t kA0, kA1, kA2, kA3, kB0, kB1, kB2, kB3;
        ldm_x4(kA0, kA1, kA2, kA3, base);
        ldm_x4(kB0, kB1, kB2, kB3, base + 32);
        mma16816(sacc[2 * p],     qh[0][0], qh[0][1], qh[0][2], qh[0][3], kA0, kA2);
        mma16816(sacc[2 * p + 1], qh[0][0], qh[0][1], qh[0][2], qh[0][3], kA1, kA3);
        mma16816(sacc[2 * p],     qh[1][0], qh[1][1], qh[1][2], qh[1][3], kB0, kB2);
        mma16816(sacc[2 * p + 1], qh[1][0], qh[1][1], qh[1][2], qh[1][3], kB1, kB3);
    }

    // ---- bias + ex2 + pack P ----
    const int kbase = kb * 64;
    uint32_t pha[8][2];
#pragma unroll
    for (int nt = 0; nt < 8; nt++) {
        int jl0 = nt * 8 + 2 * t;
        int jg0 = kbase + jl0;
        int jg1 = jg0 + 1;
        int jc0 = LAST ? (jg0 < 624 ? jg0 : 624) : jg0;
        int jc1 = LAST ? (jg1 < 624 ? jg1 : 624) : jg1;
        int sub0 = jc0 + 24 * ((jc0 * 1311) >> 15);
        int sub1 = jc1 + 24 * ((jc1 * 1311) >> 15);
        float b00 = BL[add0 - sub0], b01 = BL[add0 - sub1];
        float b10 = BL[add1 - sub0], b11 = BL[add1 - sub1];
        float p0 = ex2(fmaf(sacc[nt][0], SL2, b00));
        float p1 = ex2(fmaf(sacc[nt][1], SL2, b01));
        float p2 = ex2(fmaf(sacc[nt][2], SL2, b10));
        float p3 = ex2(fmaf(sacc[nt][3], SL2, b11));
        if (LAST) {
            if (jg0 >= 625) { p0 = 0.f; p2 = 0.f; }
            if (jg1 >= 625) { p1 = 0.f; p3 = 0.f; }
        }
        l0 += p0 + p1;
        l1 += p2 + p3;
        pha[nt][0] = pack2bf(p0, p1);
        pha[nt][1] = pack2bf(p2, p3);
    }

    // ---- O += P V ----
#pragma unroll
    for (int p2 = 0; p2 < 2; p2++) {
#pragma unroll
        for (int kc2 = 0; kc2 < 4; kc2++) {
            uint32_t d0, d1, d2, d3;
            ldm_x4t(d0, d1, d2, d3, Vb + (kc2 * 16 + arow) * SBK + p2 * 32 + kh);
            mma16816(oacc[2 * p2],     pha[2 * kc2][0], pha[2 * kc2][1],
                     pha[2 * kc2 + 1][0], pha[2 * kc2 + 1][1], d0, d1);
            mma16816(oacc[2 * p2 + 1], pha[2 * kc2][0], pha[2 * kc2][1],
                     pha[2 * kc2 + 1][0], pha[2 * kc2 + 1][1], d2, d3);
        }
    }
}

__global__ __launch_bounds__(256) void attn_tc(const ush* __restrict__ qh_,
                                               const float* __restrict__ table,
                                               ush* __restrict__ oh)
{
    __shared__ uint32_t QHI[128 * SROW];
    __shared__ uint32_t KHI[2 * KVB];
    __shared__ uint32_t VHI[2 * KVB];
    __shared__ float    BL[2401];

    const int head = blockIdx.x;
    const int win  = blockIdx.y;
    const int qt   = blockIdx.z;
    const int tid  = threadIdx.x;
    const int w = tid >> 5, lane = tid & 31;
    const int g = lane >> 2, t = tid & 3;
    const int tok0 = win * 625;
    const int qbase = qt * 128;
    const int arow = (lane & 7) + ((lane >> 3) & 1) * 8;
    const int kh = (lane >> 4) * 16;
    const uint32_t Kb0 = smem_u32(KHI);
    const uint32_t Vb0 = smem_u32(VHI);

    // K/V tile loader: one 16B chunk of K and of V per thread, clamped row.
    const int lrr = tid >> 2, lcc = tid & 3;
#define KV_ISSUE(kb) do {                                                        \
    int _jg = (kb) * 64 + lrr; if (_jg > 624) _jg = 624;                          \
    size_t _src = (size_t)(tok0 + _jg) * QKVN + head * 32 + lcc * 8;              \
    uint32_t _off = ((kb) & 1) * (KVB * 4) + lrr * SBK + lcc * 16;                \
    CP_ASYNC16(Kb0 + _off, qh_ + _src + 256);                                     \
    CP_ASYNC16(Vb0 + _off, qh_ + _src + 512);                                     \
} while (0)

    KV_ISSUE(0); CP_COMMIT();

    for (int i = tid; i < 2401; i += 256)
        BL[i] = table[i * 8 + head] * 1.4426950408889634f;

#pragma unroll
    for (int it = 0; it < 2; it++) {
        int idx = it * 256 + tid;
        int r = idx >> 2, c = idx & 3;
        int qi = qbase + r;
        uint4 v = make_uint4(0, 0, 0, 0);
        if (qi < 625)
            v = *(const uint4*)(qh_ + (size_t)(tok0 + qi) * QKVN + head * 32 + c * 8);
        *(uint4*)(QHI + r * SROW + c * 4) = v;
    }
    __syncthreads();

    uint32_t qh[2][4];
    {
        int r0 = w * 16 + g;
#pragma unroll
        for (int kc = 0; kc < 2; kc++) {
            qh[kc][0] = QHI[r0 * SROW + kc * 8 + t];
            qh[kc][1] = QHI[(r0 + 8) * SROW + kc * 8 + t];
            qh[kc][2] = QHI[r0 * SROW + kc * 8 + t + 4];
            qh[kc][3] = QHI[(r0 + 8) * SROW + kc * 8 + t + 4];
        }
    }

    const int qi0 = qbase + w * 16 + g;
    const int qi1 = qi0 + 8;
    const int cq0 = qi0 < 625 ? qi0 : 624;
    const int cq1 = qi1 < 625 ? qi1 : 624;
    const int add0 = (cq0 / 25 + 24) * 49 + (cq0 % 25) + 24;
    const int add1 = (cq1 / 25 + 24) * 49 + (cq1 % 25) + 24;

    float l0 = 0.f, l1 = 0.f;
    float oacc[4][4];
#pragma unroll
    for (int i = 0; i < 4; i++)
#pragma unroll
        for (int j = 0; j < 4; j++) oacc[i][j] = 0.f;

#pragma unroll 1
    for (int kb = 0; kb < 9; kb++) {
        CP_WAIT0();
        __syncthreads();                 // stage kb ready; prev compute done
        KV_ISSUE(kb + 1); CP_COMMIT();   // load kb+1 while computing kb
        attn_compute<false>(kb, t, arow, kh,
                            Kb0 + (kb & 1) * (KVB * 4),
                            Vb0 + (kb & 1) * (KVB * 4),
                            BL, add0, add1, qh, l0, l1, oacc);
    }
    CP_WAIT0();
    __syncthreads();
    attn_compute<true>(9, t, arow, kh,
                       Kb0 + (9 & 1) * (KVB * 4),
                       Vb0 + (9 & 1) * (KVB * 4),
                       BL, add0, add1, qh, l0, l1, oacc);
#undef KV_ISSUE

    l0 += __shfl_xor_sync(0xffffffffu, l0, 1);
    l0 += __shfl_xor_sync(0xffffffffu, l0, 2);
    l1 += __shfl_xor_sync(0xffffffffu, l1, 1);
    l1 += __shfl_xor_sync(0xffffffffu, l1, 2);
    float inv0 = 1.f / l0, inv1 = 1.f / l1;

    if (qi0 < 625) {
        size_t o = (size_t)(tok0 + qi0) * DCH + head * 32;
#pragma unroll
        for (int nt2 = 0; nt2 < 4; nt2++) {
            int d = nt2 * 8 + 2 * t;
            *(uint32_t*)(oh + o + d) = pack2bf(oacc[nt2][0] * inv0,
                                               oacc[nt2][1] * inv0);
        }
    }
    if (qi1 < 625) {
        size_t o = (size_t)(tok0 + qi1) * DCH + head * 32;
#pragma unroll
        for (int nt2 = 0; nt2 < 4; nt2++) {
            int d = nt2 * 8 + 2 * t;
            *(uint32_t*)(oh + o + d) = pack2bf(oacc[nt2][2] * inv1,
                                               oacc[nt2][3] * inv1);
        }
    }
}

// ---------------------------------------------------------------------------
// LayerNorm over d=256: one warp per token; output bf16
// ---------------------------------------------------------------------------
__global__ __launch_bounds__(256) void ln_kernel(const float* __restrict__ in,
                                                 ush* __restrict__ oh,
                                                 const float* __restrict__ g,
                                                 const float* __restrict__ b)
{
    int wid = threadIdx.x >> 5, lane = threadIdx.x & 31;
    int t = blockIdx.x * 8 + wid;
    const float4* p = (const float4*)(in + (size_t)t * DCH);
    float4 v0 = p[lane];
    float4 v1 = p[lane + 32];
    float s  = v0.x + v0.y + v0.z + v0.w + v1.x + v1.y + v1.z + v1.w;
    float ss = v0.x * v0.x + v0.y * v0.y + v0.z * v0.z + v0.w * v0.w
             + v1.x * v1.x + v1.y * v1.y + v1.z * v1.z + v1.w * v1.w;
#pragma unroll
    for (int off = 16; off > 0; off >>= 1) {
        s  += __shfl_xor_sync(0xffffffffu, s, off);
        ss += __shfl_xor_sync(0xffffffffu, ss, off);
    }
    float mean = s * (1.f / 256.f);
    float var  = ss * (1.f / 256.f) - mean * mean;
    float rstd = rsqrtf(var + 1e-5f);

    const float4* g4 = (const float4*)g;
    const float4* b4 = (const float4*)b;
    float4 ga = g4[lane], gb = g4[lane + 32];
    float4 ba = b4[lane], bb = b4[lane + 32];

    uint2 o0, o1;
    o0.x = pack2bf((v0.x - mean) * rstd * ga.x + ba.x,
                   (v0.y - mean) * rstd * ga.y + ba.y);
    o0.y = pack2bf((v0.z - mean) * rstd * ga.z + ba.z,
                   (v0.w - mean) * rstd * ga.w + ba.w);
    o1.x = pack2bf((v1.x - mean) * rstd * gb.x + bb.x,
                   (v1.y - mean) * rstd * gb.y + bb.y);
    o1.y = pack2bf((v1.z - mean) * rstd * gb.z + bb.z,
                   (v1.w - mean) * rstd * gb.w + bb.w);

    size_t o = (size_t)t * DCH;
    *(uint2*)(oh + o + lane * 4)       = o0;
    *(uint2*)(oh + o + 128 + lane * 4) = o1;
}

// ---------------------------------------------------------------------------
extern "C" void kernel_launch(void* const* d_in, const int* in_sizes, int n_in,
                              void* d_out, int out_size)
{
    const float* x      = (const float*)d_in[0];
    const float* w_qkv  = (const float*)d_in[1];
    const float* w_out  = (const float*)d_in[2];
    const float* table  = (const float*)d_in[3];
    const float* gamma2 = (const float*)d_in[4];
    const float* beta2  = (const float*)d_in[5];
    const float* w1     = (const float*)d_in[6];
    const float* b1     = (const float*)d_in[7];
    const float* w2     = (const float*)d_in[8];
    const float* b2     = (const float*)d_in[9];
    float* out = (float*)d_out;

    ush *xw, *qkv, *att, *ln, *hid, *wv;
    float *proj;
    cudaGetSymbolAddress((void**)&xw,  g_xw);
    cudaGetSymbolAddress((void**)&qkv, g_qkv);
    cudaGetSymbolAddress((void**)&att, g_att);
    cudaGetSymbolAddress((void**)&proj, g_proj);
    cudaGetSymbolAddress((void**)&ln,  g_ln);
    cudaGetSymbolAddress((void**)&hid, g_hid);
    cudaGetSymbolAddress((void**)&wv,  g_w);

    cudaFuncSetAttribute(gemm_tc, cudaFuncAttributeMaxDynamicSharedMemorySize, GEMM_SMEM);

    // 0) weights -> bf16 plane (one launch)
    cvt4_kernel<<<WTOT / 4 / 256, 256>>>(w_qkv, w_out, w1, w2, wv);

    // 1) window partition (transposed, coalesced)
    gather_kernel<<<dim3(625, 8), 256>>>(x, xw);
    // 2) QKV projection -> bf16
    gemm_tc<<<dim3(6, 157), 256, GEMM_SMEM>>>(xw, wv + WQ,
        TOK, QKVN, DCH, 3, nullptr, nullptr, qkv);
    // 3) tensor-core windowed attention -> bf16
    attn_tc<<<dim3(8, 32, 5), 256>>>(qkv, table, att);
    // 4) output projection -> fp32
    gemm_tc<<<dim3(2, 157), 256, GEMM_SMEM>>>(att, wv + WO,
        TOK, DCH, DCH, 0, nullptr, proj, nullptr);
    // 5) layernorm -> bf16
    ln_kernel<<<2500, 256>>>(proj, ln, gamma2, beta2);
    // 6) MLP fc1 + exact GELU -> bf16
    gemm_tc<<<dim3(4, 157), 256, GEMM_SMEM>>>(ln, wv + W1,
        TOK, HID, DCH, 1, b1, nullptr, hid);
    // 7) MLP fc2 + bias -> fp32 token-major (coalesced)
    gemm_tc<<<dim3(2, 157), 256, GEMM_SMEM>>>(hid, wv + W2,
        TOK, DCH, HID, 4, b2, proj, nullptr);
    // 8) un-partition + residual -> d_out (coalesced both sides)
    scatter_res<<<dim3(625, 8), 256>>>(proj, x, out);
}

// round 11
// speedup vs baseline: 2.4031x; 1.0072x over previous
#include <cuda_runtime.h>
#include <cuda_bf16.h>
#include <cstdint>
#include <math.h>

#define TOK 20000      // 2 * 16 windows * 625 tokens
#define DCH 256
#define QKVN 768
#define HID 512

typedef unsigned short ush;

// ---- scratch: plain bf16 planes ----
__device__ ush g_xw  [TOK * DCH];   // gather out / QKV in ; later out-proj out
__device__ ush g_qkv [TOK * QKVN];
__device__ ush g_att [TOK * DCH];   // attn out / out-proj in ; later fc2 out
__device__ ush g_ln  [TOK * DCH];
__device__ ush g_hid [TOK * HID];
// all four weight matrices concatenated: wqkv | wout | w1 | w2
#define WQ 0
#define WO 196608
#define W1 262144
#define W2 393216
#define WTOT 524288
__device__ ush g_w[WTOT];

// ---------------------------------------------------------------------------
// helpers
// ---------------------------------------------------------------------------
__device__ __forceinline__ uint32_t smem_u32(const void* p) {
    uint32_t a;
    asm("{ .reg .u64 t; cvta.to.shared.u64 t, %1; cvt.u32.u64 %0, t; }" : "=r"(a) : "l"(p));
    return a;
}
#define CP_ASYNC16(dst, src) \
    asm volatile("cp.async.cg.shared.global [%0], [%1], 16;" :: "r"(dst), "l"(src))
#define CP_COMMIT() asm volatile("cp.async.commit_group;")
#define CP_WAIT2()  asm volatile("cp.async.wait_group 2;")
#define CP_WAIT1()  asm volatile("cp.async.wait_group 1;")
#define CP_WAIT0()  asm volatile("cp.async.wait_group 0;")

__device__ __forceinline__ void ldm_x4(uint32_t& d0, uint32_t& d1, uint32_t& d2,
                                       uint32_t& d3, uint32_t addr)
{
    asm volatile("ldmatrix.sync.aligned.m8n8.x4.shared.b16 {%0,%1,%2,%3}, [%4];"
                 : "=r"(d0), "=r"(d1), "=r"(d2), "=r"(d3) : "r"(addr));
}
__device__ __forceinline__ void ldm_x4t(uint32_t& d0, uint32_t& d1, uint32_t& d2,
                                        uint32_t& d3, uint32_t addr)
{
    asm volatile("ldmatrix.sync.aligned.m8n8.x4.trans.shared.b16 {%0,%1,%2,%3}, [%4];"
                 : "=r"(d0), "=r"(d1), "=r"(d2), "=r"(d3) : "r"(addr));
}

__device__ __forceinline__ void mma16816(float c[4], uint32_t a0, uint32_t a1,
                                         uint32_t a2, uint32_t a3,
                                         uint32_t b0, uint32_t b1)
{
    asm volatile(
        "mma.sync.aligned.m16n8k16.row.col.f32.bf16.bf16.f32 "
        "{%0,%1,%2,%3}, {%4,%5,%6,%7}, {%8,%9}, {%0,%1,%2,%3};"
        : "+f"(c[0]), "+f"(c[1]), "+f"(c[2]), "+f"(c[3])
        : "r"(a0), "r"(a1), "r"(a2), "r"(a3), "r"(b0), "r"(b1));
}

__device__ __forceinline__ ush bfr(float f) {
    return __bfloat16_as_ushort(__float2bfloat16_rn(f));
}
// pack 2 floats -> bf16x2 in ONE cvt (lo = first arg)
__device__ __forceinline__ uint32_t pack2bf(float lo, float hi) {
    uint32_t r;
    asm("cvt.rn.bf16x2.f32 %0, %1, %2;" : "=r"(r) : "f"(hi), "f"(lo));
    return r;
}
// packed exp2 on bf16x2
__device__ __forceinline__ uint32_t ex2_bf16x2(uint32_t x) {
    uint32_t r;
    asm("ex2.approx.ftz.bf16x2 %0, %1;" : "=r"(r) : "r"(x));
    return r;
}
__device__ __forceinline__ float lo_bf(uint32_t w) { return __uint_as_float(w << 16); }
__device__ __forceinline__ float hi_bf(uint32_t w) { return __uint_as_float(w & 0xFFFF0000u); }

__device__ __forceinline__ float gelu_exact(float v)
{
    return 0.5f * v * (1.0f + erff(v * 0.70710678118654752f));
}

// ---------------------------------------------------------------------------
// merged weight conversion
// ---------------------------------------------------------------------------
__global__ __launch_bounds__(256) void cvt4_kernel(
    const float* __restrict__ s0, const float* __restrict__ s1,
    const float* __restrict__ s2, const float* __restrict__ s3,
    ush* __restrict__ h)
{
    int base = (blockIdx.x * blockDim.x + threadIdx.x) * 4;
    if (base >= WTOT) return;
    const float* src;
    int off;
    if (base < WO)      { src = s0; off = base; }
    else if (base < W1) { src = s1; off = base - WO; }
    else if (base < W2) { src = s2; off = base - W1; }
    else                { src = s3; off = base - W2; }
    float4 v = *(const float4*)(src + off);
    uint2 o;
    o.x = pack2bf(v.x, v.y);
    o.y = pack2bf(v.z, v.w);
    *(uint2*)(h + base) = o;
}

// ---------------------------------------------------------------------------
// window partition with smem transpose: x (2,256,100,100) -> bf16 (20000,256)
// ---------------------------------------------------------------------------
__global__ __launch_bounds__(256) void gather_kernel(const float* __restrict__ x,
                                                     ush* __restrict__ xh)
{
    __shared__ float sm[32][33];
    const int w = threadIdx.x >> 5, lane = threadIdx.x & 31;
    const int tk0 = blockIdx.x * 32;
    const int ch0 = blockIdx.y * 32;

    {
        int tk = tk0 + lane;
        int bb = tk / 10000, rr = tk % 10000;
        int win = rr / 625, t = rr % 625;
        int hh = (win >> 2) * 25 + t / 25;
        int ww = (win & 3) * 25 + t % 25;
        int base = bb * 2560000 + hh * 100 + ww;
#pragma unroll
        for (int i = 0; i < 4; i++) {
            int ch = ch0 + w * 4 + i;
            sm[w * 4 + i][lane] = x[base + ch * 10000];
        }
    }
    __syncthreads();

#pragma unroll
    for (int i = 0; i < 4; i++) {
        int tl = w * 4 + i;
        xh[(size_t)(tk0 + tl) * DCH + ch0 + lane] = bfr(sm[lane][tl]);
    }
}

// ---------------------------------------------------------------------------
// un-partition + residual: yb (bf16, token-major, already + bias) -> out NCHW + x
// ---------------------------------------------------------------------------
__global__ __launch_bounds__(256) void scatter_res(const ush* __restrict__ yb,
                                                   const float* __restrict__ x,
                                                   float* __restrict__ out)
{
    __shared__ float sm[32][33];
    const int w = threadIdx.x >> 5, lane = threadIdx.x & 31;
    const int tk0 = blockIdx.x * 32;
    const int ch0 = blockIdx.y * 32;

#pragma unroll
    for (int i = 0; i < 4; i++) {
        int tl = w * 4 + i;
        sm[lane][tl] = __uint_as_float(
            ((uint32_t)yb[(size_t)(tk0 + tl) * DCH + ch0 + lane]) << 16);
    }
    __syncthreads();

    {
        int tk = tk0 + lane;
        int bb = tk / 10000, rr = tk % 10000;
        int win = rr / 625, t = rr % 625;
        int hh = (win >> 2) * 25 + t / 25;
        int ww = (win & 3) * 25 + t % 25;
        int base = bb * 2560000 + hh * 100 + ww;
#pragma unroll
        for (int i = 0; i < 4; i++) {
            int ch = ch0 + w * 4 + i;
            int addr = base + ch * 10000;
            out[addr] = x[addr] + sm[w * 4 + i][lane];
        }
    }
}

// ---------------------------------------------------------------------------
// plain-bf16 tensor-core GEMM: 4-stage cp.async pipeline + ldmatrix.
// mode 1: gelu(C+bias) -> bf16   mode 3: C -> bf16   mode 4: C + bias -> bf16
// ---------------------------------------------------------------------------
#define SB   80           // smem row stride bytes (64 data + 16 pad)
#define PLB  10240        // one matrix tile: 128 rows * SB
#define BUFB 20480        // A + B
#define NSTG 4
#define GEMM_SMEM (NSTG * BUFB)

__global__ __launch_bounds__(256) void gemm_tc(
    const ush* __restrict__ Ah, const ush* __restrict__ Bh,
    int M, int N, int K, int mode,
    const float* __restrict__ bias,
    ush* __restrict__ oh)
{
    extern __shared__ char smem[];
    const uint32_t sbb = smem_u32(smem);
    const int tid = threadIdx.x;
    const int wid = tid >> 5, lane = tid & 31;
    const int g = lane >> 2, t = lane & 3;
    const int wm = (wid & 3) * 32;
    const int wn = (wid >> 2) * 64;
    const int row0 = blockIdx.y * 128, coln0 = blockIdx.x * 128;

    float acc[2][8][4];
#pragma unroll
    for (int i = 0; i < 2; i++)
#pragma unroll
        for (int j = 0; j < 8; j++)
#pragma unroll
            for (int q = 0; q < 4; q++) acc[i][j][q] = 0.f;

    const int nst = K >> 5;

    const int lr0 = tid >> 2, lc0 = tid & 3;
    const int lr1 = 64 + (tid >> 2);
    int ga0 = row0 + lr0; if (ga0 > M - 1) ga0 = M - 1;
    int ga1 = row0 + lr1; if (ga1 > M - 1) ga1 = M - 1;

#define ISSUE(s) do {                                                          \
    int _b = (s) & (NSTG - 1);                                                 \
    int _k0 = (s) << 5;                                                        \
    uint32_t _d0 = sbb + _b * BUFB + lr0 * SB + lc0 * 16;                      \
    CP_ASYNC16(_d0,       Ah + (size_t)ga0 * K + _k0 + lc0 * 8);               \
    CP_ASYNC16(_d0 + PLB, Bh + (size_t)(coln0 + lr0) * K + _k0 + lc0 * 8);     \
    uint32_t _d1 = sbb + _b * BUFB + lr1 * SB + lc0 * 16;                      \
    CP_ASYNC16(_d1,       Ah + (size_t)ga1 * K + _k0 + lc0 * 8);               \
    CP_ASYNC16(_d1 + PLB, Bh + (size_t)(coln0 + lr1) * K + _k0 + lc0 * 8);     \
} while (0)

    ISSUE(0); CP_COMMIT();
    ISSUE(1); CP_COMMIT();
    ISSUE(2); CP_COMMIT();

    const int arow = (lane & 7) + ((lane >> 3) & 1) * 8;
    const int kh = (lane >> 4) * 16;

    for (int s = 0; s < nst; s++) {
        if (s + 3 <= nst)      CP_WAIT2();
        else if (s + 2 == nst) CP_WAIT1();
        else                   CP_WAIT0();
        __syncthreads();
        if (s + 3 < nst) { ISSUE(s + 3); CP_COMMIT(); }

        const uint32_t pa = sbb + (s & (NSTG - 1)) * BUFB;
        const uint32_t pb = pa + PLB;
#pragma unroll
        for (int ks = 0; ks < 2; ks++) {
            const uint32_t cb = ks * 32 + kh;
            uint32_t ah[2][4];
#pragma unroll
            for (int mt = 0; mt < 2; mt++) {
                uint32_t ad = pa + (wm + mt * 16 + arow) * SB + cb;
                ldm_x4(ah[mt][0], ah[mt][1], ah[mt][2], ah[mt][3], ad);
            }
            uint32_t bh[8][2];
#pragma unroll
            for (int p = 0; p < 4; p++) {
                uint32_t bd = pb + (wn + p * 16 + arow) * SB + cb;
                ldm_x4(bh[2 * p][0], bh[2 * p + 1][0], bh[2 * p][1], bh[2 * p + 1][1], bd);
            }
#pragma unroll
            for (int mt = 0; mt < 2; mt++)
#pragma unroll
                for (int nt = 0; nt < 8; nt++)
                    mma16816(acc[mt][nt], ah[mt][0], ah[mt][1], ah[mt][2], ah[mt][3],
                             bh[nt][0], bh[nt][1]);
        }
    }
#undef ISSUE

    // ---- epilogue ----
#pragma unroll
    for (int mt = 0; mt < 2; mt++) {
#pragma unroll
        for (int half = 0; half < 2; half++) {
            int r = row0 + wm + mt * 16 + g + half * 8;
            if (r >= M) continue;
#pragma unroll
            for (int nt = 0; nt < 8; nt++) {
                int col = coln0 + wn + nt * 8 + 2 * t;
                float v0 = acc[mt][nt][half * 2 + 0];
                float v1 = acc[mt][nt][half * 2 + 1];
                if (mode == 3) {
                    *(uint32_t*)(oh + (size_t)r * N + col) = pack2bf(v0, v1);
                } else if (mode == 1) {
                    *(uint32_t*)(oh + (size_t)r * N + col) =
                        pack2bf(gelu_exact(v0 + bias[col]),
                                gelu_exact(v1 + bias[col + 1]));
                } else { // mode 4: C + bias -> bf16
                    *(uint32_t*)(oh + (size_t)r * N + col) =
                        pack2bf(v0 + bias[col], v1 + bias[col + 1]);
                }
            }
        }
    }
}

// ---------------------------------------------------------------------------
// tensor-core windowed attention: bf16, cp.async double-buffered K/V,
// ldmatrix (V via .trans), packed-bf16 exp, row-sum via mma-with-ones.
// grid = (head 8, win 32, qtile 5); CTA 256 thr.
// ---------------------------------------------------------------------------
#define SROW 20
#define SBK  80     // row stride bytes for K/V tiles
#define KVB  (64 * SROW)    // one K or V tile in words
#define SL2  0.25503487f    // (1/sqrt(32)) * log2(e)
#define ONES 0x3F803F80u    // bf16x2 {1.0, 1.0}

template<bool LAST>
__device__ __forceinline__ void attn_compute(
    int kb, int t, int arow, int kh,
    uint32_t Kb, uint32_t Vb,
    const float* BL, int add0, int add1,
    const uint32_t qh[2][4], float lacc[4], float oacc[4][4])
{
    // ---- S = Q K^T ----
    float sacc[8][4];
#pragma unroll
    for (int i = 0; i < 8; i++)
#pragma unroll
        for (int j = 0; j < 4; j++) sacc[i][j] = 0.f;

#pragma unroll
    for (int p = 0; p < 4; p++) {
        uint32_t base = Kb + (p * 16 + arow) * SBK + kh;
        uint32_t kA0, kA1, kA2, kA3, kB0, kB1, kB2, kB3;
        ldm_x4(kA0, kA1, kA2, kA3, base);
        ldm_x4(kB0, kB1, kB2, kB3, base + 32);
        mma16816(sacc[2 * p],     qh[0][0], qh[0][1], qh[0][2], qh[0][3], kA0, kA2);
        mma16816(sacc[2 * p + 1], qh[0][0], qh[0][1], qh[0][2], qh[0][3], kA1, kA3);
        mma16816(sacc[2 * p],     qh[1][0], qh[1][1], qh[1][2], qh[1][3], kB0, kB2);
        mma16816(sacc[2 * p + 1], qh[1][0], qh[1][1], qh[1][2], qh[1][3], kB1, kB3);
    }

    // ---- bias + packed bf16 ex2 ----
    const int kbase = kb * 64;
    uint32_t pha[8][2];
#pragma unroll
    for (int nt = 0; nt < 8; nt++) {
        int jl0 = nt * 8 + 2 * t;
        int jg0 = kbase + jl0;
        int jg1 = jg0 + 1;
        int jc0 = LAST ? (jg0 < 624 ? jg0 : 624) : jg0;
        int jc1 = LAST ? (jg1 < 624 ? jg1 : 624) : jg1;
        int sub0 = jc0 + 24 * ((jc0 * 1311) >> 15);
        int sub1 = jc1 + 24 * ((jc1 * 1311) >> 15);
        float t0 = fmaf(sacc[nt][0], SL2, BL[add0 - sub0]);
        float t1 = fmaf(sacc[nt][1], SL2, BL[add0 - sub1]);
        float t2 = fmaf(sacc[nt][2], SL2, BL[add1 - sub0]);
        float t3 = fmaf(sacc[nt][3], SL2, BL[add1 - sub1]);
        if (LAST) {
            if (jg0 >= 625) { t0 = -1e30f; t2 = -1e30f; }
            if (jg1 >= 625) { t1 = -1e30f; t3 = -1e30f; }
        }
        pha[nt][0] = ex2_bf16x2(pack2bf(t0, t1));
        pha[nt][1] = ex2_bf16x2(pack2bf(t2, t3));
    }

    // ---- row sums: lacc += P * ones  (full K=64 reduction inside mma) ----
#pragma unroll
    for (int kc2 = 0; kc2 < 4; kc2++)
        mma16816(lacc, pha[2 * kc2][0], pha[2 * kc2][1],
                 pha[2 * kc2 + 1][0], pha[2 * kc2 + 1][1], ONES, ONES);

    // ---- O += P V ----
#pragma unroll
    for (int p2 = 0; p2 < 2; p2++) {
#pragma unroll
        for (int kc2 = 0; kc2 < 4; kc2++) {
            uint32_t d0, d1, d2, d3;
            ldm_x4t(d0, d1, d2, d3, Vb + (kc2 * 16 + arow) * SBK + p2 * 32 + kh);
            mma16816(oacc[2 * p2],     pha[2 * kc2][0], pha[2 * kc2][1],
                     pha[2 * kc2 + 1][0], pha[2 * kc2 + 1][1], d0, d1);
            mma16816(oacc[2 * p2 + 1], pha[2 * kc2][0], pha[2 * kc2][1],
                     pha[2 * kc2 + 1][0], pha[2 * kc2 + 1][1], d2, d3);
        }
    }
}

__global__ __launch_bounds__(256) void attn_tc(const ush* __restrict__ qh_,
                                               const float* __restrict__ table,
                                               ush* __restrict__ oh)
{
    __shared__ uint32_t QHI[128 * SROW];
    __shared__ uint32_t KHI[2 * KVB];
    __shared__ uint32_t VHI[2 * KVB];
    __shared__ float    BL[2401];

    const int head = blockIdx.x;
    const int win  = blockIdx.y;
    const int qt   = blockIdx.z;
    const int tid  = threadIdx.x;
    const int w = tid >> 5, lane = tid & 31;
    const int g = lane >> 2, t = tid & 3;
    const int tok0 = win * 625;
    const int qbase = qt * 128;
    const int arow = (lane & 7) + ((lane >> 3) & 1) * 8;
    const int kh = (lane >> 4) * 16;
    const uint32_t Kb0 = smem_u32(KHI);
    const uint32_t Vb0 = smem_u32(VHI);

    const int lrr = tid >> 2, lcc = tid & 3;
#define KV_ISSUE(kb) do {                                                        \
    int _jg = (kb) * 64 + lrr; if (_jg > 624) _jg = 624;                          \
    size_t _src = (size_t)(tok0 + _jg) * QKVN + head * 32 + lcc * 8;              \
    uint32_t _off = ((kb) & 1) * (KVB * 4) + lrr * SBK + lcc * 16;                \
    CP_ASYNC16(Kb0 + _off, qh_ + _src + 256);                                     \
    CP_ASYNC16(Vb0 + _off, qh_ + _src + 512);                                     \
} while (0)

    KV_ISSUE(0); CP_COMMIT();

    for (int i = tid; i < 2401; i += 256)
        BL[i] = table[i * 8 + head] * 1.4426950408889634f;

#pragma unroll
    for (int it = 0; it < 2; it++) {
        int idx = it * 256 + tid;
        int r = idx >> 2, c = idx & 3;
        int qi = qbase + r;
        uint4 v = make_uint4(0, 0, 0, 0);
        if (qi < 625)
            v = *(const uint4*)(qh_ + (size_t)(tok0 + qi) * QKVN + head * 32 + c * 8);
        *(uint4*)(QHI + r * SROW + c * 4) = v;
    }
    __syncthreads();

    uint32_t qh[2][4];
    {
        int r0 = w * 16 + g;
#pragma unroll
        for (int kc = 0; kc < 2; kc++) {
            qh[kc][0] = QHI[r0 * SROW + kc * 8 + t];
            qh[kc][1] = QHI[(r0 + 8) * SROW + kc * 8 + t];
            qh[kc][2] = QHI[r0 * SROW + kc * 8 + t + 4];
            qh[kc][3] = QHI[(r0 + 8) * SROW + kc * 8 + t + 4];
        }
    }

    const int qi0 = qbase + w * 16 + g;
    const int qi1 = qi0 + 8;
    const int cq0 = qi0 < 625 ? qi0 : 624;
    const int cq1 = qi1 < 625 ? qi1 : 624;
    const int add0 = (cq0 / 25 + 24) * 49 + (cq0 % 25) + 24;
    const int add1 = (cq1 / 25 + 24) * 49 + (cq1 % 25) + 24;

    float lacc[4] = {0.f, 0.f, 0.f, 0.f};
    float oacc[4][4];
#pragma unroll
    for (int i = 0; i < 4; i++)
#pragma unroll
        for (int j = 0; j < 4; j++) oacc[i][j] = 0.f;

#pragma unroll 1
    for (int kb = 0; kb < 9; kb++) {
        CP_WAIT0();
        __syncthreads();
        KV_ISSUE(kb + 1); CP_COMMIT();
        attn_compute<false>(kb, t, arow, kh,
                            Kb0 + (kb & 1) * (KVB * 4),
                            Vb0 + (kb & 1) * (KVB * 4),
                            BL, add0, add1, qh, lacc, oacc);
    }
    CP_WAIT0();
    __syncthreads();
    attn_compute<true>(9, t, arow, kh,
                       Kb0 + (9 & 1) * (KVB * 4),
                       Vb0 + (9 & 1) * (KVB * 4),
                       BL, add0, add1, qh, lacc, oacc);
#undef KV_ISSUE

    float inv0 = 1.f / lacc[0], inv1 = 1.f / lacc[2];

    if (qi0 < 625) {
        size_t o = (size_t)(tok0 + qi0) * DCH + head * 32;
#pragma unroll
        for (int nt2 = 0; nt2 < 4; nt2++) {
            int d = nt2 * 8 + 2 * t;
            *(uint32_t*)(oh + o + d) = pack2bf(oacc[nt2][0] * inv0,
                                               oacc[nt2][1] * inv0);
        }
    }
    if (qi1 < 625) {
        size_t o = (size_t)(tok0 + qi1) * DCH + head * 32;
#pragma unroll
        for (int nt2 = 0; nt2 < 4; nt2++) {
            int d = nt2 * 8 + 2 * t;
            *(uint32_t*)(oh + o + d) = pack2bf(oacc[nt2][2] * inv1,
                                               oacc[nt2][3] * inv1);
        }
    }
}

// ---------------------------------------------------------------------------
// LayerNorm over d=256: one warp per token; bf16 in -> bf16 out
// ---------------------------------------------------------------------------
__global__ __launch_bounds__(256) void ln_kernel(const ush* __restrict__ in,
                                                 ush* __restrict__ oh,
                                                 const float* __restrict__ g,
                                                 const float* __restrict__ b)
{
    int wid = threadIdx.x >> 5, lane = threadIdx.x & 31;
    int t = blockIdx.x * 8 + wid;
    const uint2* p = (const uint2*)(in + (size_t)t * DCH);
    uint2 a = p[lane];
    uint2 c = p[lane + 32];
    float f0 = lo_bf(a.x), f1 = hi_bf(a.x), f2 = lo_bf(a.y), f3 = hi_bf(a.y);
    float f4 = lo_bf(c.x), f5 = hi_bf(c.x), f6 = lo_bf(c.y), f7 = hi_bf(c.y);

    float s  = f0 + f1 + f2 + f3 + f4 + f5 + f6 + f7;
    float ss = f0 * f0 + f1 * f1 + f2 * f2 + f3 * f3
             + f4 * f4 + f5 * f5 + f6 * f6 + f7 * f7;
#pragma unroll
    for (int off = 16; off > 0; off >>= 1) {
        s  += __shfl_xor_sync(0xffffffffu, s, off);
        ss += __shfl_xor_sync(0xffffffffu, ss, off);
    }
    float mean = s * (1.f / 256.f);
    float var  = ss * (1.f / 256.f) - mean * mean;
    float rstd = rsqrtf(var + 1e-5f);

    const float4* g4 = (const float4*)g;
    const float4* b4 = (const float4*)b;
    float4 ga = g4[lane], gb = g4[lane + 32];
    float4 ba = b4[lane], bb = b4[lane + 32];

    uint2 o0, o1;
    o0.x = pack2bf((f0 - mean) * rstd * ga.x + ba.x,
                   (f1 - mean) * rstd * ga.y + ba.y);
    o0.y = pack2bf((f2 - mean) * rstd * ga.z + ba.z,
                   (f3 - mean) * rstd * ga.w + ba.w);
    o1.x = pack2bf((f4 - mean) * rstd * gb.x + bb.x,
                   (f5 - mean) * rstd * gb.y + bb.y);
    o1.y = pack2bf((f6 - mean) * rstd * gb.z + bb.z,
                   (f7 - mean) * rstd * gb.w + bb.w);

    size_t o = (size_t)t * DCH;
    *(uint2*)(oh + o + lane * 4)       = o0;
    *(uint2*)(oh + o + 128 + lane * 4) = o1;
}

// ---------------------------------------------------------------------------
extern "C" void kernel_launch(void* const* d_in, const int* in_sizes, int n_in,
                              void* d_out, int out_size)
{
    const float* x      = (const float*)d_in[0];
    const float* w_qkv  = (const float*)d_in[1];
    const float* w_out  = (const float*)d_in[2];
    const float* table  = (const float*)d_in[3];
    const float* gamma2 = (const float*)d_in[4];
    const float* beta2  = (const float*)d_in[5];
    const float* w1     = (const float*)d_in[6];
    const float* b1     = (const float*)d_in[7];
    const float* w2     = (const float*)d_in[8];
    const float* b2     = (const float*)d_in[9];
    float* out = (float*)d_out;

    ush *xw, *qkv, *att, *ln, *hid, *wv;
    cudaGetSymbolAddress((void**)&xw,  g_xw);
    cudaGetSymbolAddress((void**)&qkv, g_qkv);
    cudaGetSymbolAddress((void**)&att, g_att);
    cudaGetSymbolAddress((void**)&ln,  g_ln);
    cudaGetSymbolAddress((void**)&hid, g_hid);
    cudaGetSymbolAddress((void**)&wv,  g_w);

    cudaFuncSetAttribute(gemm_tc, cudaFuncAttributeMaxDynamicSharedMemorySize, GEMM_SMEM);

    // 0) weights -> bf16 plane
    cvt4_kernel<<<WTOT / 4 / 256, 256>>>(w_qkv, w_out, w1, w2, wv);

    // 1) window partition (transposed, coalesced)
    gather_kernel<<<dim3(625, 8), 256>>>(x, xw);
    // 2) QKV projection -> bf16
    gemm_tc<<<dim3(6, 157), 256, GEMM_SMEM>>>(xw, wv + WQ,
        TOK, QKVN, DCH, 3, nullptr, qkv);
    // 3) tensor-core windowed attention -> bf16
    attn_tc<<<dim3(8, 32, 5), 256>>>(qkv, table, att);
    // 4) output projection -> bf16 (reuses g_xw)
    gemm_tc<<<dim3(2, 157), 256, GEMM_SMEM>>>(att, wv + WO,
        TOK, DCH, DCH, 3, nullptr, xw);
    // 5) layernorm (bf16 in) -> bf16
    ln_kernel<<<2500, 256>>>(xw, ln, gamma2, beta2);
    // 6) MLP fc1 + exact GELU -> bf16
    gemm_tc<<<dim3(4, 157), 256, GEMM_SMEM>>>(ln, wv + W1,
        TOK, HID, DCH, 1, b1, hid);
    // 7) MLP fc2 + bias -> bf16 token-major (reuses g_att)
    gemm_tc<<<dim3(2, 157), 256, GEMM_SMEM>>>(hid, wv + W2,
        TOK, DCH, HID, 4, b2, att);
    // 8) un-partition + residual -> d_out (coalesced both sides)
    scatter_res<<<dim3(625, 8), 256>>>(att, x, out);
}

// round 12
// speedup vs baseline: 2.4899x; 1.0361x over previous
#include <cuda_runtime.h>
#include <cuda_bf16.h>
#include <cstdint>
#include <math.h>

#define TOK 20000      // 2 * 16 windows * 625 tokens
#define DCH 256
#define QKVN 768
#define HID 512

typedef unsigned short ush;

// ---- scratch: plain bf16 planes ----
__device__ ush g_xw  [TOK * DCH];   // gather out / QKV in ; later out-proj out
__device__ ush g_qkv [TOK * QKVN];
__device__ ush g_att [TOK * DCH];   // attn out / out-proj in
__device__ ush g_ln  [TOK * DCH];
__device__ ush g_hid [TOK * HID];
// all four weight matrices concatenated: wqkv | wout | w1 | w2
#define WQ 0
#define WO 196608
#define W1 262144
#define W2 393216
#define WTOT 524288
__device__ ush g_w[WTOT];

// ---------------------------------------------------------------------------
// helpers
// ---------------------------------------------------------------------------
__device__ __forceinline__ uint32_t smem_u32(const void* p) {
    uint32_t a;
    asm("{ .reg .u64 t; cvta.to.shared.u64 t, %1; cvt.u32.u64 %0, t; }" : "=r"(a) : "l"(p));
    return a;
}
#define CP_ASYNC16(dst, src) \
    asm volatile("cp.async.cg.shared.global [%0], [%1], 16;" :: "r"(dst), "l"(src))
#define CP_COMMIT() asm volatile("cp.async.commit_group;")
#define CP_WAIT2()  asm volatile("cp.async.wait_group 2;")
#define CP_WAIT1()  asm volatile("cp.async.wait_group 1;")
#define CP_WAIT0()  asm volatile("cp.async.wait_group 0;")

__device__ __forceinline__ void ldm_x4(uint32_t& d0, uint32_t& d1, uint32_t& d2,
                                       uint32_t& d3, uint32_t addr)
{
    asm volatile("ldmatrix.sync.aligned.m8n8.x4.shared.b16 {%0,%1,%2,%3}, [%4];"
                 : "=r"(d0), "=r"(d1), "=r"(d2), "=r"(d3) : "r"(addr));
}
__device__ __forceinline__ void ldm_x4t(uint32_t& d0, uint32_t& d1, uint32_t& d2,
                                        uint32_t& d3, uint32_t addr)
{
    asm volatile("ldmatrix.sync.aligned.m8n8.x4.trans.shared.b16 {%0,%1,%2,%3}, [%4];"
                 : "=r"(d0), "=r"(d1), "=r"(d2), "=r"(d3) : "r"(addr));
}

__device__ __forceinline__ void mma16816(float c[4], uint32_t a0, uint32_t a1,
                                         uint32_t a2, uint32_t a3,
                                         uint32_t b0, uint32_t b1)
{
    asm volatile(
        "mma.sync.aligned.m16n8k16.row.col.f32.bf16.bf16.f32 "
        "{%0,%1,%2,%3}, {%4,%5,%6,%7}, {%8,%9}, {%0,%1,%2,%3};"
        : "+f"(c[0]), "+f"(c[1]), "+f"(c[2]), "+f"(c[3])
        : "r"(a0), "r"(a1), "r"(a2), "r"(a3), "r"(b0), "r"(b1));
}

__device__ __forceinline__ ush bfr(float f) {
    return __bfloat16_as_ushort(__float2bfloat16_rn(f));
}
// pack 2 floats -> bf16x2 in ONE cvt (lo = first arg)
__device__ __forceinline__ uint32_t pack2bf(float lo, float hi) {
    uint32_t r;
    asm("cvt.rn.bf16x2.f32 %0, %1, %2;" : "=r"(r) : "f"(hi), "f"(lo));
    return r;
}
// packed exp2 on bf16x2
__device__ __forceinline__ uint32_t ex2_bf16x2(uint32_t x) {
    uint32_t r;
    asm("ex2.approx.ftz.bf16x2 %0, %1;" : "=r"(r) : "r"(x));
    return r;
}
__device__ __forceinline__ float lo_bf(uint32_t w) { return __uint_as_float(w << 16); }
__device__ __forceinline__ float hi_bf(uint32_t w) { return __uint_as_float(w & 0xFFFF0000u); }

__device__ __forceinline__ float gelu_exact(float v)
{
    return 0.5f * v * (1.0f + erff(v * 0.70710678118654752f));
}

// ---------------------------------------------------------------------------
// merged weight conversion
// ---------------------------------------------------------------------------
__global__ __launch_bounds__(256) void cvt4_kernel(
    const float* __restrict__ s0, const float* __restrict__ s1,
    const float* __restrict__ s2, const float* __restrict__ s3,
    ush* __restrict__ h)
{
    int base = (blockIdx.x * blockDim.x + threadIdx.x) * 4;
    if (base >= WTOT) return;
    const float* src;
    int off;
    if (base < WO)      { src = s0; off = base; }
    else if (base < W1) { src = s1; off = base - WO; }
    else if (base < W2) { src = s2; off = base - W1; }
    else                { src = s3; off = base - W2; }
    float4 v = *(const float4*)(src + off);
    uint2 o;
    o.x = pack2bf(v.x, v.y);
    o.y = pack2bf(v.z, v.w);
    *(uint2*)(h + base) = o;
}

// ---------------------------------------------------------------------------
// window partition with smem transpose: x (2,256,100,100) -> bf16 (20000,256)
// ---------------------------------------------------------------------------
__global__ __launch_bounds__(256) void gather_kernel(const float* __restrict__ x,
                                                     ush* __restrict__ xh)
{
    __shared__ float sm[32][33];
    const int w = threadIdx.x >> 5, lane = threadIdx.x & 31;
    const int tk0 = blockIdx.x * 32;
    const int ch0 = blockIdx.y * 32;

    {
        int tk = tk0 + lane;
        int bb = tk / 10000, rr = tk % 10000;
        int win = rr / 625, t = rr % 625;
        int hh = (win >> 2) * 25 + t / 25;
        int ww = (win & 3) * 25 + t % 25;
        int base = bb * 2560000 + hh * 100 + ww;
#pragma unroll
        for (int i = 0; i < 4; i++) {
            int ch = ch0 + w * 4 + i;
            sm[w * 4 + i][lane] = x[base + ch * 10000];
        }
    }
    __syncthreads();

#pragma unroll
    for (int i = 0; i < 4; i++) {
        int tl = w * 4 + i;
        xh[(size_t)(tk0 + tl) * DCH + ch0 + lane] = bfr(sm[lane][tl]);
    }
}

// ---------------------------------------------------------------------------
// plain-bf16 tensor-core GEMM: 4-stage cp.async pipeline + ldmatrix.
// mode 1: gelu(C+bias) -> bf16   mode 2: out[scatter]=xres+C+bias (fp32)
// mode 3: C -> bf16
// ---------------------------------------------------------------------------
#define SB   80           // smem row stride bytes (64 data + 16 pad)
#define PLB  10240        // one matrix tile: 128 rows * SB
#define BUFB 20480        // A + B
#define NSTG 4
#define GEMM_SMEM (NSTG * BUFB)

__global__ __launch_bounds__(256) void gemm_tc(
    const ush* __restrict__ Ah, const ush* __restrict__ Bh,
    int M, int N, int K, int mode,
    const float* __restrict__ bias, const float* __restrict__ xres,
    float* __restrict__ outF, ush* __restrict__ oh)
{
    extern __shared__ char smem[];
    const uint32_t sbb = smem_u32(smem);
    const int tid = threadIdx.x;
    const int wid = tid >> 5, lane = tid & 31;
    const int g = lane >> 2, t = lane & 3;
    const int wm = (wid & 3) * 32;
    const int wn = (wid >> 2) * 64;
    const int row0 = blockIdx.y * 128, coln0 = blockIdx.x * 128;

    float acc[2][8][4];
#pragma unroll
    for (int i = 0; i < 2; i++)
#pragma unroll
        for (int j = 0; j < 8; j++)
#pragma unroll
            for (int q = 0; q < 4; q++) acc[i][j][q] = 0.f;

    const int nst = K >> 5;

    const int lr0 = tid >> 2, lc0 = tid & 3;
    const int lr1 = 64 + (tid >> 2);
    int ga0 = row0 + lr0; if (ga0 > M - 1) ga0 = M - 1;
    int ga1 = row0 + lr1; if (ga1 > M - 1) ga1 = M - 1;

#define ISSUE(s) do {                                                          \
    int _b = (s) & (NSTG - 1);                                                 \
    int _k0 = (s) << 5;                                                        \
    uint32_t _d0 = sbb + _b * BUFB + lr0 * SB + lc0 * 16;                      \
    CP_ASYNC16(_d0,       Ah + (size_t)ga0 * K + _k0 + lc0 * 8);               \
    CP_ASYNC16(_d0 + PLB, Bh + (size_t)(coln0 + lr0) * K + _k0 + lc0 * 8);     \
    uint32_t _d1 = sbb + _b * BUFB + lr1 * SB + lc0 * 16;                      \
    CP_ASYNC16(_d1,       Ah + (size_t)ga1 * K + _k0 + lc0 * 8);               \
    CP_ASYNC16(_d1 + PLB, Bh + (size_t)(coln0 + lr1) * K + _k0 + lc0 * 8);     \
} while (0)

    ISSUE(0); CP_COMMIT();
    ISSUE(1); CP_COMMIT();
    ISSUE(2); CP_COMMIT();

    const int arow = (lane & 7) + ((lane >> 3) & 1) * 8;
    const int kh = (lane >> 4) * 16;

    for (int s = 0; s < nst; s++) {
        if (s + 3 <= nst)      CP_WAIT2();
        else if (s + 2 == nst) CP_WAIT1();
        else                   CP_WAIT0();
        __syncthreads();
        if (s + 3 < nst) { ISSUE(s + 3); CP_COMMIT(); }

        const uint32_t pa = sbb + (s & (NSTG - 1)) * BUFB;
        const uint32_t pb = pa + PLB;
#pragma unroll
        for (int ks = 0; ks < 2; ks++) {
            const uint32_t cb = ks * 32 + kh;
            uint32_t ah[2][4];
#pragma unroll
            for (int mt = 0; mt < 2; mt++) {
                uint32_t ad = pa + (wm + mt * 16 + arow) * SB + cb;
                ldm_x4(ah[mt][0], ah[mt][1], ah[mt][2], ah[mt][3], ad);
            }
            uint32_t bh[8][2];
#pragma unroll
            for (int p = 0; p < 4; p++) {
                uint32_t bd = pb + (wn + p * 16 + arow) * SB + cb;
                ldm_x4(bh[2 * p][0], bh[2 * p + 1][0], bh[2 * p][1], bh[2 * p + 1][1], bd);
            }
#pragma unroll
            for (int mt = 0; mt < 2; mt++)
#pragma unroll
                for (int nt = 0; nt < 8; nt++)
                    mma16816(acc[mt][nt], ah[mt][0], ah[mt][1], ah[mt][2], ah[mt][3],
                             bh[nt][0], bh[nt][1]);
        }
    }
#undef ISSUE

    // ---- epilogue ----
#pragma unroll
    for (int mt = 0; mt < 2; mt++) {
#pragma unroll
        for (int half = 0; half < 2; half++) {
            int r = row0 + wm + mt * 16 + g + half * 8;
            if (r >= M) continue;
#pragma unroll
            for (int nt = 0; nt < 8; nt++) {
                int col = coln0 + wn + nt * 8 + 2 * t;
                float v0 = acc[mt][nt][half * 2 + 0];
                float v1 = acc[mt][nt][half * 2 + 1];
                if (mode == 3) {
                    *(uint32_t*)(oh + (size_t)r * N + col) = pack2bf(v0, v1);
                } else if (mode == 1) {
                    *(uint32_t*)(oh + (size_t)r * N + col) =
                        pack2bf(gelu_exact(v0 + bias[col]),
                                gelu_exact(v1 + bias[col + 1]));
                } else { // mode 2: scatter + residual
                    int bb = r / 10000, rr = r % 10000;
                    int win = rr / 625, tt = rr % 625;
                    int hh2 = (win >> 2) * 25 + tt / 25;
                    int ww = (win & 3) * 25 + tt % 25;
                    int obase = bb * 2560000 + hh2 * 100 + ww;
                    int oi0 = obase + col * 10000;
                    int oi1 = obase + (col + 1) * 10000;
                    outF[oi0] = xres[oi0] + v0 + bias[col];
                    outF[oi1] = xres[oi1] + v1 + bias[col + 1];
                }
            }
        }
    }
}

// ---------------------------------------------------------------------------
// tensor-core windowed attention: bf16, cp.async double-buffered K/V,
// ldmatrix (V via .trans), packed-bf16 exp, row-sum via mma-with-ones.
// grid = (head 8, win 32, qtile 5); CTA 256 thr; 3 CTAs/SM enforced.
// ---------------------------------------------------------------------------
#define SROW 20
#define SBK  80     // row stride bytes for K/V tiles
#define KVB  (64 * SROW)    // one K or V tile in words
#define SL2  0.25503487f    // (1/sqrt(32)) * log2(e)
#define ONES 0x3F803F80u    // bf16x2 {1.0, 1.0}

template<bool LAST>
__device__ __forceinline__ void attn_compute(
    int kb, int t, int arow, int kh,
    uint32_t Kb, uint32_t Vb,
    const float* BL, int add0, int add1,
    const uint32_t qh[2][4], float lacc[4], float oacc[4][4])
{
    // ---- S = Q K^T ----
    float sacc[8][4];
#pragma unroll
    for (int i = 0; i < 8; i++)
#pragma unroll
        for (int j = 0; j < 4; j++) sacc[i][j] = 0.f;

#pragma unroll
    for (int p = 0; p < 4; p++) {
        uint32_t base = Kb + (p * 16 + arow) * SBK + kh;
        uint32_t kA0, kA1, kA2, kA3, kB0, kB1, kB2, kB3;
        ldm_x4(kA0, kA1, kA2, kA3, base);
        ldm_x4(kB0, kB1, kB2, kB3, base + 32);
        mma16816(sacc[2 * p],     qh[0][0], qh[0][1], qh[0][2], qh[0][3], kA0, kA2);
        mma16816(sacc[2 * p + 1], qh[0][0], qh[0][1], qh[0][2], qh[0][3], kA1, kA3);
        mma16816(sacc[2 * p],     qh[1][0], qh[1][1], qh[1][2], qh[1][3], kB0, kB2);
        mma16816(sacc[2 * p + 1], qh[1][0], qh[1][1], qh[1][2], qh[1][3], kB1, kB3);
    }

    // ---- bias + packed bf16 ex2 ----
    const int kbase = kb * 64;
    uint32_t pha[8][2];
#pragma unroll
    for (int nt = 0; nt < 8; nt++) {
        int jl0 = nt * 8 + 2 * t;
        int jg0 = kbase + jl0;
        int jg1 = jg0 + 1;
        int jc0 = LAST ? (jg0 < 624 ? jg0 : 624) : jg0;
        int jc1 = LAST ? (jg1 < 624 ? jg1 : 624) : jg1;
        int sub0 = jc0 + 24 * ((jc0 * 1311) >> 15);
        int sub1 = jc1 + 24 * ((jc1 * 1311) >> 15);
        float t0 = fmaf(sacc[nt][0], SL2, BL[add0 - sub0]);
        float t1 = fmaf(sacc[nt][1], SL2, BL[add0 - sub1]);
        float t2 = fmaf(sacc[nt][2], SL2, BL[add1 - sub0]);
        float t3 = fmaf(sacc[nt][3], SL2, BL[add1 - sub1]);
        if (LAST) {
            if (jg0 >= 625) { t0 = -1e30f; t2 = -1e30f; }
            if (jg1 >= 625) { t1 = -1e30f; t3 = -1e30f; }
        }
        pha[nt][0] = ex2_bf16x2(pack2bf(t0, t1));
        pha[nt][1] = ex2_bf16x2(pack2bf(t2, t3));
    }

    // ---- row sums: lacc += P * ones ----
#pragma unroll
    for (int kc2 = 0; kc2 < 4; kc2++)
        mma16816(lacc, pha[2 * kc2][0], pha[2 * kc2][1],
                 pha[2 * kc2 + 1][0], pha[2 * kc2 + 1][1], ONES, ONES);

    // ---- O += P V ----
#pragma unroll
    for (int p2 = 0; p2 < 2; p2++) {
#pragma unroll
        for (int kc2 = 0; kc2 < 4; kc2++) {
            uint32_t d0, d1, d2, d3;
            ldm_x4t(d0, d1, d2, d3, Vb + (kc2 * 16 + arow) * SBK + p2 * 32 + kh);
            mma16816(oacc[2 * p2],     pha[2 * kc2][0], pha[2 * kc2][1],
                     pha[2 * kc2 + 1][0], pha[2 * kc2 + 1][1], d0, d1);
            mma16816(oacc[2 * p2 + 1], pha[2 * kc2][0], pha[2 * kc2][1],
                     pha[2 * kc2 + 1][0], pha[2 * kc2 + 1][1], d2, d3);
        }
    }
}

__global__ __launch_bounds__(256, 3) void attn_tc(const ush* __restrict__ qh_,
                                                  const float* __restrict__ table,
                                                  ush* __restrict__ oh)
{
    __shared__ uint32_t QHI[128 * SROW];
    __shared__ uint32_t KHI[2 * KVB];
    __shared__ uint32_t VHI[2 * KVB];
    __shared__ float    BL[2401];

    const int head = blockIdx.x;
    const int win  = blockIdx.y;
    const int qt   = blockIdx.z;
    const int tid  = threadIdx.x;
    const int w = tid >> 5, lane = tid & 31;
    const int g = lane >> 2, t = tid & 3;
    const int tok0 = win * 625;
    const int qbase = qt * 128;
    const int arow = (lane & 7) + ((lane >> 3) & 1) * 8;
    const int kh = (lane >> 4) * 16;
    const uint32_t Kb0 = smem_u32(KHI);
    const uint32_t Vb0 = smem_u32(VHI);

    const int lrr = tid >> 2, lcc = tid & 3;
#define KV_ISSUE(kb) do {                                                        \
    int _jg = (kb) * 64 + lrr; if (_jg > 624) _jg = 624;                          \
    size_t _src = (size_t)(tok0 + _jg) * QKVN + head * 32 + lcc * 8;              \
    uint32_t _off = ((kb) & 1) * (KVB * 4) + lrr * SBK + lcc * 16;                \
    CP_ASYNC16(Kb0 + _off, qh_ + _src + 256);                                     \
    CP_ASYNC16(Vb0 + _off, qh_ + _src + 512);                                     \
} while (0)

    KV_ISSUE(0); CP_COMMIT();

    for (int i = tid; i < 2401; i += 256)
        BL[i] = table[i * 8 + head] * 1.4426950408889634f;

#pragma unroll
    for (int it = 0; it < 2; it++) {
        int idx = it * 256 + tid;
        int r = idx >> 2, c = idx & 3;
        int qi = qbase + r;
        uint4 v = make_uint4(0, 0, 0, 0);
        if (qi < 625)
            v = *(const uint4*)(qh_ + (size_t)(tok0 + qi) * QKVN + head * 32 + c * 8);
        *(uint4*)(QHI + r * SROW + c * 4) = v;
    }
    __syncthreads();

    uint32_t qh[2][4];
    {
        int r0 = w * 16 + g;
#pragma unroll
        for (int kc = 0; kc < 2; kc++) {
            qh[kc][0] = QHI[r0 * SROW + kc * 8 + t];
            qh[kc][1] = QHI[(r0 + 8) * SROW + kc * 8 + t];
            qh[kc][2] = QHI[r0 * SROW + kc * 8 + t + 4];
            qh[kc][3] = QHI[(r0 + 8) * SROW + kc * 8 + t + 4];
        }
    }

    const int qi0 = qbase + w * 16 + g;
    const int qi1 = qi0 + 8;
    const int cq0 = qi0 < 625 ? qi0 : 624;
    const int cq1 = qi1 < 625 ? qi1 : 624;
    const int add0 = (cq0 / 25 + 24) * 49 + (cq0 % 25) + 24;
    const int add1 = (cq1 / 25 + 24) * 49 + (cq1 % 25) + 24;

    float lacc[4] = {0.f, 0.f, 0.f, 0.f};
    float oacc[4][4];
#pragma unroll
    for (int i = 0; i < 4; i++)
#pragma unroll
        for (int j = 0; j < 4; j++) oacc[i][j] = 0.f;

#pragma unroll 1
    for (int kb = 0; kb < 9; kb++) {
        CP_WAIT0();
        __syncthreads();
        KV_ISSUE(kb + 1); CP_COMMIT();
        attn_compute<false>(kb, t, arow, kh,
                            Kb0 + (kb & 1) * (KVB * 4),
                            Vb0 + (kb & 1) * (KVB * 4),
                            BL, add0, add1, qh, lacc, oacc);
    }
    CP_WAIT0();
    __syncthreads();
    attn_compute<true>(9, t, arow, kh,
                       Kb0 + (9 & 1) * (KVB * 4),
                       Vb0 + (9 & 1) * (KVB * 4),
                       BL, add0, add1, qh, lacc, oacc);
#undef KV_ISSUE

    float inv0 = 1.f / lacc[0], inv1 = 1.f / lacc[2];

    if (qi0 < 625) {
        size_t o = (size_t)(tok0 + qi0) * DCH + head * 32;
#pragma unroll
        for (int nt2 = 0; nt2 < 4; nt2++) {
            int d = nt2 * 8 + 2 * t;
            *(uint32_t*)(oh + o + d) = pack2bf(oacc[nt2][0] * inv0,
                                               oacc[nt2][1] * inv0);
        }
    }
    if (qi1 < 625) {
        size_t o = (size_t)(tok0 + qi1) * DCH + head * 32;
#pragma unroll
        for (int nt2 = 0; nt2 < 4; nt2++) {
            int d = nt2 * 8 + 2 * t;
            *(uint32_t*)(oh + o + d) = pack2bf(oacc[nt2][2] * inv1,
                                               oacc[nt2][3] * inv1);
        }
    }
}

// ---------------------------------------------------------------------------
// LayerNorm over d=256: one warp per token; bf16 in -> bf16 out
// ---------------------------------------------------------------------------
__global__ __launch_bounds__(256) void ln_kernel(const ush* __restrict__ in,
                                                 ush* __restrict__ oh,
                                                 const float* __restrict__ g,
                                                 const float* __restrict__ b)
{
    int wid = threadIdx.x >> 5, lane = threadIdx.x & 31;
    int t = blockIdx.x * 8 + wid;
    const uint2* p = (const uint2*)(in + (size_t)t * DCH);
    uint2 a = p[lane];
    uint2 c = p[lane + 32];
    float f0 = lo_bf(a.x), f1 = hi_bf(a.x), f2 = lo_bf(a.y), f3 = hi_bf(a.y);
    float f4 = lo_bf(c.x), f5 = hi_bf(c.x), f6 = lo_bf(c.y), f7 = hi_bf(c.y);

    float s  = f0 + f1 + f2 + f3 + f4 + f5 + f6 + f7;
    float ss = f0 * f0 + f1 * f1 + f2 * f2 + f3 * f3
             + f4 * f4 + f5 * f5 + f6 * f6 + f7 * f7;
#pragma unroll
    for (int off = 16; off > 0; off >>= 1) {
        s  += __shfl_xor_sync(0xffffffffu, s, off);
        ss += __shfl_xor_sync(0xffffffffu, ss, off);
    }
    float mean = s * (1.f / 256.f);
    float var  = ss * (1.f / 256.f) - mean * mean;
    float rstd = rsqrtf(var + 1e-5f);

    const float4* g4 = (const float4*)g;
    const float4* b4 = (const float4*)b;
    float4 ga = g4[lane], gb = g4[lane + 32];
    float4 ba = b4[lane], bb = b4[lane + 32];

    uint2 o0, o1;
    o0.x = pack2bf((f0 - mean) * rstd * ga.x + ba.x,
                   (f1 - mean) * rstd * ga.y + ba.y);
    o0.y = pack2bf((f2 - mean) * rstd * ga.z + ba.z,
                   (f3 - mean) * rstd * ga.w + ba.w);
    o1.x = pack2bf((f4 - mean) * rstd * gb.x + bb.x,
                   (f5 - mean) * rstd * gb.y + bb.y);
    o1.y = pack2bf((f6 - mean) * rstd * gb.z + bb.z,
                   (f7 - mean) * rstd * gb.w + bb.w);

    size_t o = (size_t)t * DCH;
    *(uint2*)(oh + o + lane * 4)       = o0;
    *(uint2*)(oh + o + 128 + lane * 4) = o1;
}

// ---------------------------------------------------------------------------
extern "C" void kernel_launch(void* const* d_in, const int* in_sizes, int n_in,
                              void* d_out, int out_size)
{
    const float* x      = (const float*)d_in[0];
    const float* w_qkv  = (const float*)d_in[1];
    const float* w_out  = (const float*)d_in[2];
    const float* table  = (const float*)d_in[3];
    const float* gamma2 = (const float*)d_in[4];
    const float* beta2  = (const float*)d_in[5];
    const float* w1     = (const float*)d_in[6];
    const float* b1     = (const float*)d_in[7];
    const float* w2     = (const float*)d_in[8];
    const float* b2     = (const float*)d_in[9];
    float* out = (float*)d_out;

    ush *xw, *qkv, *att, *ln, *hid, *wv;
    cudaGetSymbolAddress((void**)&xw,  g_xw);
    cudaGetSymbolAddress((void**)&qkv, g_qkv);
    cudaGetSymbolAddress((void**)&att, g_att);
    cudaGetSymbolAddress((void**)&ln,  g_ln);
    cudaGetSymbolAddress((void**)&hid, g_hid);
    cudaGetSymbolAddress((void**)&wv,  g_w);

    cudaFuncSetAttribute(gemm_tc, cudaFuncAttributeMaxDynamicSharedMemorySize, GEMM_SMEM);

    // 0) weights -> bf16 plane
    cvt4_kernel<<<WTOT / 4 / 256, 256>>>(w_qkv, w_out, w1, w2, wv);

    // 1) window partition (transposed, coalesced)
    gather_kernel<<<dim3(625, 8), 256>>>(x, xw);
    // 2) QKV projection -> bf16
    gemm_tc<<<dim3(6, 157), 256, GEMM_SMEM>>>(xw, wv + WQ,
        TOK, QKVN, DCH, 3, nullptr, nullptr, nullptr, qkv);
    // 3) tensor-core windowed attention -> bf16
    attn_tc<<<dim3(8, 32, 5), 256>>>(qkv, table, att);
    // 4) output projection -> bf16 (reuses g_xw)
    gemm_tc<<<dim3(2, 157), 256, GEMM_SMEM>>>(att, wv + WO,
        TOK, DCH, DCH, 3, nullptr, nullptr, nullptr, xw);
    // 5) layernorm (bf16 in) -> bf16
    ln_kernel<<<2500, 256>>>(xw, ln, gamma2, beta2);
    // 6) MLP fc1 + exact GELU -> bf16
    gemm_tc<<<dim3(4, 157), 256, GEMM_SMEM>>>(ln, wv + W1,
        TOK, HID, DCH, 1, b1, nullptr, nullptr, hid);
    // 7) MLP fc2 + bias + un-partition + residual -> d_out (fused scatter)
    gemm_tc<<<dim3(2, 157), 256, GEMM_SMEM>>>(hid, wv + W2,
        TOK, DCH, HID, 2, b2, x, out, nullptr);
}